// round 4
// baseline (speedup 1.0000x reference)
#include <cuda_runtime.h>
#include <math.h>
#include <stdint.h>

#define H 512
#define BB 32
#define SS 128
#define TT 512
#define NHEAD 8
#define DHD 64
#define NL 4
#define FF 2048
#define NOUT 102
#define NJ 50

// ---------------- scratch ----------------
__device__ float g_m[BB * SS * H];
__device__ float g_mem[BB * TT * H];
__device__ float g_x[BB * TT * H];
__device__ float g_h[BB * TT * H];
__device__ float g_qkv[BB * TT * 3 * H];
__device__ float g_scores[BB * NHEAD * TT * TT];
__device__ float g_att[BB * TT * H];
__device__ float g_ff[BB * TT * FF];
__device__ float g_head[BB * TT * NOUT];
__device__ float g_pe[TT * H];
__device__ float g_convT[4 * H * H];

__constant__ int PAR[NJ] = {
    -1, 0, 1, 2, 3, 1, 5, 6, 1,
    4, 9, 10, 11,  4, 13, 14, 15,  4, 17, 18, 19,  4, 21, 22, 23,  4, 25, 26, 27,
    7, 29, 30, 31, 7, 33, 34, 35,  7, 37, 38, 39,  7, 41, 42, 43,  7, 45, 46, 47,
    8
};

#define EPI_NONE 0
#define EPI_SCALE 1
#define EPI_BIAS 2
#define EPI_BIAS_RES 3
#define EPI_BIAS_GELU 4
#define EPI_CONV 5

// ---------------- ptx helpers ----------------
__device__ __forceinline__ uint32_t f2tf(float f)
{
    uint32_t u;
    asm("cvt.rna.tf32.f32 %0, %1;" : "=r"(u) : "f"(f));
    return u;
}
__device__ __forceinline__ void cp16(uint32_t dst, const void* src)
{
    asm volatile("cp.async.cg.shared.global [%0], [%1], 16;\n" :: "r"(dst), "l"(src));
}
__device__ __forceinline__ void cp16z(uint32_t dst, const void* src, bool p)
{
    int sz = p ? 16 : 0;
    asm volatile("cp.async.cg.shared.global [%0], [%1], 16, %2;\n"
                 :: "r"(dst), "l"(src), "r"(sz));
}
__device__ __forceinline__ void cpcommit()
{
    asm volatile("cp.async.commit_group;\n" ::: "memory");
}
template <int W>
__device__ __forceinline__ void cpwait()
{
    asm volatile("cp.async.wait_group %0;\n" :: "n"(W) : "memory");
}
__device__ __forceinline__ void mma8(float* d, const uint32_t* a, const uint32_t* b)
{
    asm volatile(
        "mma.sync.aligned.m16n8k8.row.col.f32.tf32.tf32.f32 "
        "{%0,%1,%2,%3}, {%4,%5,%6,%7}, {%8,%9}, {%0,%1,%2,%3};\n"
        : "+f"(d[0]), "+f"(d[1]), "+f"(d[2]), "+f"(d[3])
        : "r"(a[0]), "r"(a[1]), "r"(a[2]), "r"(a[3]), "r"(b[0]), "r"(b[1]));
}
__device__ __forceinline__ void ldsm4(uint32_t* r, uint32_t addr)
{
    asm volatile("ldmatrix.sync.aligned.m8n8.x4.shared.b16 {%0,%1,%2,%3}, [%4];\n"
                 : "=r"(r[0]), "=r"(r[1]), "=r"(r[2]), "=r"(r[3]) : "r"(addr));
}
__device__ __forceinline__ void ldsm2(uint32_t* r, uint32_t addr)
{
    asm volatile("ldmatrix.sync.aligned.m8n8.x2.shared.b16 {%0,%1}, [%2];\n"
                 : "=r"(r[0]), "=r"(r[1]) : "r"(addr));
}

// ---------------- tf32 tensor-core GEMM (ldmatrix + tile preconvert) ----------------
// C[r,c] = sum_k A[r,k] * (TRANSB ? B[c,k] : B[k,c])  per batch z.
// M % 128 == 0, K % 32 == 0, rows 16B-aligned.
template <bool TRANSB, int EPI, int BN_>
__global__ void __launch_bounds__(256, 2) gemm4(
    const float* __restrict__ A, const float* __restrict__ Bm,
    const float* __restrict__ bias, const float* __restrict__ resid,
    float* __restrict__ C,
    int M, int N, int K, int lda, int ldb, int ldc,
    long sAb, long sAh, long sBb, long sBh, long sCb, long sCh,
    int nh, float scale)
{
    constexpr int BM = 128, BK = 32;
    constexpr int WTM = 64, WTN = BN_ / 4;
    constexpr int MT = WTM / 16;               // 4
    constexpr int NT = WTN / 8;                // 4 or 2
    constexpr int LDA = BK + 4;                // 36
    constexpr int LDB = TRANSB ? (BK + 4) : (BN_ + 4);
    constexpr int SBR = TRANSB ? BN_ : BK;
    constexpr int ACH = BM * BK / 4 / 256;     // 4
    constexpr int BCH = SBR * (TRANSB ? BK : BN_) / 4 / 256;

    extern __shared__ float sm[];
    float* sA = sm;
    float* sB = sm + 2 * BM * LDA;
    const uint32_t sAu = (uint32_t)__cvta_generic_to_shared(sA);
    const uint32_t sBu = (uint32_t)__cvta_generic_to_shared(sB);

    const int z = blockIdx.z;
    const int bb = z / nh, hh = z - bb * nh;
    A += (long)bb * sAb + (long)hh * sAh;
    Bm += (long)bb * sBb + (long)hh * sBh;
    const long coff = (long)bb * sCb + (long)hh * sCh;

    const int row0 = blockIdx.y * BM;
    const int col0 = blockIdx.x * BN_;
    const int tid = threadIdx.x;
    const int warp = tid >> 5;
    const int lane = tid & 31;
    const int wm = warp >> 2;
    const int wn = warp & 3;
    const int gid = lane >> 2;
    const int tig = lane & 3;
    const int l15 = lane & 15;
    const int l7 = lane & 7;
    const int acol = (lane >> 4) << 2;          // 0 or 4
    const int bcol = ((lane >> 3) & 1) << 2;    // 0 or 4

    float acc[MT][NT][4];
#pragma unroll
    for (int i = 0; i < MT; i++)
#pragma unroll
        for (int j = 0; j < NT; j++)
#pragma unroll
            for (int q = 0; q < 4; q++) acc[i][j][q] = 0.f;

    auto cpA = [&](int k0, int st) {
#pragma unroll
        for (int l = 0; l < ACH; l++) {
            int idx = l * 256 + tid;
            int r = idx >> 3;
            int cq = (idx & 7) * 4;
            cp16(sAu + (uint32_t)(st * BM * LDA + r * LDA + cq) * 4,
                 A + (long)(row0 + r) * lda + k0 + cq);
        }
    };
    auto cpB = [&](int k0, int st) {
        if (TRANSB) {
#pragma unroll
            for (int l = 0; l < BCH; l++) {
                int idx = l * 256 + tid;
                int n = idx >> 3;
                int cq = (idx & 7) * 4;
                cp16z(sBu + (uint32_t)(st * SBR * LDB + n * LDB + cq) * 4,
                      Bm + (long)(col0 + n) * ldb + k0 + cq,
                      (col0 + n) < N);
            }
        } else {
#pragma unroll
            for (int l = 0; l < BCH; l++) {
                int idx = l * 256 + tid;
                int kk = idx / (BN_ / 4);
                int nq = (idx % (BN_ / 4)) * 4;
                cp16(sBu + (uint32_t)(st * SBR * LDB + kk * LDB + nq) * 4,
                     Bm + (long)(k0 + kk) * ldb + col0 + nq);
            }
        }
    };

    // in-place fp32 -> tf32-rounded conversion of one stage (whole CTA)
    auto cvtp = [&](int st) {
        float* pA = sA + st * BM * LDA;
#pragma unroll
        for (int l = 0; l < ACH; l++) {
            int idx = l * 256 + tid;
            int r = idx >> 3;
            int cq = (idx & 7) * 4;
            float4* p = (float4*)&pA[r * LDA + cq];
            float4 v = *p;
            v.x = __uint_as_float(f2tf(v.x));
            v.y = __uint_as_float(f2tf(v.y));
            v.z = __uint_as_float(f2tf(v.z));
            v.w = __uint_as_float(f2tf(v.w));
            *p = v;
        }
        float* pB = sB + st * SBR * LDB;
        if (TRANSB) {
#pragma unroll
            for (int l = 0; l < BCH; l++) {
                int idx = l * 256 + tid;
                int n = idx >> 3;
                int cq = (idx & 7) * 4;
                float4* p = (float4*)&pB[n * LDB + cq];
                float4 v = *p;
                v.x = __uint_as_float(f2tf(v.x));
                v.y = __uint_as_float(f2tf(v.y));
                v.z = __uint_as_float(f2tf(v.z));
                v.w = __uint_as_float(f2tf(v.w));
                *p = v;
            }
        } else {
#pragma unroll
            for (int l = 0; l < BCH; l++) {
                int idx = l * 256 + tid;
                int kk = idx / (BN_ / 4);
                int nq = (idx % (BN_ / 4)) * 4;
                float4* p = (float4*)&pB[kk * LDB + nq];
                float4 v = *p;
                v.x = __uint_as_float(f2tf(v.x));
                v.y = __uint_as_float(f2tf(v.y));
                v.z = __uint_as_float(f2tf(v.z));
                v.w = __uint_as_float(f2tf(v.w));
                *p = v;
            }
        }
    };

    auto compute = [&](int st) {
        const uint32_t pAu = sAu + (uint32_t)(st * BM * LDA) * 4;
        const uint32_t pBu32 = sBu + (uint32_t)(st * SBR * LDB) * 4;
        const uint32_t* pB = (const uint32_t*)(sB + st * SBR * LDB);
#pragma unroll
        for (int ks = 0; ks < 4; ks++) {
            const int k = ks * 8;
            uint32_t af[MT][4], bf[NT][2];
#pragma unroll
            for (int mi = 0; mi < MT; mi++) {
                int r0 = wm * WTM + mi * 16 + l15;
                ldsm4(af[mi], pAu + (uint32_t)(r0 * LDA + k + acol) * 4);
            }
            if (TRANSB) {
#pragma unroll
                for (int ni = 0; ni < NT; ni++) {
                    int n0 = wn * WTN + ni * 8 + l7;
                    ldsm2(bf[ni], pBu32 + (uint32_t)(n0 * LDB + k + bcol) * 4);
                }
            } else {
#pragma unroll
                for (int ni = 0; ni < NT; ni++) {
                    int n0 = wn * WTN + ni * 8 + gid;
                    bf[ni][0] = pB[(k + tig) * LDB + n0];
                    bf[ni][1] = pB[(k + tig + 4) * LDB + n0];
                }
            }
#pragma unroll
            for (int mi = 0; mi < MT; mi++)
#pragma unroll
                for (int ni = 0; ni < NT; ni++)
                    mma8(acc[mi][ni], af[mi], bf[ni]);
        }
    };

    const int nt = K / BK;
    cpA(0, 0); cpB(0, 0); cpcommit();
    if (nt > 1) { cpA(BK, 1); cpB(BK, 1); cpcommit(); }

    for (int t = 0; t < nt; t++) {
        if (t < nt - 1) cpwait<1>(); else cpwait<0>();
        __syncthreads();
        cvtp(t & 1);
        __syncthreads();
        compute(t & 1);
        if (t + 2 < nt) {
            __syncthreads();
            cpA((t + 2) * BK, t & 1); cpB((t + 2) * BK, t & 1); cpcommit();
        }
    }

    // ---- epilogue ----
    auto emit = [&](int r, int c, float v) {
        if (EPI == EPI_SCALE) v *= scale;
        if (EPI == EPI_BIAS || EPI == EPI_BIAS_RES || EPI == EPI_BIAS_GELU || EPI == EPI_CONV)
            v += bias[c];
        if (EPI == EPI_BIAS_GELU)
            v = 0.5f * v * (1.f + erff(v * 0.70710678118654752f));
        if (EPI == EPI_CONV) {
            int b_ = r >> 7;
            int s_ = r & 127;
            int t_ = s_ * 4 + hh;
            C[((long)b_ * TT + t_) * ldc + c] = v + resid[t_ * H + c];
        } else {
            long idx = coff + (long)r * ldc + c;
            if (EPI == EPI_BIAS_RES) v += resid[idx];
            C[idx] = v;
        }
    };

#pragma unroll
    for (int mi = 0; mi < MT; mi++) {
        int r0 = row0 + wm * WTM + mi * 16 + gid;
#pragma unroll
        for (int ni = 0; ni < NT; ni++) {
            int c0 = col0 + wn * WTN + ni * 8 + tig * 2;
            if (c0 < N)     emit(r0,     c0,     acc[mi][ni][0]);
            if (c0 + 1 < N) emit(r0,     c0 + 1, acc[mi][ni][1]);
            if (c0 < N)     emit(r0 + 8, c0,     acc[mi][ni][2]);
            if (c0 + 1 < N) emit(r0 + 8, c0 + 1, acc[mi][ni][3]);
        }
    }
}

// ---------------- LayerNorm ----------------
__global__ void ln_k(const float* __restrict__ x, const float* __restrict__ g,
                     const float* __restrict__ b, float* __restrict__ o)
{
    long row = blockIdx.x;
    int t = threadIdx.x;
    float4 v = ((const float4*)(x + row * H))[t];
    float s = v.x + v.y + v.z + v.w;
    float ss = v.x * v.x + v.y * v.y + v.z * v.z + v.w * v.w;
#pragma unroll
    for (int off = 16; off; off >>= 1) {
        s += __shfl_xor_sync(0xffffffffu, s, off);
        ss += __shfl_xor_sync(0xffffffffu, ss, off);
    }
    __shared__ float sm0[4], sm1[4];
    int w = t >> 5;
    if ((t & 31) == 0) { sm0[w] = s; sm1[w] = ss; }
    __syncthreads();
    s = sm0[0] + sm0[1] + sm0[2] + sm0[3];
    ss = sm1[0] + sm1[1] + sm1[2] + sm1[3];
    float mean = s * (1.f / H);
    float var = ss * (1.f / H) - mean * mean;
    float rstd = rsqrtf(var + 1e-5f);
    float4 gg = ((const float4*)g)[t];
    float4 bb4 = ((const float4*)b)[t];
    float4 out;
    out.x = (v.x - mean) * rstd * gg.x + bb4.x;
    out.y = (v.y - mean) * rstd * gg.y + bb4.y;
    out.z = (v.z - mean) * rstd * gg.z + bb4.z;
    out.w = (v.w - mean) * rstd * gg.w + bb4.w;
    ((float4*)(o + row * H))[t] = out;
}

// ---------------- softmax ----------------
__global__ void softmax_k(float* __restrict__ sc)
{
    long row = blockIdx.x;
    int t = threadIdx.x;
    float4* p = (float4*)(sc + row * 512);
    float4 v = p[t];
    float mx = fmaxf(fmaxf(v.x, v.y), fmaxf(v.z, v.w));
#pragma unroll
    for (int off = 16; off; off >>= 1) mx = fmaxf(mx, __shfl_xor_sync(0xffffffffu, mx, off));
    __shared__ float sm0[4], sm1[4];
    int w = t >> 5;
    if ((t & 31) == 0) sm0[w] = mx;
    __syncthreads();
    mx = fmaxf(fmaxf(sm0[0], sm0[1]), fmaxf(sm0[2], sm0[3]));
    v.x = expf(v.x - mx); v.y = expf(v.y - mx);
    v.z = expf(v.z - mx); v.w = expf(v.w - mx);
    float s = v.x + v.y + v.z + v.w;
#pragma unroll
    for (int off = 16; off; off >>= 1) s += __shfl_xor_sync(0xffffffffu, s, off);
    if ((t & 31) == 0) sm1[w] = s;
    __syncthreads();
    s = sm1[0] + sm1[1] + sm1[2] + sm1[3];
    float inv = 1.f / s;
    v.x *= inv; v.y *= inv; v.z *= inv; v.w *= inv;
    p[t] = v;
}

// ---------------- misc kernels ----------------
__global__ void pe_k(float* __restrict__ pe)
{
    int t = blockIdx.x;
    int i = threadIdx.x;
    float div = expf(-(float)(2 * i) * (logf(10000.f) / (float)H));
    float a = (float)t * div;
    pe[t * H + 2 * i] = sinf(a);
    pe[t * H + 2 * i + 1] = cosf(a);
}

__global__ void convT_k(const float* __restrict__ w, float* __restrict__ o)
{
    int idx = blockIdx.x * blockDim.x + threadIdx.x;
    if (idx >= 4 * H * H) return;
    int k = idx / (H * H);
    int d = (idx / H) % H;
    int c = idx % H;
    o[idx] = w[c * H * 4 + d * 4 + k];
}

__global__ void xinit_k(const float* __restrict__ qe, const float* __restrict__ pe,
                        float* __restrict__ x)
{
    long i = blockIdx.x * (long)blockDim.x + threadIdx.x;
    if (i >= (long)BB * TT * H) return;
    int td = (int)(i % (TT * H));
    x[i] = qe[td] + pe[td];
}

__global__ void kin_k(const float* __restrict__ ho, float* __restrict__ out)
{
    int row = blockIdx.x * blockDim.x + threadIdx.x;
    if (row >= BB * TT) return;
    const float* r = ho + (long)row * NOUT;
    float* o = out + (long)row * (3 * NJ);
    float gx[NJ], px[NJ], py[NJ];
    gx[0] = 0.f;
    px[0] = r[100];
    py[0] = r[101];
    o[0] = px[0]; o[1] = py[0]; o[2] = 1.f;
    for (int j = 1; j < NJ; j++) {
        int pa = PAR[j];
        float gg = gx[pa] + r[j];
        gx[j] = gg;
        float s = r[50 + j];
        float sn, cs;
        sincosf(gg, &sn, &cs);
        px[j] = px[pa] + cs * s;
        py[j] = py[pa] + sn * s;
        o[j * 3 + 0] = px[j];
        o[j * 3 + 1] = py[j];
        o[j * 3 + 2] = 1.f;
    }
}

// ---------------- launcher ----------------
static inline dim3 gg128(int M, int N, int bz = 1)
{
    return dim3((N + 127) / 128, (M + 127) / 128, bz);
}

#define Z6 0L, 0L, 0L, 0L, 0L, 0L

#define SMEM_T128 73728
#define SMEM_N64  54272

extern "C" void kernel_launch(void* const* d_in, const int* in_sizes, int n_in,
                              void* d_out, int out_size)
{
    const float* memory   = (const float*)d_in[0];
    const float* in_w     = (const float*)d_in[1];
    const float* in_b     = (const float*)d_in[2];
    const float* conv_w   = (const float*)d_in[3];
    const float* conv_b   = (const float*)d_in[4];
    const float* qemb     = (const float*)d_in[5];
    const float* sa_in_w  = (const float*)d_in[6];
    const float* sa_in_b  = (const float*)d_in[7];
    const float* sa_out_w = (const float*)d_in[8];
    const float* sa_out_b = (const float*)d_in[9];
    const float* ca_in_w  = (const float*)d_in[10];
    const float* ca_in_b  = (const float*)d_in[11];
    const float* ca_out_w = (const float*)d_in[12];
    const float* ca_out_b = (const float*)d_in[13];
    const float* ln1_g    = (const float*)d_in[14];
    const float* ln1_b    = (const float*)d_in[15];
    const float* ln2_g    = (const float*)d_in[16];
    const float* ln2_b    = (const float*)d_in[17];
    const float* ln3_g    = (const float*)d_in[18];
    const float* ln3_b    = (const float*)d_in[19];
    const float* ff1_w    = (const float*)d_in[20];
    const float* ff1_b    = (const float*)d_in[21];
    const float* ff2_w    = (const float*)d_in[22];
    const float* ff2_b    = (const float*)d_in[23];
    const float* out_w    = (const float*)d_in[24];
    const float* out_b    = (const float*)d_in[25];

    float *m_, *mem_, *x_, *h_, *qkv_, *sc_, *att_, *ff_, *ho_, *pe_, *cT_;
    cudaGetSymbolAddress((void**)&m_,   g_m);
    cudaGetSymbolAddress((void**)&mem_, g_mem);
    cudaGetSymbolAddress((void**)&x_,   g_x);
    cudaGetSymbolAddress((void**)&h_,   g_h);
    cudaGetSymbolAddress((void**)&qkv_, g_qkv);
    cudaGetSymbolAddress((void**)&sc_,  g_scores);
    cudaGetSymbolAddress((void**)&att_, g_att);
    cudaGetSymbolAddress((void**)&ff_,  g_ff);
    cudaGetSymbolAddress((void**)&ho_,  g_head);
    cudaGetSymbolAddress((void**)&pe_,  g_pe);
    cudaGetSymbolAddress((void**)&cT_,  g_convT);

    cudaFuncSetAttribute(gemm4<true,  EPI_BIAS,      128>, cudaFuncAttributeMaxDynamicSharedMemorySize, SMEM_T128);
    cudaFuncSetAttribute(gemm4<true,  EPI_CONV,      128>, cudaFuncAttributeMaxDynamicSharedMemorySize, SMEM_T128);
    cudaFuncSetAttribute(gemm4<true,  EPI_SCALE,     128>, cudaFuncAttributeMaxDynamicSharedMemorySize, SMEM_T128);
    cudaFuncSetAttribute(gemm4<true,  EPI_BIAS_RES,  128>, cudaFuncAttributeMaxDynamicSharedMemorySize, SMEM_T128);
    cudaFuncSetAttribute(gemm4<true,  EPI_BIAS_GELU, 128>, cudaFuncAttributeMaxDynamicSharedMemorySize, SMEM_T128);
    cudaFuncSetAttribute(gemm4<false, EPI_NONE,       64>, cudaFuncAttributeMaxDynamicSharedMemorySize, SMEM_N64);

    pe_k<<<TT, 256>>>(pe_);
    convT_k<<<(4 * H * H + 255) / 256, 256>>>(conv_w, cT_);

    gemm4<true, EPI_BIAS, 128><<<gg128(BB * SS, H), 256, SMEM_T128>>>(
        memory, in_w, in_b, nullptr, m_,
        BB * SS, H, H, H, H, H, Z6, 1, 1.f);

    gemm4<true, EPI_CONV, 128><<<gg128(BB * SS, H, 4), 256, SMEM_T128>>>(
        m_, cT_, conv_b, pe_, mem_,
        BB * SS, H, H, H, H, H,
        0L, 0L, 0L, (long)H * H, 0L, 0L, 4, 1.f);

    xinit_k<<<(BB * TT * H + 255) / 256, 256>>>(qemb, pe_, x_);

    const long sQb = (long)TT * 3 * H;
    const long sScb = (long)NHEAD * TT * TT;
    const long sSch = (long)TT * TT;

    for (int l = 0; l < NL; l++) {
        // ======== self-attention ========
        ln_k<<<BB * TT, 128>>>(x_, ln1_g + l * H, ln1_b + l * H, h_);
        gemm4<true, EPI_BIAS, 128><<<gg128(BB * TT, 3 * H), 256, SMEM_T128>>>(
            h_, sa_in_w + (long)l * 3 * H * H, sa_in_b + (long)l * 3 * H, nullptr, qkv_,
            BB * TT, 3 * H, H, H, H, 3 * H, Z6, 1, 1.f);
        gemm4<true, EPI_SCALE, 128><<<dim3(4, 4, BB * NHEAD), 256, SMEM_T128>>>(
            qkv_, qkv_ + H, nullptr, nullptr, sc_,
            TT, TT, DHD, 3 * H, 3 * H, TT,
            sQb, (long)DHD, sQb, (long)DHD, sScb, sSch,
            NHEAD, 0.125f);
        softmax_k<<<BB * NHEAD * TT, 128>>>(sc_);
        gemm4<false, EPI_NONE, 64><<<dim3(1, 4, BB * NHEAD), 256, SMEM_N64>>>(
            sc_, qkv_ + 2 * H, nullptr, nullptr, att_,
            TT, DHD, TT, TT, 3 * H, H,
            sScb, sSch, sQb, (long)DHD, (long)TT * H, (long)DHD,
            NHEAD, 1.f);
        gemm4<true, EPI_BIAS_RES, 128><<<gg128(BB * TT, H), 256, SMEM_T128>>>(
            att_, sa_out_w + (long)l * H * H, sa_out_b + (long)l * H, x_, x_,
            BB * TT, H, H, H, H, H, Z6, 1, 1.f);

        // ======== cross-attention ========
        ln_k<<<BB * TT, 128>>>(x_, ln2_g + l * H, ln2_b + l * H, h_);
        gemm4<true, EPI_BIAS, 128><<<gg128(BB * TT, H), 256, SMEM_T128>>>(
            h_, ca_in_w + (long)l * 3 * H * H, ca_in_b + (long)l * 3 * H, nullptr, qkv_,
            BB * TT, H, H, H, H, 3 * H, Z6, 1, 1.f);
        gemm4<true, EPI_BIAS, 128><<<gg128(BB * TT, 2 * H), 256, SMEM_T128>>>(
            mem_, ca_in_w + (long)l * 3 * H * H + (long)H * H,
            ca_in_b + (long)l * 3 * H + H, nullptr, qkv_ + H,
            BB * TT, 2 * H, H, H, H, 3 * H, Z6, 1, 1.f);
        gemm4<true, EPI_SCALE, 128><<<dim3(4, 4, BB * NHEAD), 256, SMEM_T128>>>(
            qkv_, qkv_ + H, nullptr, nullptr, sc_,
            TT, TT, DHD, 3 * H, 3 * H, TT,
            sQb, (long)DHD, sQb, (long)DHD, sScb, sSch,
            NHEAD, 0.125f);
        softmax_k<<<BB * NHEAD * TT, 128>>>(sc_);
        gemm4<false, EPI_NONE, 64><<<dim3(1, 4, BB * NHEAD), 256, SMEM_N64>>>(
            sc_, qkv_ + 2 * H, nullptr, nullptr, att_,
            TT, DHD, TT, TT, 3 * H, H,
            sScb, sSch, sQb, (long)DHD, (long)TT * H, (long)DHD,
            NHEAD, 1.f);
        gemm4<true, EPI_BIAS_RES, 128><<<gg128(BB * TT, H), 256, SMEM_T128>>>(
            att_, ca_out_w + (long)l * H * H, ca_out_b + (long)l * H, x_, x_,
            BB * TT, H, H, H, H, H, Z6, 1, 1.f);

        // ======== FFN ========
        ln_k<<<BB * TT, 128>>>(x_, ln3_g + l * H, ln3_b + l * H, h_);
        gemm4<true, EPI_BIAS_GELU, 128><<<gg128(BB * TT, FF), 256, SMEM_T128>>>(
            h_, ff1_w + (long)l * FF * H, ff1_b + (long)l * FF, nullptr, ff_,
            BB * TT, FF, H, H, H, FF, Z6, 1, 1.f);
        gemm4<true, EPI_BIAS_RES, 128><<<gg128(BB * TT, H), 256, SMEM_T128>>>(
            ff_, ff2_w + (long)l * H * FF, ff2_b + (long)l * H, x_, x_,
            BB * TT, H, FF, FF, FF, H, Z6, 1, 1.f);
    }

    gemm4<true, EPI_BIAS, 128><<<gg128(BB * TT, NOUT), 256, SMEM_T128>>>(
        x_, out_w, out_b, nullptr, ho_,
        BB * TT, NOUT, H, H, H, NOUT, Z6, 1, 1.f);

    kin_k<<<(BB * TT + 255) / 256, 256>>>(ho_, (float*)d_out);
}

// round 5
// speedup vs baseline: 1.2469x; 1.2469x over previous
#include <cuda_runtime.h>
#include <math.h>
#include <stdint.h>

#define H 512
#define BB 32
#define SS 128
#define TT 512
#define NHEAD 8
#define DHD 64
#define NL 4
#define FF 2048
#define NOUT 102
#define NJ 50

// ---------------- scratch ----------------
__device__ float g_m[BB * SS * H];
__device__ float g_mem[BB * TT * H];
__device__ float g_x[BB * TT * H];
__device__ float g_h[BB * TT * H];
__device__ float g_qkv[BB * TT * 3 * H];
__device__ float g_att[BB * TT * H];
__device__ float g_ff[BB * TT * FF];
__device__ float g_head[BB * TT * NOUT];
__device__ float g_pe[TT * H];
__device__ float g_convT[4 * H * H];

__constant__ int PAR[NJ] = {
    -1, 0, 1, 2, 3, 1, 5, 6, 1,
    4, 9, 10, 11,  4, 13, 14, 15,  4, 17, 18, 19,  4, 21, 22, 23,  4, 25, 26, 27,
    7, 29, 30, 31, 7, 33, 34, 35,  7, 37, 38, 39,  7, 41, 42, 43,  7, 45, 46, 47,
    8
};

#define EPI_NONE 0
#define EPI_SCALE 1
#define EPI_BIAS 2
#define EPI_BIAS_RES 3
#define EPI_BIAS_GELU 4
#define EPI_CONV 5

// ---------------- ptx helpers ----------------
__device__ __forceinline__ uint32_t f2tf(float f)
{
    uint32_t u;
    asm("cvt.rna.tf32.f32 %0, %1;" : "=r"(u) : "f"(f));
    return u;
}
__device__ __forceinline__ void cp16(uint32_t dst, const void* src)
{
    asm volatile("cp.async.cg.shared.global [%0], [%1], 16;\n" :: "r"(dst), "l"(src));
}
__device__ __forceinline__ void cp16z(uint32_t dst, const void* src, bool p)
{
    int sz = p ? 16 : 0;
    asm volatile("cp.async.cg.shared.global [%0], [%1], 16, %2;\n"
                 :: "r"(dst), "l"(src), "r"(sz));
}
__device__ __forceinline__ void cpcommit()
{
    asm volatile("cp.async.commit_group;\n" ::: "memory");
}
template <int W>
__device__ __forceinline__ void cpwait()
{
    asm volatile("cp.async.wait_group %0;\n" :: "n"(W) : "memory");
}
__device__ __forceinline__ void mma8(float* d, const uint32_t* a, const uint32_t* b)
{
    asm volatile(
        "mma.sync.aligned.m16n8k8.row.col.f32.tf32.tf32.f32 "
        "{%0,%1,%2,%3}, {%4,%5,%6,%7}, {%8,%9}, {%0,%1,%2,%3};\n"
        : "+f"(d[0]), "+f"(d[1]), "+f"(d[2]), "+f"(d[3])
        : "r"(a[0]), "r"(a[1]), "r"(a[2]), "r"(a[3]), "r"(b[0]), "r"(b[1]));
}

// ---------------- tf32 tensor-core GEMM (round-3 version, reverted) ----------------
template <bool TRANSB, int EPI, int BN_>
__global__ void __launch_bounds__(256, 2) gemm3(
    const float* __restrict__ A, const float* __restrict__ Bm,
    const float* __restrict__ bias, const float* __restrict__ resid,
    float* __restrict__ C,
    int M, int N, int K, int lda, int ldb, int ldc,
    long sAb, long sAh, long sBb, long sBh, long sCb, long sCh,
    int nh, float scale)
{
    constexpr int BM = 128, BK = 32;
    constexpr int WGN = 4;
    constexpr int WTM = 64, WTN = BN_ / WGN;
    constexpr int MT = WTM / 16;
    constexpr int NT = WTN / 8;
    constexpr int LDA = BK + 4;
    constexpr int LDB = TRANSB ? (BK + 4) : (BN_ + 4);
    constexpr int SBR = TRANSB ? BN_ : BK;
    constexpr int ACH = BM * BK / 4 / 256;
    constexpr int BCH = SBR * (TRANSB ? BK : BN_) / 4 / 256;

    extern __shared__ float sm[];
    float* sA = sm;
    float* sB = sm + 2 * BM * LDA;
    const uint32_t sAu = (uint32_t)__cvta_generic_to_shared(sA);
    const uint32_t sBu = (uint32_t)__cvta_generic_to_shared(sB);

    const int z = blockIdx.z;
    const int bb = z / nh, hh = z - bb * nh;
    A += (long)bb * sAb + (long)hh * sAh;
    Bm += (long)bb * sBb + (long)hh * sBh;
    const long coff = (long)bb * sCb + (long)hh * sCh;

    const int row0 = blockIdx.y * BM;
    const int col0 = blockIdx.x * BN_;
    const int tid = threadIdx.x;
    const int warp = tid >> 5;
    const int lane = tid & 31;
    const int wm = warp >> 2;
    const int wn = warp & 3;
    const int gid = lane >> 2;
    const int tig = lane & 3;

    float acc[MT][NT][4];
#pragma unroll
    for (int i = 0; i < MT; i++)
#pragma unroll
        for (int j = 0; j < NT; j++)
#pragma unroll
            for (int q = 0; q < 4; q++) acc[i][j][q] = 0.f;

    auto cpA = [&](int k0, int st) {
#pragma unroll
        for (int l = 0; l < ACH; l++) {
            int idx = l * 256 + tid;
            int r = idx >> 3;
            int cq = (idx & 7) * 4;
            cp16(sAu + (uint32_t)(st * BM * LDA + r * LDA + cq) * 4,
                 A + (long)(row0 + r) * lda + k0 + cq);
        }
    };
    auto cpB = [&](int k0, int st) {
        if (TRANSB) {
#pragma unroll
            for (int l = 0; l < BCH; l++) {
                int idx = l * 256 + tid;
                int n = idx >> 3;
                int cq = (idx & 7) * 4;
                cp16z(sBu + (uint32_t)(st * SBR * LDB + n * LDB + cq) * 4,
                      Bm + (long)(col0 + n) * ldb + k0 + cq,
                      (col0 + n) < N);
            }
        } else {
#pragma unroll
            for (int l = 0; l < BCH; l++) {
                int idx = l * 256 + tid;
                int kk = idx / (BN_ / 4);
                int nq = (idx % (BN_ / 4)) * 4;
                cp16(sBu + (uint32_t)(st * SBR * LDB + kk * LDB + nq) * 4,
                     Bm + (long)(k0 + kk) * ldb + col0 + nq);
            }
        }
    };

    auto compute = [&](int st) {
        const float* pA = sA + st * BM * LDA;
        const float* pB = sB + st * SBR * LDB;
#pragma unroll
        for (int ks = 0; ks < 4; ks++) {
            const int k = ks * 8;
            uint32_t af[MT][4], bf[NT][2];
#pragma unroll
            for (int mi = 0; mi < MT; mi++) {
                int r0 = wm * WTM + mi * 16 + gid;
                af[mi][0] = f2tf(pA[r0 * LDA + k + tig]);
                af[mi][1] = f2tf(pA[(r0 + 8) * LDA + k + tig]);
                af[mi][2] = f2tf(pA[r0 * LDA + k + tig + 4]);
                af[mi][3] = f2tf(pA[(r0 + 8) * LDA + k + tig + 4]);
            }
#pragma unroll
            for (int ni = 0; ni < NT; ni++) {
                int n0 = wn * WTN + ni * 8 + gid;
                if (TRANSB) {
                    bf[ni][0] = f2tf(pB[n0 * LDB + k + tig]);
                    bf[ni][1] = f2tf(pB[n0 * LDB + k + tig + 4]);
                } else {
                    bf[ni][0] = f2tf(pB[(k + tig) * LDB + n0]);
                    bf[ni][1] = f2tf(pB[(k + tig + 4) * LDB + n0]);
                }
            }
#pragma unroll
            for (int mi = 0; mi < MT; mi++)
#pragma unroll
                for (int ni = 0; ni < NT; ni++)
                    mma8(acc[mi][ni], af[mi], bf[ni]);
        }
    };

    const int nt = K / BK;
    cpA(0, 0); cpB(0, 0); cpcommit();
    if (nt > 1) { cpA(BK, 1); cpB(BK, 1); cpcommit(); }

    for (int t = 0; t < nt; t++) {
        if (t < nt - 1) cpwait<1>(); else cpwait<0>();
        __syncthreads();
        compute(t & 1);
        __syncthreads();
        if (t + 2 < nt) { cpA((t + 2) * BK, t & 1); cpB((t + 2) * BK, t & 1); cpcommit(); }
    }

    auto emit = [&](int r, int c, float v) {
        if (EPI == EPI_SCALE) v *= scale;
        if (EPI == EPI_BIAS || EPI == EPI_BIAS_RES || EPI == EPI_BIAS_GELU || EPI == EPI_CONV)
            v += bias[c];
        if (EPI == EPI_BIAS_GELU)
            v = 0.5f * v * (1.f + erff(v * 0.70710678118654752f));
        if (EPI == EPI_CONV) {
            int b_ = r >> 7;
            int s_ = r & 127;
            int t_ = s_ * 4 + hh;
            C[((long)b_ * TT + t_) * ldc + c] = v + resid[t_ * H + c];
        } else {
            long idx = coff + (long)r * ldc + c;
            if (EPI == EPI_BIAS_RES) v += resid[idx];
            C[idx] = v;
        }
    };

#pragma unroll
    for (int mi = 0; mi < MT; mi++) {
        int r0 = row0 + wm * WTM + mi * 16 + gid;
#pragma unroll
        for (int ni = 0; ni < NT; ni++) {
            int c0 = col0 + wn * WTN + ni * 8 + tig * 2;
            if (c0 < N)     emit(r0,     c0,     acc[mi][ni][0]);
            if (c0 + 1 < N) emit(r0,     c0 + 1, acc[mi][ni][1]);
            if (c0 < N)     emit(r0 + 8, c0,     acc[mi][ni][2]);
            if (c0 + 1 < N) emit(r0 + 8, c0 + 1, acc[mi][ni][3]);
        }
    }
}

// ---------------- fused flash attention (tf32 MMA, online softmax) ----------------
// grid: (TT/128, BB*NHEAD). CTA: 256 threads. Q tile 128 x 64, K/V streamed 128 keys.
// qkv packed rows of 3H: q @ +0, k @ +H, v @ +2H; head offset hh*64. scale 1/8 folded into Q.
#define FA_SQ 0
#define FA_SK 8704
#define FA_SV 17408
#define FA_SP 26112          // 128 x 132
#define FA_RED 43008         // 4 x 128
#define FA_M 43520
#define FA_L 43648
#define FA_AL 43776
#define FA_SMEM_FLOATS 43904
#define FA_SMEM_BYTES (FA_SMEM_FLOATS * 4)

__global__ void __launch_bounds__(256, 1) fattn_k(
    const float* __restrict__ qkv, float* __restrict__ att)
{
    extern __shared__ float sm[];
    float* sQ = sm + FA_SQ;
    float* sK = sm + FA_SK;
    float* sV = sm + FA_SV;
    float* sP = sm + FA_SP;
    float* sRed = sm + FA_RED;
    float* sM = sm + FA_M;
    float* sL = sm + FA_L;
    float* sAl = sm + FA_AL;
    const uint32_t smu = (uint32_t)__cvta_generic_to_shared(sm);
    const uint32_t* uQ = (const uint32_t*)sQ;
    const uint32_t* uK = (const uint32_t*)sK;
    const uint32_t* uV = (const uint32_t*)sV;
    const uint32_t* uP = (const uint32_t*)sP;

    const int z = blockIdx.y;
    const int bb = z >> 3, hh = z & 7;
    const int q0 = blockIdx.x * 128;
    const long base = (long)bb * TT * 3 * H + (long)hh * DHD;

    const int tid = threadIdx.x;
    const int warp = tid >> 5, lane = tid & 31;
    const int wm = warp >> 2, wn = warp & 3;
    const int gid = lane >> 2, tig = lane & 3;

    // ---- load + preconvert Q (scaled by 1/8) ----
#pragma unroll
    for (int l = 0; l < 8; l++) {
        int idx = l * 256 + tid;
        int r = idx >> 4, c4 = (idx & 15) * 4;
        cp16(smu + (uint32_t)(FA_SQ + r * 68 + c4) * 4,
             qkv + base + (long)(q0 + r) * (3 * H) + c4);
    }
    cpcommit();
    cpwait<0>();
    __syncthreads();
#pragma unroll
    for (int l = 0; l < 8; l++) {
        int idx = l * 256 + tid;
        int r = idx >> 4, c4 = (idx & 15) * 4;
        float4* p = (float4*)&sQ[r * 68 + c4];
        float4 v = *p;
        v.x = __uint_as_float(f2tf(v.x * 0.125f));
        v.y = __uint_as_float(f2tf(v.y * 0.125f));
        v.z = __uint_as_float(f2tf(v.z * 0.125f));
        v.w = __uint_as_float(f2tf(v.w * 0.125f));
        *p = v;
    }
    if (tid < 128) { sM[tid] = -1e30f; sL[tid] = 0.f; }

    float oacc[4][2][4];
#pragma unroll
    for (int mi = 0; mi < 4; mi++)
#pragma unroll
        for (int ni = 0; ni < 2; ni++)
#pragma unroll
            for (int q = 0; q < 4; q++) oacc[mi][ni][q] = 0.f;

    for (int j = 0; j < 4; j++) {
        __syncthreads();   // protect sK/sV reuse; publish Q cvt on first iter
        // ---- load K_j, V_j ----
#pragma unroll
        for (int l = 0; l < 8; l++) {
            int idx = l * 256 + tid;
            int r = idx >> 4, c4 = (idx & 15) * 4;
            long row = (long)(j * 128 + r) * (3 * H);
            cp16(smu + (uint32_t)(FA_SK + r * 68 + c4) * 4, qkv + base + H + row + c4);
            cp16(smu + (uint32_t)(FA_SV + r * 68 + c4) * 4, qkv + base + 2 * H + row + c4);
        }
        cpcommit();
        cpwait<0>();
        __syncthreads();
        // ---- preconvert K, V ----
#pragma unroll
        for (int l = 0; l < 8; l++) {
            int idx = l * 256 + tid;
            int r = idx >> 4, c4 = (idx & 15) * 4;
            float4* pk = (float4*)&sK[r * 68 + c4];
            float4 vk = *pk;
            vk.x = __uint_as_float(f2tf(vk.x));
            vk.y = __uint_as_float(f2tf(vk.y));
            vk.z = __uint_as_float(f2tf(vk.z));
            vk.w = __uint_as_float(f2tf(vk.w));
            *pk = vk;
            float4* pv = (float4*)&sV[r * 68 + c4];
            float4 vv = *pv;
            vv.x = __uint_as_float(f2tf(vv.x));
            vv.y = __uint_as_float(f2tf(vv.y));
            vv.z = __uint_as_float(f2tf(vv.z));
            vv.w = __uint_as_float(f2tf(vv.w));
            *pv = vv;
        }
        __syncthreads();

        // ---- S = Q @ K_j^T  (128x128, k=64) ----
        float sacc[4][4][4];
#pragma unroll
        for (int mi = 0; mi < 4; mi++)
#pragma unroll
            for (int ni = 0; ni < 4; ni++)
#pragma unroll
                for (int q = 0; q < 4; q++) sacc[mi][ni][q] = 0.f;
#pragma unroll
        for (int ks = 0; ks < 8; ks++) {
            const int k = ks * 8;
            uint32_t af[4][4], bf[4][2];
#pragma unroll
            for (int mi = 0; mi < 4; mi++) {
                int r0 = wm * 64 + mi * 16 + gid;
                af[mi][0] = uQ[r0 * 68 + k + tig];
                af[mi][1] = uQ[(r0 + 8) * 68 + k + tig];
                af[mi][2] = uQ[r0 * 68 + k + tig + 4];
                af[mi][3] = uQ[(r0 + 8) * 68 + k + tig + 4];
            }
#pragma unroll
            for (int ni = 0; ni < 4; ni++) {
                int n0 = wn * 32 + ni * 8 + gid;
                bf[ni][0] = uK[n0 * 68 + k + tig];
                bf[ni][1] = uK[n0 * 68 + k + tig + 4];
            }
#pragma unroll
            for (int mi = 0; mi < 4; mi++)
#pragma unroll
                for (int ni = 0; ni < 4; ni++)
                    mma8(sacc[mi][ni], af[mi], bf[ni]);
        }

        // ---- row max (tile) ----
#pragma unroll
        for (int mi = 0; mi < 4; mi++) {
            float r0m = -1e30f, r1m = -1e30f;
#pragma unroll
            for (int ni = 0; ni < 4; ni++) {
                r0m = fmaxf(r0m, fmaxf(sacc[mi][ni][0], sacc[mi][ni][1]));
                r1m = fmaxf(r1m, fmaxf(sacc[mi][ni][2], sacc[mi][ni][3]));
            }
            r0m = fmaxf(r0m, __shfl_xor_sync(0xffffffffu, r0m, 1));
            r0m = fmaxf(r0m, __shfl_xor_sync(0xffffffffu, r0m, 2));
            r1m = fmaxf(r1m, __shfl_xor_sync(0xffffffffu, r1m, 1));
            r1m = fmaxf(r1m, __shfl_xor_sync(0xffffffffu, r1m, 2));
            if (tig == 0) {
                int r0 = wm * 64 + mi * 16 + gid;
                sRed[wn * 128 + r0] = r0m;
                sRed[wn * 128 + r0 + 8] = r1m;
            }
        }
        __syncthreads();
        if (tid < 128) {
            float mt = fmaxf(fmaxf(sRed[tid], sRed[128 + tid]),
                             fmaxf(sRed[256 + tid], sRed[384 + tid]));
            float mo = sM[tid];
            float mn = fmaxf(mo, mt);
            sAl[tid] = __expf(mo - mn);
            sM[tid] = mn;
        }
        __syncthreads();

        // ---- P = exp(S - m), rowsum, store P to smem (tf32 bits) ----
#pragma unroll
        for (int mi = 0; mi < 4; mi++) {
            int r0 = wm * 64 + mi * 16 + gid;
            float m0 = sM[r0], m1 = sM[r0 + 8];
            float rs0 = 0.f, rs1 = 0.f;
#pragma unroll
            for (int ni = 0; ni < 4; ni++) {
                int c0 = wn * 32 + ni * 8 + tig * 2;
                float p00 = __expf(sacc[mi][ni][0] - m0);
                float p01 = __expf(sacc[mi][ni][1] - m0);
                float p10 = __expf(sacc[mi][ni][2] - m1);
                float p11 = __expf(sacc[mi][ni][3] - m1);
                rs0 += p00 + p01;
                rs1 += p10 + p11;
                *(float2*)&sP[r0 * 132 + c0] =
                    make_float2(__uint_as_float(f2tf(p00)), __uint_as_float(f2tf(p01)));
                *(float2*)&sP[(r0 + 8) * 132 + c0] =
                    make_float2(__uint_as_float(f2tf(p10)), __uint_as_float(f2tf(p11)));
            }
            rs0 += __shfl_xor_sync(0xffffffffu, rs0, 1);
            rs0 += __shfl_xor_sync(0xffffffffu, rs0, 2);
            rs1 += __shfl_xor_sync(0xffffffffu, rs1, 1);
            rs1 += __shfl_xor_sync(0xffffffffu, rs1, 2);
            if (tig == 0) {
                sRed[wn * 128 + r0] = rs0;
                sRed[wn * 128 + r0 + 8] = rs1;
            }
        }
        __syncthreads();
        if (tid < 128) {
            sL[tid] = sL[tid] * sAl[tid] +
                      (sRed[tid] + sRed[128 + tid]) + (sRed[256 + tid] + sRed[384 + tid]);
        }

        // ---- rescale O by alpha ----
#pragma unroll
        for (int mi = 0; mi < 4; mi++) {
            int r0 = wm * 64 + mi * 16 + gid;
            float a0 = sAl[r0], a1 = sAl[r0 + 8];
#pragma unroll
            for (int ni = 0; ni < 2; ni++) {
                oacc[mi][ni][0] *= a0;
                oacc[mi][ni][1] *= a0;
                oacc[mi][ni][2] *= a1;
                oacc[mi][ni][3] *= a1;
            }
        }

        // ---- O += P @ V_j  (128x64, k=128) ----
#pragma unroll
        for (int ks = 0; ks < 16; ks++) {
            const int k = ks * 8;
            uint32_t af[4][4], bf[2][2];
#pragma unroll
            for (int mi = 0; mi < 4; mi++) {
                int r0 = wm * 64 + mi * 16 + gid;
                af[mi][0] = uP[r0 * 132 + k + tig];
                af[mi][1] = uP[(r0 + 8) * 132 + k + tig];
                af[mi][2] = uP[r0 * 132 + k + tig + 4];
                af[mi][3] = uP[(r0 + 8) * 132 + k + tig + 4];
            }
#pragma unroll
            for (int ni = 0; ni < 2; ni++) {
                int n0 = wn * 16 + ni * 8 + gid;
                bf[ni][0] = uV[(k + tig) * 68 + n0];
                bf[ni][1] = uV[(k + tig + 4) * 68 + n0];
            }
#pragma unroll
            for (int mi = 0; mi < 4; mi++)
#pragma unroll
                for (int ni = 0; ni < 2; ni++)
                    mma8(oacc[mi][ni], af[mi], bf[ni]);
        }
    }
    __syncthreads();   // sL final values visible

    // ---- O /= l, write out ----
#pragma unroll
    for (int mi = 0; mi < 4; mi++) {
        int r0 = wm * 64 + mi * 16 + gid;
        float i0 = 1.f / sL[r0], i1 = 1.f / sL[r0 + 8];
        long o0 = ((long)bb * TT + q0 + r0) * H + hh * DHD;
        long o1 = ((long)bb * TT + q0 + r0 + 8) * H + hh * DHD;
#pragma unroll
        for (int ni = 0; ni < 2; ni++) {
            int c0 = wn * 16 + ni * 8 + tig * 2;
            *(float2*)&att[o0 + c0] = make_float2(oacc[mi][ni][0] * i0, oacc[mi][ni][1] * i0);
            *(float2*)&att[o1 + c0] = make_float2(oacc[mi][ni][2] * i1, oacc[mi][ni][3] * i1);
        }
    }
}

// ---------------- LayerNorm ----------------
__global__ void ln_k(const float* __restrict__ x, const float* __restrict__ g,
                     const float* __restrict__ b, float* __restrict__ o)
{
    long row = blockIdx.x;
    int t = threadIdx.x;
    float4 v = ((const float4*)(x + row * H))[t];
    float s = v.x + v.y + v.z + v.w;
    float ss = v.x * v.x + v.y * v.y + v.z * v.z + v.w * v.w;
#pragma unroll
    for (int off = 16; off; off >>= 1) {
        s += __shfl_xor_sync(0xffffffffu, s, off);
        ss += __shfl_xor_sync(0xffffffffu, ss, off);
    }
    __shared__ float sm0[4], sm1[4];
    int w = t >> 5;
    if ((t & 31) == 0) { sm0[w] = s; sm1[w] = ss; }
    __syncthreads();
    s = sm0[0] + sm0[1] + sm0[2] + sm0[3];
    ss = sm1[0] + sm1[1] + sm1[2] + sm1[3];
    float mean = s * (1.f / H);
    float var = ss * (1.f / H) - mean * mean;
    float rstd = rsqrtf(var + 1e-5f);
    float4 gg = ((const float4*)g)[t];
    float4 bb4 = ((const float4*)b)[t];
    float4 out;
    out.x = (v.x - mean) * rstd * gg.x + bb4.x;
    out.y = (v.y - mean) * rstd * gg.y + bb4.y;
    out.z = (v.z - mean) * rstd * gg.z + bb4.z;
    out.w = (v.w - mean) * rstd * gg.w + bb4.w;
    ((float4*)(o + row * H))[t] = out;
}

// ---------------- misc kernels ----------------
__global__ void pe_k(float* __restrict__ pe)
{
    int t = blockIdx.x;
    int i = threadIdx.x;
    float div = expf(-(float)(2 * i) * (logf(10000.f) / (float)H));
    float a = (float)t * div;
    pe[t * H + 2 * i] = sinf(a);
    pe[t * H + 2 * i + 1] = cosf(a);
}

__global__ void convT_k(const float* __restrict__ w, float* __restrict__ o)
{
    int idx = blockIdx.x * blockDim.x + threadIdx.x;
    if (idx >= 4 * H * H) return;
    int k = idx / (H * H);
    int d = (idx / H) % H;
    int c = idx % H;
    o[idx] = w[c * H * 4 + d * 4 + k];
}

__global__ void xinit_k(const float* __restrict__ qe, const float* __restrict__ pe,
                        float* __restrict__ x)
{
    long i = blockIdx.x * (long)blockDim.x + threadIdx.x;
    if (i >= (long)BB * TT * H) return;
    int td = (int)(i % (TT * H));
    x[i] = qe[td] + pe[td];
}

__global__ void kin_k(const float* __restrict__ ho, float* __restrict__ out)
{
    int row = blockIdx.x * blockDim.x + threadIdx.x;
    if (row >= BB * TT) return;
    const float* r = ho + (long)row * NOUT;
    float* o = out + (long)row * (3 * NJ);
    float gx[NJ], px[NJ], py[NJ];
    gx[0] = 0.f;
    px[0] = r[100];
    py[0] = r[101];
    o[0] = px[0]; o[1] = py[0]; o[2] = 1.f;
    for (int j = 1; j < NJ; j++) {
        int pa = PAR[j];
        float gg = gx[pa] + r[j];
        gx[j] = gg;
        float s = r[50 + j];
        float sn, cs;
        sincosf(gg, &sn, &cs);
        px[j] = px[pa] + cs * s;
        py[j] = py[pa] + sn * s;
        o[j * 3 + 0] = px[j];
        o[j * 3 + 1] = py[j];
        o[j * 3 + 2] = 1.f;
    }
}

// ---------------- launcher ----------------
static inline dim3 gg128(int M, int N, int bz = 1)
{
    return dim3((N + 127) / 128, (M + 127) / 128, bz);
}

#define Z6 0L, 0L, 0L, 0L, 0L, 0L

#define SMEM_T128 73728

extern "C" void kernel_launch(void* const* d_in, const int* in_sizes, int n_in,
                              void* d_out, int out_size)
{
    const float* memory   = (const float*)d_in[0];
    const float* in_w     = (const float*)d_in[1];
    const float* in_b     = (const float*)d_in[2];
    const float* conv_w   = (const float*)d_in[3];
    const float* conv_b   = (const float*)d_in[4];
    const float* qemb     = (const float*)d_in[5];
    const float* sa_in_w  = (const float*)d_in[6];
    const float* sa_in_b  = (const float*)d_in[7];
    const float* sa_out_w = (const float*)d_in[8];
    const float* sa_out_b = (const float*)d_in[9];
    const float* ca_in_w  = (const float*)d_in[10];
    const float* ca_in_b  = (const float*)d_in[11];
    const float* ca_out_w = (const float*)d_in[12];
    const float* ca_out_b = (const float*)d_in[13];
    const float* ln1_g    = (const float*)d_in[14];
    const float* ln1_b    = (const float*)d_in[15];
    const float* ln2_g    = (const float*)d_in[16];
    const float* ln2_b    = (const float*)d_in[17];
    const float* ln3_g    = (const float*)d_in[18];
    const float* ln3_b    = (const float*)d_in[19];
    const float* ff1_w    = (const float*)d_in[20];
    const float* ff1_b    = (const float*)d_in[21];
    const float* ff2_w    = (const float*)d_in[22];
    const float* ff2_b    = (const float*)d_in[23];
    const float* out_w    = (const float*)d_in[24];
    const float* out_b    = (const float*)d_in[25];

    float *m_, *mem_, *x_, *h_, *qkv_, *att_, *ff_, *ho_, *pe_, *cT_;
    cudaGetSymbolAddress((void**)&m_,   g_m);
    cudaGetSymbolAddress((void**)&mem_, g_mem);
    cudaGetSymbolAddress((void**)&x_,   g_x);
    cudaGetSymbolAddress((void**)&h_,   g_h);
    cudaGetSymbolAddress((void**)&qkv_, g_qkv);
    cudaGetSymbolAddress((void**)&att_, g_att);
    cudaGetSymbolAddress((void**)&ff_,  g_ff);
    cudaGetSymbolAddress((void**)&ho_,  g_head);
    cudaGetSymbolAddress((void**)&pe_,  g_pe);
    cudaGetSymbolAddress((void**)&cT_,  g_convT);

    cudaFuncSetAttribute(gemm3<true,  EPI_BIAS,      128>, cudaFuncAttributeMaxDynamicSharedMemorySize, SMEM_T128);
    cudaFuncSetAttribute(gemm3<true,  EPI_CONV,      128>, cudaFuncAttributeMaxDynamicSharedMemorySize, SMEM_T128);
    cudaFuncSetAttribute(gemm3<true,  EPI_BIAS_RES,  128>, cudaFuncAttributeMaxDynamicSharedMemorySize, SMEM_T128);
    cudaFuncSetAttribute(gemm3<true,  EPI_BIAS_GELU, 128>, cudaFuncAttributeMaxDynamicSharedMemorySize, SMEM_T128);
    cudaFuncSetAttribute(fattn_k, cudaFuncAttributeMaxDynamicSharedMemorySize, FA_SMEM_BYTES);

    pe_k<<<TT, 256>>>(pe_);
    convT_k<<<(4 * H * H + 255) / 256, 256>>>(conv_w, cT_);

    gemm3<true, EPI_BIAS, 128><<<gg128(BB * SS, H), 256, SMEM_T128>>>(
        memory, in_w, in_b, nullptr, m_,
        BB * SS, H, H, H, H, H, Z6, 1, 1.f);

    gemm3<true, EPI_CONV, 128><<<gg128(BB * SS, H, 4), 256, SMEM_T128>>>(
        m_, cT_, conv_b, pe_, mem_,
        BB * SS, H, H, H, H, H,
        0L, 0L, 0L, (long)H * H, 0L, 0L, 4, 1.f);

    xinit_k<<<(BB * TT * H + 255) / 256, 256>>>(qemb, pe_, x_);

    const dim3 fa_grid(TT / 128, BB * NHEAD);

    for (int l = 0; l < NL; l++) {
        // ======== self-attention ========
        ln_k<<<BB * TT, 128>>>(x_, ln1_g + l * H, ln1_b + l * H, h_);
        gemm3<true, EPI_BIAS, 128><<<gg128(BB * TT, 3 * H), 256, SMEM_T128>>>(
            h_, sa_in_w + (long)l * 3 * H * H, sa_in_b + (long)l * 3 * H, nullptr, qkv_,
            BB * TT, 3 * H, H, H, H, 3 * H, Z6, 1, 1.f);
        fattn_k<<<fa_grid, 256, FA_SMEM_BYTES>>>(qkv_, att_);
        gemm3<true, EPI_BIAS_RES, 128><<<gg128(BB * TT, H), 256, SMEM_T128>>>(
            att_, sa_out_w + (long)l * H * H, sa_out_b + (long)l * H, x_, x_,
            BB * TT, H, H, H, H, H, Z6, 1, 1.f);

        // ======== cross-attention ========
        ln_k<<<BB * TT, 128>>>(x_, ln2_g + l * H, ln2_b + l * H, h_);
        gemm3<true, EPI_BIAS, 128><<<gg128(BB * TT, H), 256, SMEM_T128>>>(
            h_, ca_in_w + (long)l * 3 * H * H, ca_in_b + (long)l * 3 * H, nullptr, qkv_,
            BB * TT, H, H, H, H, 3 * H, Z6, 1, 1.f);
        gemm3<true, EPI_BIAS, 128><<<gg128(BB * TT, 2 * H), 256, SMEM_T128>>>(
            mem_, ca_in_w + (long)l * 3 * H * H + (long)H * H,
            ca_in_b + (long)l * 3 * H + H, nullptr, qkv_ + H,
            BB * TT, 2 * H, H, H, H, 3 * H, Z6, 1, 1.f);
        fattn_k<<<fa_grid, 256, FA_SMEM_BYTES>>>(qkv_, att_);
        gemm3<true, EPI_BIAS_RES, 128><<<gg128(BB * TT, H), 256, SMEM_T128>>>(
            att_, ca_out_w + (long)l * H * H, ca_out_b + (long)l * H, x_, x_,
            BB * TT, H, H, H, H, H, Z6, 1, 1.f);

        // ======== FFN ========
        ln_k<<<BB * TT, 128>>>(x_, ln3_g + l * H, ln3_b + l * H, h_);
        gemm3<true, EPI_BIAS_GELU, 128><<<gg128(BB * TT, FF), 256, SMEM_T128>>>(
            h_, ff1_w + (long)l * FF * H, ff1_b + (long)l * FF, nullptr, ff_,
            BB * TT, FF, H, H, H, FF, Z6, 1, 1.f);
        gemm3<true, EPI_BIAS_RES, 128><<<gg128(BB * TT, H), 256, SMEM_T128>>>(
            ff_, ff2_w + (long)l * H * FF, ff2_b + (long)l * H, x_, x_,
            BB * TT, H, FF, FF, FF, H, Z6, 1, 1.f);
    }

    gemm3<true, EPI_BIAS, 128><<<gg128(BB * TT, NOUT), 256, SMEM_T128>>>(
        x_, out_w, out_b, nullptr, ho_,
        BB * TT, NOUT, H, H, H, NOUT, Z6, 1, 1.f);

    kin_k<<<(BB * TT + 255) / 256, 256>>>(ho_, (float*)d_out);
}

// round 6
// speedup vs baseline: 1.2736x; 1.0214x over previous
#include <cuda_runtime.h>
#include <math.h>
#include <stdint.h>

#define H 512
#define BB 32
#define SS 128
#define TT 512
#define NHEAD 8
#define DHD 64
#define NL 4
#define FF 2048
#define NOUT 102
#define NJ 50

// ---------------- scratch ----------------
__device__ float g_m[BB * SS * H];
__device__ float g_mem[BB * TT * H];
__device__ float g_x[BB * TT * H];
__device__ float g_h[BB * TT * H];
__device__ float g_qkv[BB * TT * 3 * H];
__device__ float g_att[BB * TT * H];
__device__ float g_ff[BB * TT * FF];
__device__ float g_head[BB * TT * NOUT];
__device__ float g_pe[TT * H];
__device__ float g_convT[4 * H * H];

__constant__ int PAR[NJ] = {
    -1, 0, 1, 2, 3, 1, 5, 6, 1,
    4, 9, 10, 11,  4, 13, 14, 15,  4, 17, 18, 19,  4, 21, 22, 23,  4, 25, 26, 27,
    7, 29, 30, 31, 7, 33, 34, 35,  7, 37, 38, 39,  7, 41, 42, 43,  7, 45, 46, 47,
    8
};

#define EPI_NONE 0
#define EPI_SCALE 1
#define EPI_BIAS 2
#define EPI_BIAS_RES 3
#define EPI_BIAS_GELU 4
#define EPI_CONV 5

// ---------------- ptx helpers ----------------
__device__ __forceinline__ uint32_t f2tf(float f)
{
    uint32_t u;
    asm("cvt.rna.tf32.f32 %0, %1;" : "=r"(u) : "f"(f));
    return u;
}
__device__ __forceinline__ uint32_t u2tf(uint32_t x)
{
    uint32_t u;
    asm("cvt.rna.tf32.f32 %0, %1;" : "=r"(u) : "f"(__uint_as_float(x)));
    return u;
}
__device__ __forceinline__ void cp16(uint32_t dst, const void* src)
{
    asm volatile("cp.async.cg.shared.global [%0], [%1], 16;\n" :: "r"(dst), "l"(src));
}
__device__ __forceinline__ void cp16z(uint32_t dst, const void* src, bool p)
{
    int sz = p ? 16 : 0;
    asm volatile("cp.async.cg.shared.global [%0], [%1], 16, %2;\n"
                 :: "r"(dst), "l"(src), "r"(sz));
}
__device__ __forceinline__ void cpcommit()
{
    asm volatile("cp.async.commit_group;\n" ::: "memory");
}
template <int W>
__device__ __forceinline__ void cpwait()
{
    asm volatile("cp.async.wait_group %0;\n" :: "n"(W) : "memory");
}
__device__ __forceinline__ void mma8(float* d, const uint32_t* a, const uint32_t* b)
{
    asm volatile(
        "mma.sync.aligned.m16n8k8.row.col.f32.tf32.tf32.f32 "
        "{%0,%1,%2,%3}, {%4,%5,%6,%7}, {%8,%9}, {%0,%1,%2,%3};\n"
        : "+f"(d[0]), "+f"(d[1]), "+f"(d[2]), "+f"(d[3])
        : "r"(a[0]), "r"(a[1]), "r"(a[2]), "r"(a[3]), "r"(b[0]), "r"(b[1]));
}
__device__ __forceinline__ void ldsm4(uint32_t* r, uint32_t addr)
{
    asm volatile("ldmatrix.sync.aligned.m8n8.x4.shared.b16 {%0,%1,%2,%3}, [%4];\n"
                 : "=r"(r[0]), "=r"(r[1]), "=r"(r[2]), "=r"(r[3]) : "r"(addr));
}
__device__ __forceinline__ void ldsm2(uint32_t* r, uint32_t addr)
{
    asm volatile("ldmatrix.sync.aligned.m8n8.x2.shared.b16 {%0,%1}, [%2];\n"
                 : "=r"(r[0]), "=r"(r[1]) : "r"(addr));
}

// ---------------- tf32 tensor-core GEMM (ldmatrix fragments + register cvt) ----------------
// C[r,c] = sum_k A[r,k] * B[c,k]  (TRANSB layouts only; all uses are TRANSB)
template <int EPI, int BN_>
__global__ void __launch_bounds__(256, 2) gemm5(
    const float* __restrict__ A, const float* __restrict__ Bm,
    const float* __restrict__ bias, const float* __restrict__ resid,
    float* __restrict__ C,
    int M, int N, int K, int lda, int ldb, int ldc,
    long sAb, long sAh, long sBb, long sBh, long sCb, long sCh,
    int nh, float scale)
{
    constexpr int BM = 128, BK = 32;
    constexpr int WTM = 64, WTN = BN_ / 4;
    constexpr int MT = WTM / 16;
    constexpr int NT = WTN / 8;
    constexpr int LDA = BK + 4;
    constexpr int LDB = BK + 4;
    constexpr int ACH = BM * BK / 4 / 256;
    constexpr int BCH = BN_ * BK / 4 / 256;

    extern __shared__ float sm[];
    float* sA = sm;
    float* sB = sm + 2 * BM * LDA;
    const uint32_t sAu = (uint32_t)__cvta_generic_to_shared(sA);
    const uint32_t sBu = (uint32_t)__cvta_generic_to_shared(sB);

    const int z = blockIdx.z;
    const int bb = z / nh, hh = z - bb * nh;
    A += (long)bb * sAb + (long)hh * sAh;
    Bm += (long)bb * sBb + (long)hh * sBh;
    const long coff = (long)bb * sCb + (long)hh * sCh;

    const int row0 = blockIdx.y * BM;
    const int col0 = blockIdx.x * BN_;
    const int tid = threadIdx.x;
    const int warp = tid >> 5;
    const int lane = tid & 31;
    const int wm = warp >> 2;
    const int wn = warp & 3;
    const int gid = lane >> 2;
    const int tig = lane & 3;
    const int l15 = lane & 15;
    const int l7 = lane & 7;
    const int acol = (lane >> 4) << 2;          // 0 or 4
    const int bcol = ((lane >> 3) & 1) << 2;    // 0 or 4

    float acc[MT][NT][4];
#pragma unroll
    for (int i = 0; i < MT; i++)
#pragma unroll
        for (int j = 0; j < NT; j++)
#pragma unroll
            for (int q = 0; q < 4; q++) acc[i][j][q] = 0.f;

    auto cpA = [&](int k0, int st) {
#pragma unroll
        for (int l = 0; l < ACH; l++) {
            int idx = l * 256 + tid;
            int r = idx >> 3;
            int cq = (idx & 7) * 4;
            cp16(sAu + (uint32_t)(st * BM * LDA + r * LDA + cq) * 4,
                 A + (long)(row0 + r) * lda + k0 + cq);
        }
    };
    auto cpB = [&](int k0, int st) {
#pragma unroll
        for (int l = 0; l < BCH; l++) {
            int idx = l * 256 + tid;
            int n = idx >> 3;
            int cq = (idx & 7) * 4;
            cp16z(sBu + (uint32_t)(st * BN_ * LDB + n * LDB + cq) * 4,
                  Bm + (long)(col0 + n) * ldb + k0 + cq,
                  (col0 + n) < N);
        }
    };

    auto compute = [&](int st) {
        const uint32_t pAu = sAu + (uint32_t)(st * BM * LDA) * 4;
        const uint32_t pBu = sBu + (uint32_t)(st * BN_ * LDB) * 4;
#pragma unroll
        for (int ks = 0; ks < 4; ks++) {
            const int k = ks * 8;
            uint32_t af[MT][4], bf[NT][2];
#pragma unroll
            for (int mi = 0; mi < MT; mi++) {
                int r0 = wm * WTM + mi * 16 + l15;
                ldsm4(af[mi], pAu + (uint32_t)(r0 * LDA + k + acol) * 4);
                af[mi][0] = u2tf(af[mi][0]);
                af[mi][1] = u2tf(af[mi][1]);
                af[mi][2] = u2tf(af[mi][2]);
                af[mi][3] = u2tf(af[mi][3]);
            }
#pragma unroll
            for (int ni = 0; ni < NT; ni++) {
                int n0 = wn * WTN + ni * 8 + l7;
                ldsm2(bf[ni], pBu + (uint32_t)(n0 * LDB + k + bcol) * 4);
                bf[ni][0] = u2tf(bf[ni][0]);
                bf[ni][1] = u2tf(bf[ni][1]);
            }
#pragma unroll
            for (int mi = 0; mi < MT; mi++)
#pragma unroll
                for (int ni = 0; ni < NT; ni++)
                    mma8(acc[mi][ni], af[mi], bf[ni]);
        }
    };

    const int nt = K / BK;
    cpA(0, 0); cpB(0, 0); cpcommit();
    if (nt > 1) { cpA(BK, 1); cpB(BK, 1); cpcommit(); }

    for (int t = 0; t < nt; t++) {
        if (t < nt - 1) cpwait<1>(); else cpwait<0>();
        __syncthreads();
        compute(t & 1);
        __syncthreads();
        if (t + 2 < nt) { cpA((t + 2) * BK, t & 1); cpB((t + 2) * BK, t & 1); cpcommit(); }
    }

    auto emit = [&](int r, int c, float v) {
        if (EPI == EPI_SCALE) v *= scale;
        if (EPI == EPI_BIAS || EPI == EPI_BIAS_RES || EPI == EPI_BIAS_GELU || EPI == EPI_CONV)
            v += bias[c];
        if (EPI == EPI_BIAS_GELU)
            v = 0.5f * v * (1.f + erff(v * 0.70710678118654752f));
        if (EPI == EPI_CONV) {
            int b_ = r >> 7;
            int s_ = r & 127;
            int t_ = s_ * 4 + hh;
            C[((long)b_ * TT + t_) * ldc + c] = v + resid[t_ * H + c];
        } else {
            long idx = coff + (long)r * ldc + c;
            if (EPI == EPI_BIAS_RES) v += resid[idx];
            C[idx] = v;
        }
    };

#pragma unroll
    for (int mi = 0; mi < MT; mi++) {
        int r0 = row0 + wm * WTM + mi * 16 + gid;
#pragma unroll
        for (int ni = 0; ni < NT; ni++) {
            int c0 = col0 + wn * WTN + ni * 8 + tig * 2;
            if (c0 < N)     emit(r0,     c0,     acc[mi][ni][0]);
            if (c0 + 1 < N) emit(r0,     c0 + 1, acc[mi][ni][1]);
            if (c0 < N)     emit(r0 + 8, c0,     acc[mi][ni][2]);
            if (c0 + 1 < N) emit(r0 + 8, c0 + 1, acc[mi][ni][3]);
        }
    }
}

// ---------------- fused flash attention (unchanged from round 5) ----------------
#define FA_SQ 0
#define FA_SK 8704
#define FA_SV 17408
#define FA_SP 26112
#define FA_RED 43008
#define FA_M 43520
#define FA_L 43648
#define FA_AL 43776
#define FA_SMEM_FLOATS 43904
#define FA_SMEM_BYTES (FA_SMEM_FLOATS * 4)

__global__ void __launch_bounds__(256, 1) fattn_k(
    const float* __restrict__ qkv, float* __restrict__ att)
{
    extern __shared__ float sm[];
    float* sQ = sm + FA_SQ;
    float* sK = sm + FA_SK;
    float* sV = sm + FA_SV;
    float* sP = sm + FA_SP;
    float* sRed = sm + FA_RED;
    float* sM = sm + FA_M;
    float* sL = sm + FA_L;
    float* sAl = sm + FA_AL;
    const uint32_t smu = (uint32_t)__cvta_generic_to_shared(sm);
    const uint32_t* uQ = (const uint32_t*)sQ;
    const uint32_t* uK = (const uint32_t*)sK;
    const uint32_t* uV = (const uint32_t*)sV;
    const uint32_t* uP = (const uint32_t*)sP;

    const int z = blockIdx.y;
    const int bb = z >> 3, hh = z & 7;
    const int q0 = blockIdx.x * 128;
    const long base = (long)bb * TT * 3 * H + (long)hh * DHD;

    const int tid = threadIdx.x;
    const int warp = tid >> 5, lane = tid & 31;
    const int wm = warp >> 2, wn = warp & 3;
    const int gid = lane >> 2, tig = lane & 3;

#pragma unroll
    for (int l = 0; l < 8; l++) {
        int idx = l * 256 + tid;
        int r = idx >> 4, c4 = (idx & 15) * 4;
        cp16(smu + (uint32_t)(FA_SQ + r * 68 + c4) * 4,
             qkv + base + (long)(q0 + r) * (3 * H) + c4);
    }
    cpcommit();
    cpwait<0>();
    __syncthreads();
#pragma unroll
    for (int l = 0; l < 8; l++) {
        int idx = l * 256 + tid;
        int r = idx >> 4, c4 = (idx & 15) * 4;
        float4* p = (float4*)&sQ[r * 68 + c4];
        float4 v = *p;
        v.x = __uint_as_float(f2tf(v.x * 0.125f));
        v.y = __uint_as_float(f2tf(v.y * 0.125f));
        v.z = __uint_as_float(f2tf(v.z * 0.125f));
        v.w = __uint_as_float(f2tf(v.w * 0.125f));
        *p = v;
    }
    if (tid < 128) { sM[tid] = -1e30f; sL[tid] = 0.f; }

    float oacc[4][2][4];
#pragma unroll
    for (int mi = 0; mi < 4; mi++)
#pragma unroll
        for (int ni = 0; ni < 2; ni++)
#pragma unroll
            for (int q = 0; q < 4; q++) oacc[mi][ni][q] = 0.f;

    for (int j = 0; j < 4; j++) {
        __syncthreads();
#pragma unroll
        for (int l = 0; l < 8; l++) {
            int idx = l * 256 + tid;
            int r = idx >> 4, c4 = (idx & 15) * 4;
            long row = (long)(j * 128 + r) * (3 * H);
            cp16(smu + (uint32_t)(FA_SK + r * 68 + c4) * 4, qkv + base + H + row + c4);
            cp16(smu + (uint32_t)(FA_SV + r * 68 + c4) * 4, qkv + base + 2 * H + row + c4);
        }
        cpcommit();
        cpwait<0>();
        __syncthreads();
#pragma unroll
        for (int l = 0; l < 8; l++) {
            int idx = l * 256 + tid;
            int r = idx >> 4, c4 = (idx & 15) * 4;
            float4* pk = (float4*)&sK[r * 68 + c4];
            float4 vk = *pk;
            vk.x = __uint_as_float(f2tf(vk.x));
            vk.y = __uint_as_float(f2tf(vk.y));
            vk.z = __uint_as_float(f2tf(vk.z));
            vk.w = __uint_as_float(f2tf(vk.w));
            *pk = vk;
            float4* pv = (float4*)&sV[r * 68 + c4];
            float4 vv = *pv;
            vv.x = __uint_as_float(f2tf(vv.x));
            vv.y = __uint_as_float(f2tf(vv.y));
            vv.z = __uint_as_float(f2tf(vv.z));
            vv.w = __uint_as_float(f2tf(vv.w));
            *pv = vv;
        }
        __syncthreads();

        float sacc[4][4][4];
#pragma unroll
        for (int mi = 0; mi < 4; mi++)
#pragma unroll
            for (int ni = 0; ni < 4; ni++)
#pragma unroll
                for (int q = 0; q < 4; q++) sacc[mi][ni][q] = 0.f;
#pragma unroll
        for (int ks = 0; ks < 8; ks++) {
            const int k = ks * 8;
            uint32_t af[4][4], bf[4][2];
#pragma unroll
            for (int mi = 0; mi < 4; mi++) {
                int r0 = wm * 64 + mi * 16 + gid;
                af[mi][0] = uQ[r0 * 68 + k + tig];
                af[mi][1] = uQ[(r0 + 8) * 68 + k + tig];
                af[mi][2] = uQ[r0 * 68 + k + tig + 4];
                af[mi][3] = uQ[(r0 + 8) * 68 + k + tig + 4];
            }
#pragma unroll
            for (int ni = 0; ni < 4; ni++) {
                int n0 = wn * 32 + ni * 8 + gid;
                bf[ni][0] = uK[n0 * 68 + k + tig];
                bf[ni][1] = uK[n0 * 68 + k + tig + 4];
            }
#pragma unroll
            for (int mi = 0; mi < 4; mi++)
#pragma unroll
                for (int ni = 0; ni < 4; ni++)
                    mma8(sacc[mi][ni], af[mi], bf[ni]);
        }

#pragma unroll
        for (int mi = 0; mi < 4; mi++) {
            float r0m = -1e30f, r1m = -1e30f;
#pragma unroll
            for (int ni = 0; ni < 4; ni++) {
                r0m = fmaxf(r0m, fmaxf(sacc[mi][ni][0], sacc[mi][ni][1]));
                r1m = fmaxf(r1m, fmaxf(sacc[mi][ni][2], sacc[mi][ni][3]));
            }
            r0m = fmaxf(r0m, __shfl_xor_sync(0xffffffffu, r0m, 1));
            r0m = fmaxf(r0m, __shfl_xor_sync(0xffffffffu, r0m, 2));
            r1m = fmaxf(r1m, __shfl_xor_sync(0xffffffffu, r1m, 1));
            r1m = fmaxf(r1m, __shfl_xor_sync(0xffffffffu, r1m, 2));
            if (tig == 0) {
                int r0 = wm * 64 + mi * 16 + gid;
                sRed[wn * 128 + r0] = r0m;
                sRed[wn * 128 + r0 + 8] = r1m;
            }
        }
        __syncthreads();
        if (tid < 128) {
            float mt = fmaxf(fmaxf(sRed[tid], sRed[128 + tid]),
                             fmaxf(sRed[256 + tid], sRed[384 + tid]));
            float mo = sM[tid];
            float mn = fmaxf(mo, mt);
            sAl[tid] = __expf(mo - mn);
            sM[tid] = mn;
        }
        __syncthreads();

#pragma unroll
        for (int mi = 0; mi < 4; mi++) {
            int r0 = wm * 64 + mi * 16 + gid;
            float m0 = sM[r0], m1 = sM[r0 + 8];
            float rs0 = 0.f, rs1 = 0.f;
#pragma unroll
            for (int ni = 0; ni < 4; ni++) {
                int c0 = wn * 32 + ni * 8 + tig * 2;
                float p00 = __expf(sacc[mi][ni][0] - m0);
                float p01 = __expf(sacc[mi][ni][1] - m0);
                float p10 = __expf(sacc[mi][ni][2] - m1);
                float p11 = __expf(sacc[mi][ni][3] - m1);
                rs0 += p00 + p01;
                rs1 += p10 + p11;
                *(float2*)&sP[r0 * 132 + c0] =
                    make_float2(__uint_as_float(f2tf(p00)), __uint_as_float(f2tf(p01)));
                *(float2*)&sP[(r0 + 8) * 132 + c0] =
                    make_float2(__uint_as_float(f2tf(p10)), __uint_as_float(f2tf(p11)));
            }
            rs0 += __shfl_xor_sync(0xffffffffu, rs0, 1);
            rs0 += __shfl_xor_sync(0xffffffffu, rs0, 2);
            rs1 += __shfl_xor_sync(0xffffffffu, rs1, 1);
            rs1 += __shfl_xor_sync(0xffffffffu, rs1, 2);
            if (tig == 0) {
                sRed[wn * 128 + r0] = rs0;
                sRed[wn * 128 + r0 + 8] = rs1;
            }
        }
        __syncthreads();
        if (tid < 128) {
            sL[tid] = sL[tid] * sAl[tid] +
                      (sRed[tid] + sRed[128 + tid]) + (sRed[256 + tid] + sRed[384 + tid]);
        }

#pragma unroll
        for (int mi = 0; mi < 4; mi++) {
            int r0 = wm * 64 + mi * 16 + gid;
            float a0 = sAl[r0], a1 = sAl[r0 + 8];
#pragma unroll
            for (int ni = 0; ni < 2; ni++) {
                oacc[mi][ni][0] *= a0;
                oacc[mi][ni][1] *= a0;
                oacc[mi][ni][2] *= a1;
                oacc[mi][ni][3] *= a1;
            }
        }

#pragma unroll
        for (int ks = 0; ks < 16; ks++) {
            const int k = ks * 8;
            uint32_t af[4][4], bf[2][2];
#pragma unroll
            for (int mi = 0; mi < 4; mi++) {
                int r0 = wm * 64 + mi * 16 + gid;
                af[mi][0] = uP[r0 * 132 + k + tig];
                af[mi][1] = uP[(r0 + 8) * 132 + k + tig];
                af[mi][2] = uP[r0 * 132 + k + tig + 4];
                af[mi][3] = uP[(r0 + 8) * 132 + k + tig + 4];
            }
#pragma unroll
            for (int ni = 0; ni < 2; ni++) {
                int n0 = wn * 16 + ni * 8 + gid;
                bf[ni][0] = uV[(k + tig) * 68 + n0];
                bf[ni][1] = uV[(k + tig + 4) * 68 + n0];
            }
#pragma unroll
            for (int mi = 0; mi < 4; mi++)
#pragma unroll
                for (int ni = 0; ni < 2; ni++)
                    mma8(oacc[mi][ni], af[mi], bf[ni]);
        }
    }
    __syncthreads();

#pragma unroll
    for (int mi = 0; mi < 4; mi++) {
        int r0 = wm * 64 + mi * 16 + gid;
        float i0 = 1.f / sL[r0], i1 = 1.f / sL[r0 + 8];
        long o0 = ((long)bb * TT + q0 + r0) * H + hh * DHD;
        long o1 = ((long)bb * TT + q0 + r0 + 8) * H + hh * DHD;
#pragma unroll
        for (int ni = 0; ni < 2; ni++) {
            int c0 = wn * 16 + ni * 8 + tig * 2;
            *(float2*)&att[o0 + c0] = make_float2(oacc[mi][ni][0] * i0, oacc[mi][ni][1] * i0);
            *(float2*)&att[o1 + c0] = make_float2(oacc[mi][ni][2] * i1, oacc[mi][ni][3] * i1);
        }
    }
}

// ---------------- LayerNorm ----------------
__global__ void ln_k(const float* __restrict__ x, const float* __restrict__ g,
                     const float* __restrict__ b, float* __restrict__ o)
{
    long row = blockIdx.x;
    int t = threadIdx.x;
    float4 v = ((const float4*)(x + row * H))[t];
    float s = v.x + v.y + v.z + v.w;
    float ss = v.x * v.x + v.y * v.y + v.z * v.z + v.w * v.w;
#pragma unroll
    for (int off = 16; off; off >>= 1) {
        s += __shfl_xor_sync(0xffffffffu, s, off);
        ss += __shfl_xor_sync(0xffffffffu, ss, off);
    }
    __shared__ float sm0[4], sm1[4];
    int w = t >> 5;
    if ((t & 31) == 0) { sm0[w] = s; sm1[w] = ss; }
    __syncthreads();
    s = sm0[0] + sm0[1] + sm0[2] + sm0[3];
    ss = sm1[0] + sm1[1] + sm1[2] + sm1[3];
    float mean = s * (1.f / H);
    float var = ss * (1.f / H) - mean * mean;
    float rstd = rsqrtf(var + 1e-5f);
    float4 gg = ((const float4*)g)[t];
    float4 bb4 = ((const float4*)b)[t];
    float4 out;
    out.x = (v.x - mean) * rstd * gg.x + bb4.x;
    out.y = (v.y - mean) * rstd * gg.y + bb4.y;
    out.z = (v.z - mean) * rstd * gg.z + bb4.z;
    out.w = (v.w - mean) * rstd * gg.w + bb4.w;
    ((float4*)(o + row * H))[t] = out;
}

// ---------------- misc kernels ----------------
__global__ void pe_k(float* __restrict__ pe)
{
    int t = blockIdx.x;
    int i = threadIdx.x;
    float div = expf(-(float)(2 * i) * (logf(10000.f) / (float)H));
    float a = (float)t * div;
    pe[t * H + 2 * i] = sinf(a);
    pe[t * H + 2 * i + 1] = cosf(a);
}

__global__ void convT_k(const float* __restrict__ w, float* __restrict__ o)
{
    int idx = blockIdx.x * blockDim.x + threadIdx.x;
    if (idx >= 4 * H * H) return;
    int k = idx / (H * H);
    int d = (idx / H) % H;
    int c = idx % H;
    o[idx] = w[c * H * 4 + d * 4 + k];
}

__global__ void xinit_k(const float* __restrict__ qe, const float* __restrict__ pe,
                        float* __restrict__ x)
{
    long i = blockIdx.x * (long)blockDim.x + threadIdx.x;
    if (i >= (long)BB * TT * H) return;
    int td = (int)(i % (TT * H));
    x[i] = qe[td] + pe[td];
}

__global__ void kin_k(const float* __restrict__ ho, float* __restrict__ out)
{
    int row = blockIdx.x * blockDim.x + threadIdx.x;
    if (row >= BB * TT) return;
    const float* r = ho + (long)row * NOUT;
    float* o = out + (long)row * (3 * NJ);
    float gx[NJ], px[NJ], py[NJ];
    gx[0] = 0.f;
    px[0] = r[100];
    py[0] = r[101];
    o[0] = px[0]; o[1] = py[0]; o[2] = 1.f;
    for (int j = 1; j < NJ; j++) {
        int pa = PAR[j];
        float gg = gx[pa] + r[j];
        gx[j] = gg;
        float s = r[50 + j];
        float sn, cs;
        sincosf(gg, &sn, &cs);
        px[j] = px[pa] + cs * s;
        py[j] = py[pa] + sn * s;
        o[j * 3 + 0] = px[j];
        o[j * 3 + 1] = py[j];
        o[j * 3 + 2] = 1.f;
    }
}

// ---------------- launcher ----------------
static inline dim3 gg128(int M, int N, int bz = 1)
{
    return dim3((N + 127) / 128, (M + 127) / 128, bz);
}

#define Z6 0L, 0L, 0L, 0L, 0L, 0L

#define SMEM_T128 73728

extern "C" void kernel_launch(void* const* d_in, const int* in_sizes, int n_in,
                              void* d_out, int out_size)
{
    const float* memory   = (const float*)d_in[0];
    const float* in_w     = (const float*)d_in[1];
    const float* in_b     = (const float*)d_in[2];
    const float* conv_w   = (const float*)d_in[3];
    const float* conv_b   = (const float*)d_in[4];
    const float* qemb     = (const float*)d_in[5];
    const float* sa_in_w  = (const float*)d_in[6];
    const float* sa_in_b  = (const float*)d_in[7];
    const float* sa_out_w = (const float*)d_in[8];
    const float* sa_out_b = (const float*)d_in[9];
    const float* ca_in_w  = (const float*)d_in[10];
    const float* ca_in_b  = (const float*)d_in[11];
    const float* ca_out_w = (const float*)d_in[12];
    const float* ca_out_b = (const float*)d_in[13];
    const float* ln1_g    = (const float*)d_in[14];
    const float* ln1_b    = (const float*)d_in[15];
    const float* ln2_g    = (const float*)d_in[16];
    const float* ln2_b    = (const float*)d_in[17];
    const float* ln3_g    = (const float*)d_in[18];
    const float* ln3_b    = (const float*)d_in[19];
    const float* ff1_w    = (const float*)d_in[20];
    const float* ff1_b    = (const float*)d_in[21];
    const float* ff2_w    = (const float*)d_in[22];
    const float* ff2_b    = (const float*)d_in[23];
    const float* out_w    = (const float*)d_in[24];
    const float* out_b    = (const float*)d_in[25];

    float *m_, *mem_, *x_, *h_, *qkv_, *att_, *ff_, *ho_, *pe_, *cT_;
    cudaGetSymbolAddress((void**)&m_,   g_m);
    cudaGetSymbolAddress((void**)&mem_, g_mem);
    cudaGetSymbolAddress((void**)&x_,   g_x);
    cudaGetSymbolAddress((void**)&h_,   g_h);
    cudaGetSymbolAddress((void**)&qkv_, g_qkv);
    cudaGetSymbolAddress((void**)&att_, g_att);
    cudaGetSymbolAddress((void**)&ff_,  g_ff);
    cudaGetSymbolAddress((void**)&ho_,  g_head);
    cudaGetSymbolAddress((void**)&pe_,  g_pe);
    cudaGetSymbolAddress((void**)&cT_,  g_convT);

    cudaFuncSetAttribute(gemm5<EPI_BIAS,      128>, cudaFuncAttributeMaxDynamicSharedMemorySize, SMEM_T128);
    cudaFuncSetAttribute(gemm5<EPI_CONV,      128>, cudaFuncAttributeMaxDynamicSharedMemorySize, SMEM_T128);
    cudaFuncSetAttribute(gemm5<EPI_BIAS_RES,  128>, cudaFuncAttributeMaxDynamicSharedMemorySize, SMEM_T128);
    cudaFuncSetAttribute(gemm5<EPI_BIAS_GELU, 128>, cudaFuncAttributeMaxDynamicSharedMemorySize, SMEM_T128);
    cudaFuncSetAttribute(fattn_k, cudaFuncAttributeMaxDynamicSharedMemorySize, FA_SMEM_BYTES);

    pe_k<<<TT, 256>>>(pe_);
    convT_k<<<(4 * H * H + 255) / 256, 256>>>(conv_w, cT_);

    gemm5<EPI_BIAS, 128><<<gg128(BB * SS, H), 256, SMEM_T128>>>(
        memory, in_w, in_b, nullptr, m_,
        BB * SS, H, H, H, H, H, Z6, 1, 1.f);

    gemm5<EPI_CONV, 128><<<gg128(BB * SS, H, 4), 256, SMEM_T128>>>(
        m_, cT_, conv_b, pe_, mem_,
        BB * SS, H, H, H, H, H,
        0L, 0L, 0L, (long)H * H, 0L, 0L, 4, 1.f);

    xinit_k<<<(BB * TT * H + 255) / 256, 256>>>(qemb, pe_, x_);

    const dim3 fa_grid(TT / 128, BB * NHEAD);

    for (int l = 0; l < NL; l++) {
        // ======== self-attention ========
        ln_k<<<BB * TT, 128>>>(x_, ln1_g + l * H, ln1_b + l * H, h_);
        gemm5<EPI_BIAS, 128><<<gg128(BB * TT, 3 * H), 256, SMEM_T128>>>(
            h_, sa_in_w + (long)l * 3 * H * H, sa_in_b + (long)l * 3 * H, nullptr, qkv_,
            BB * TT, 3 * H, H, H, H, 3 * H, Z6, 1, 1.f);
        fattn_k<<<fa_grid, 256, FA_SMEM_BYTES>>>(qkv_, att_);
        gemm5<EPI_BIAS_RES, 128><<<gg128(BB * TT, H), 256, SMEM_T128>>>(
            att_, sa_out_w + (long)l * H * H, sa_out_b + (long)l * H, x_, x_,
            BB * TT, H, H, H, H, H, Z6, 1, 1.f);

        // ======== cross-attention ========
        ln_k<<<BB * TT, 128>>>(x_, ln2_g + l * H, ln2_b + l * H, h_);
        gemm5<EPI_BIAS, 128><<<gg128(BB * TT, H), 256, SMEM_T128>>>(
            h_, ca_in_w + (long)l * 3 * H * H, ca_in_b + (long)l * 3 * H, nullptr, qkv_,
            BB * TT, H, H, H, H, 3 * H, Z6, 1, 1.f);
        gemm5<EPI_BIAS, 128><<<gg128(BB * TT, 2 * H), 256, SMEM_T128>>>(
            mem_, ca_in_w + (long)l * 3 * H * H + (long)H * H,
            ca_in_b + (long)l * 3 * H + H, nullptr, qkv_ + H,
            BB * TT, 2 * H, H, H, H, 3 * H, Z6, 1, 1.f);
        fattn_k<<<fa_grid, 256, FA_SMEM_BYTES>>>(qkv_, att_);
        gemm5<EPI_BIAS_RES, 128><<<gg128(BB * TT, H), 256, SMEM_T128>>>(
            att_, ca_out_w + (long)l * H * H, ca_out_b + (long)l * H, x_, x_,
            BB * TT, H, H, H, H, H, Z6, 1, 1.f);

        // ======== FFN ========
        ln_k<<<BB * TT, 128>>>(x_, ln3_g + l * H, ln3_b + l * H, h_);
        gemm5<EPI_BIAS_GELU, 128><<<gg128(BB * TT, FF), 256, SMEM_T128>>>(
            h_, ff1_w + (long)l * FF * H, ff1_b + (long)l * FF, nullptr, ff_,
            BB * TT, FF, H, H, H, FF, Z6, 1, 1.f);
        gemm5<EPI_BIAS_RES, 128><<<gg128(BB * TT, H), 256, SMEM_T128>>>(
            ff_, ff2_w + (long)l * H * FF, ff2_b + (long)l * H, x_, x_,
            BB * TT, H, FF, FF, FF, H, Z6, 1, 1.f);
    }

    gemm5<EPI_BIAS, 128><<<gg128(BB * TT, NOUT), 256, SMEM_T128>>>(
        x_, out_w, out_b, nullptr, ho_,
        BB * TT, NOUT, H, H, H, NOUT, Z6, 1, 1.f);

    kin_k<<<(BB * TT + 255) / 256, 256>>>(ho_, (float*)d_out);
}

// round 7
// speedup vs baseline: 1.3490x; 1.0592x over previous
#include <cuda_runtime.h>
#include <math.h>
#include <stdint.h>

#define H 512
#define BB 32
#define SS 128
#define TT 512
#define NHEAD 8
#define DHD 64
#define NL 4
#define FF 2048
#define NOUT 102
#define NJ 50

// ---------------- scratch ----------------
__device__ float g_m[BB * SS * H];
__device__ float g_mem[BB * TT * H];
__device__ float g_x[BB * TT * H];
__device__ float g_h[BB * TT * H];
__device__ float g_qkv[BB * TT * 3 * H];
__device__ float g_att[BB * TT * H];
__device__ float g_ff[BB * TT * FF];
__device__ float g_head[BB * TT * NOUT];
__device__ float g_pe[TT * H];
__device__ float g_convT[4 * H * H];
__device__ float g_wtf[16777216];   // tf32-rounded weights, 64 MB

// offsets into g_wtf (floats)
#define WOFF_SAIN  0
#define WOFF_SAOUT 3145728
#define WOFF_CAIN  4194304
#define WOFF_CAOUT 7340032
#define WOFF_FF1   8388608
#define WOFF_FF2   12582912

__constant__ int PAR[NJ] = {
    -1, 0, 1, 2, 3, 1, 5, 6, 1,
    4, 9, 10, 11,  4, 13, 14, 15,  4, 17, 18, 19,  4, 21, 22, 23,  4, 25, 26, 27,
    7, 29, 30, 31, 7, 33, 34, 35,  7, 37, 38, 39,  7, 41, 42, 43,  7, 45, 46, 47,
    8
};

#define EPI_NONE 0
#define EPI_SCALE 1
#define EPI_BIAS 2
#define EPI_BIAS_RES 3
#define EPI_BIAS_GELU 4
#define EPI_CONV 5

// ---------------- ptx helpers ----------------
__device__ __forceinline__ uint32_t f2tf(float f)
{
    uint32_t u;
    asm("cvt.rna.tf32.f32 %0, %1;" : "=r"(u) : "f"(f));
    return u;
}
__device__ __forceinline__ uint32_t u2tf(uint32_t x)
{
    uint32_t u;
    asm("cvt.rna.tf32.f32 %0, %1;" : "=r"(u) : "f"(__uint_as_float(x)));
    return u;
}
__device__ __forceinline__ float rndf(float f) { return __uint_as_float(f2tf(f)); }

__device__ __forceinline__ void cp16(uint32_t dst, const void* src)
{
    asm volatile("cp.async.cg.shared.global [%0], [%1], 16;\n" :: "r"(dst), "l"(src));
}
__device__ __forceinline__ void cp16z(uint32_t dst, const void* src, bool p)
{
    int sz = p ? 16 : 0;
    asm volatile("cp.async.cg.shared.global [%0], [%1], 16, %2;\n"
                 :: "r"(dst), "l"(src), "r"(sz));
}
__device__ __forceinline__ void cpcommit()
{
    asm volatile("cp.async.commit_group;\n" ::: "memory");
}
template <int W>
__device__ __forceinline__ void cpwait()
{
    asm volatile("cp.async.wait_group %0;\n" :: "n"(W) : "memory");
}
__device__ __forceinline__ void mma8(float* d, const uint32_t* a, const uint32_t* b)
{
    asm volatile(
        "mma.sync.aligned.m16n8k8.row.col.f32.tf32.tf32.f32 "
        "{%0,%1,%2,%3}, {%4,%5,%6,%7}, {%8,%9}, {%0,%1,%2,%3};\n"
        : "+f"(d[0]), "+f"(d[1]), "+f"(d[2]), "+f"(d[3])
        : "r"(a[0]), "r"(a[1]), "r"(a[2]), "r"(a[3]), "r"(b[0]), "r"(b[1]));
}
__device__ __forceinline__ void ldsm4(uint32_t* r, uint32_t addr)
{
    asm volatile("ldmatrix.sync.aligned.m8n8.x4.shared.b16 {%0,%1,%2,%3}, [%4];\n"
                 : "=r"(r[0]), "=r"(r[1]), "=r"(r[2]), "=r"(r[3]) : "r"(addr));
}
__device__ __forceinline__ void ldsm2(uint32_t* r, uint32_t addr)
{
    asm volatile("ldmatrix.sync.aligned.m8n8.x2.shared.b16 {%0,%1}, [%2];\n"
                 : "=r"(r[0]), "=r"(r[1]) : "r"(addr));
}

// ---------------- tf32 tensor-core GEMM ----------------
// C[r,c] = sum_k A[r,k] * B[c,k].  CVTIN: round operands in-loop (raw fp32 inputs).
// RND: write tf32-rounded outputs (for buffers feeding later GEMM A-operands).
template <int EPI, bool CVTIN, bool RND>
__global__ void __launch_bounds__(256, 2) gemm6(
    const float* __restrict__ A, const float* __restrict__ Bm,
    const float* __restrict__ bias, const float* __restrict__ resid,
    float* __restrict__ C,
    int M, int N, int K, int lda, int ldb, int ldc,
    long sAb, long sAh, long sBb, long sBh, long sCb, long sCh,
    int nh, float scale)
{
    constexpr int BM = 128, BN_ = 128, BK = 32;
    constexpr int WTM = 64, WTN = 32;
    constexpr int MT = 4, NT = 4;
    constexpr int LDA = BK + 4;
    constexpr int LDB = BK + 4;
    constexpr int ACH = BM * BK / 4 / 256;
    constexpr int BCH = BN_ * BK / 4 / 256;

    extern __shared__ float sm[];
    float* sA = sm;
    float* sB = sm + 2 * BM * LDA;
    const uint32_t sAu = (uint32_t)__cvta_generic_to_shared(sA);
    const uint32_t sBu = (uint32_t)__cvta_generic_to_shared(sB);

    const int z = blockIdx.z;
    const int bb = z / nh, hh = z - bb * nh;
    A += (long)bb * sAb + (long)hh * sAh;
    Bm += (long)bb * sBb + (long)hh * sBh;
    const long coff = (long)bb * sCb + (long)hh * sCh;

    const int row0 = blockIdx.y * BM;
    const int col0 = blockIdx.x * BN_;
    const int tid = threadIdx.x;
    const int warp = tid >> 5;
    const int lane = tid & 31;
    const int wm = warp >> 2;
    const int wn = warp & 3;
    const int gid = lane >> 2;
    const int tig = lane & 3;
    const int l15 = lane & 15;
    const int l7 = lane & 7;
    const int acol = (lane >> 4) << 2;
    const int bcol = ((lane >> 3) & 1) << 2;

    float acc[MT][NT][4];
#pragma unroll
    for (int i = 0; i < MT; i++)
#pragma unroll
        for (int j = 0; j < NT; j++)
#pragma unroll
            for (int q = 0; q < 4; q++) acc[i][j][q] = 0.f;

    auto cpA = [&](int k0, int st) {
#pragma unroll
        for (int l = 0; l < ACH; l++) {
            int idx = l * 256 + tid;
            int r = idx >> 3;
            int cq = (idx & 7) * 4;
            cp16(sAu + (uint32_t)(st * BM * LDA + r * LDA + cq) * 4,
                 A + (long)(row0 + r) * lda + k0 + cq);
        }
    };
    auto cpB = [&](int k0, int st) {
#pragma unroll
        for (int l = 0; l < BCH; l++) {
            int idx = l * 256 + tid;
            int n = idx >> 3;
            int cq = (idx & 7) * 4;
            cp16z(sBu + (uint32_t)(st * BN_ * LDB + n * LDB + cq) * 4,
                  Bm + (long)(col0 + n) * ldb + k0 + cq,
                  (col0 + n) < N);
        }
    };

    auto compute = [&](int st) {
        const uint32_t pAu = sAu + (uint32_t)(st * BM * LDA) * 4;
        const uint32_t pBu = sBu + (uint32_t)(st * BN_ * LDB) * 4;
#pragma unroll
        for (int ks = 0; ks < 4; ks++) {
            const int k = ks * 8;
            uint32_t af[MT][4], bf[NT][2];
#pragma unroll
            for (int mi = 0; mi < MT; mi++) {
                int r0 = wm * WTM + mi * 16 + l15;
                ldsm4(af[mi], pAu + (uint32_t)(r0 * LDA + k + acol) * 4);
                if (CVTIN) {
                    af[mi][0] = u2tf(af[mi][0]);
                    af[mi][1] = u2tf(af[mi][1]);
                    af[mi][2] = u2tf(af[mi][2]);
                    af[mi][3] = u2tf(af[mi][3]);
                }
            }
#pragma unroll
            for (int ni = 0; ni < NT; ni++) {
                int n0 = wn * WTN + ni * 8 + l7;
                ldsm2(bf[ni], pBu + (uint32_t)(n0 * LDB + k + bcol) * 4);
                if (CVTIN) {
                    bf[ni][0] = u2tf(bf[ni][0]);
                    bf[ni][1] = u2tf(bf[ni][1]);
                }
            }
#pragma unroll
            for (int mi = 0; mi < MT; mi++)
#pragma unroll
                for (int ni = 0; ni < NT; ni++)
                    mma8(acc[mi][ni], af[mi], bf[ni]);
        }
    };

    const int nt = K / BK;
    cpA(0, 0); cpB(0, 0); cpcommit();
    if (nt > 1) { cpA(BK, 1); cpB(BK, 1); cpcommit(); }

    for (int t = 0; t < nt; t++) {
        if (t < nt - 1) cpwait<1>(); else cpwait<0>();
        __syncthreads();
        compute(t & 1);
        __syncthreads();
        if (t + 2 < nt) { cpA((t + 2) * BK, t & 1); cpB((t + 2) * BK, t & 1); cpcommit(); }
    }

    auto emit = [&](int r, int c, float v) {
        if (EPI == EPI_SCALE) v *= scale;
        if (EPI == EPI_BIAS || EPI == EPI_BIAS_RES || EPI == EPI_BIAS_GELU || EPI == EPI_CONV)
            v += bias[c];
        if (EPI == EPI_BIAS_GELU)
            v = 0.5f * v * (1.f + erff(v * 0.70710678118654752f));
        if (EPI == EPI_CONV) {
            int b_ = r >> 7;
            int s_ = r & 127;
            int t_ = s_ * 4 + hh;
            v += resid[t_ * H + c];
            if (RND) v = rndf(v);
            C[((long)b_ * TT + t_) * ldc + c] = v;
        } else {
            long idx = coff + (long)r * ldc + c;
            if (EPI == EPI_BIAS_RES) v += resid[idx];
            if (RND) v = rndf(v);
            C[idx] = v;
        }
    };

#pragma unroll
    for (int mi = 0; mi < MT; mi++) {
        int r0 = row0 + wm * WTM + mi * 16 + gid;
#pragma unroll
        for (int ni = 0; ni < NT; ni++) {
            int c0 = col0 + wn * WTN + ni * 8 + tig * 2;
            if (c0 < N)     emit(r0,     c0,     acc[mi][ni][0]);
            if (c0 + 1 < N) emit(r0,     c0 + 1, acc[mi][ni][1]);
            if (c0 < N)     emit(r0 + 8, c0,     acc[mi][ni][2]);
            if (c0 + 1 < N) emit(r0 + 8, c0 + 1, acc[mi][ni][3]);
        }
    }
}

// ---------------- fused flash attention ----------------
// qkv arrives tf32-pre-rounded -> no K/V conversion pass needed.
#define FA_SQ 0
#define FA_SK 8704
#define FA_SV 17408
#define FA_SP 26112
#define FA_RED 43008
#define FA_M 43520
#define FA_L 43648
#define FA_AL 43776
#define FA_SMEM_FLOATS 43904
#define FA_SMEM_BYTES (FA_SMEM_FLOATS * 4)

__global__ void __launch_bounds__(256, 1) fattn_k(
    const float* __restrict__ qkv, float* __restrict__ att)
{
    extern __shared__ float sm[];
    float* sQ = sm + FA_SQ;
    float* sK = sm + FA_SK;
    float* sV = sm + FA_SV;
    float* sP = sm + FA_SP;
    float* sRed = sm + FA_RED;
    float* sM = sm + FA_M;
    float* sL = sm + FA_L;
    float* sAl = sm + FA_AL;
    const uint32_t smu = (uint32_t)__cvta_generic_to_shared(sm);
    const uint32_t* uQ = (const uint32_t*)sQ;
    const uint32_t* uK = (const uint32_t*)sK;
    const uint32_t* uV = (const uint32_t*)sV;
    const uint32_t* uP = (const uint32_t*)sP;

    const int z = blockIdx.y;
    const int bb = z >> 3, hh = z & 7;
    const int q0 = blockIdx.x * 128;
    const long base = (long)bb * TT * 3 * H + (long)hh * DHD;

    const int tid = threadIdx.x;
    const int warp = tid >> 5, lane = tid & 31;
    const int wm = warp >> 2, wn = warp & 3;
    const int gid = lane >> 2, tig = lane & 3;

    // load Q; scale by 1/8 (exact power of 2 on tf32-rounded values)
#pragma unroll
    for (int l = 0; l < 8; l++) {
        int idx = l * 256 + tid;
        int r = idx >> 4, c4 = (idx & 15) * 4;
        cp16(smu + (uint32_t)(FA_SQ + r * 68 + c4) * 4,
             qkv + base + (long)(q0 + r) * (3 * H) + c4);
    }
    cpcommit();
    cpwait<0>();
    __syncthreads();
#pragma unroll
    for (int l = 0; l < 8; l++) {
        int idx = l * 256 + tid;
        int r = idx >> 4, c4 = (idx & 15) * 4;
        float4* p = (float4*)&sQ[r * 68 + c4];
        float4 v = *p;
        v.x *= 0.125f; v.y *= 0.125f; v.z *= 0.125f; v.w *= 0.125f;
        *p = v;
    }
    if (tid < 128) { sM[tid] = -1e30f; sL[tid] = 0.f; }

    float oacc[4][2][4];
#pragma unroll
    for (int mi = 0; mi < 4; mi++)
#pragma unroll
        for (int ni = 0; ni < 2; ni++)
#pragma unroll
            for (int q = 0; q < 4; q++) oacc[mi][ni][q] = 0.f;

    for (int j = 0; j < 4; j++) {
        __syncthreads();   // prev iteration's sK/sV reads done; publish Q scale on iter 0
#pragma unroll
        for (int l = 0; l < 8; l++) {
            int idx = l * 256 + tid;
            int r = idx >> 4, c4 = (idx & 15) * 4;
            long row = (long)(j * 128 + r) * (3 * H);
            cp16(smu + (uint32_t)(FA_SK + r * 68 + c4) * 4, qkv + base + H + row + c4);
            cp16(smu + (uint32_t)(FA_SV + r * 68 + c4) * 4, qkv + base + 2 * H + row + c4);
        }
        cpcommit();
        cpwait<0>();
        __syncthreads();

        float sacc[4][4][4];
#pragma unroll
        for (int mi = 0; mi < 4; mi++)
#pragma unroll
            for (int ni = 0; ni < 4; ni++)
#pragma unroll
                for (int q = 0; q < 4; q++) sacc[mi][ni][q] = 0.f;
#pragma unroll
        for (int ks = 0; ks < 8; ks++) {
            const int k = ks * 8;
            uint32_t af[4][4], bf[4][2];
#pragma unroll
            for (int mi = 0; mi < 4; mi++) {
                int r0 = wm * 64 + mi * 16 + gid;
                af[mi][0] = uQ[r0 * 68 + k + tig];
                af[mi][1] = uQ[(r0 + 8) * 68 + k + tig];
                af[mi][2] = uQ[r0 * 68 + k + tig + 4];
                af[mi][3] = uQ[(r0 + 8) * 68 + k + tig + 4];
            }
#pragma unroll
            for (int ni = 0; ni < 4; ni++) {
                int n0 = wn * 32 + ni * 8 + gid;
                bf[ni][0] = uK[n0 * 68 + k + tig];
                bf[ni][1] = uK[n0 * 68 + k + tig + 4];
            }
#pragma unroll
            for (int mi = 0; mi < 4; mi++)
#pragma unroll
                for (int ni = 0; ni < 4; ni++)
                    mma8(sacc[mi][ni], af[mi], bf[ni]);
        }

#pragma unroll
        for (int mi = 0; mi < 4; mi++) {
            float r0m = -1e30f, r1m = -1e30f;
#pragma unroll
            for (int ni = 0; ni < 4; ni++) {
                r0m = fmaxf(r0m, fmaxf(sacc[mi][ni][0], sacc[mi][ni][1]));
                r1m = fmaxf(r1m, fmaxf(sacc[mi][ni][2], sacc[mi][ni][3]));
            }
            r0m = fmaxf(r0m, __shfl_xor_sync(0xffffffffu, r0m, 1));
            r0m = fmaxf(r0m, __shfl_xor_sync(0xffffffffu, r0m, 2));
            r1m = fmaxf(r1m, __shfl_xor_sync(0xffffffffu, r1m, 1));
            r1m = fmaxf(r1m, __shfl_xor_sync(0xffffffffu, r1m, 2));
            if (tig == 0) {
                int r0 = wm * 64 + mi * 16 + gid;
                sRed[wn * 128 + r0] = r0m;
                sRed[wn * 128 + r0 + 8] = r1m;
            }
        }
        __syncthreads();
        if (tid < 128) {
            float mt = fmaxf(fmaxf(sRed[tid], sRed[128 + tid]),
                             fmaxf(sRed[256 + tid], sRed[384 + tid]));
            float mo = sM[tid];
            float mn = fmaxf(mo, mt);
            sAl[tid] = __expf(mo - mn);
            sM[tid] = mn;
        }
        __syncthreads();

#pragma unroll
        for (int mi = 0; mi < 4; mi++) {
            int r0 = wm * 64 + mi * 16 + gid;
            float m0 = sM[r0], m1 = sM[r0 + 8];
            float rs0 = 0.f, rs1 = 0.f;
#pragma unroll
            for (int ni = 0; ni < 4; ni++) {
                int c0 = wn * 32 + ni * 8 + tig * 2;
                float p00 = __expf(sacc[mi][ni][0] - m0);
                float p01 = __expf(sacc[mi][ni][1] - m0);
                float p10 = __expf(sacc[mi][ni][2] - m1);
                float p11 = __expf(sacc[mi][ni][3] - m1);
                rs0 += p00 + p01;
                rs1 += p10 + p11;
                *(float2*)&sP[r0 * 132 + c0] =
                    make_float2(rndf(p00), rndf(p01));
                *(float2*)&sP[(r0 + 8) * 132 + c0] =
                    make_float2(rndf(p10), rndf(p11));
            }
            rs0 += __shfl_xor_sync(0xffffffffu, rs0, 1);
            rs0 += __shfl_xor_sync(0xffffffffu, rs0, 2);
            rs1 += __shfl_xor_sync(0xffffffffu, rs1, 1);
            rs1 += __shfl_xor_sync(0xffffffffu, rs1, 2);
            if (tig == 0) {
                sRed[wn * 128 + r0] = rs0;
                sRed[wn * 128 + r0 + 8] = rs1;
            }
        }
        __syncthreads();
        if (tid < 128) {
            sL[tid] = sL[tid] * sAl[tid] +
                      (sRed[tid] + sRed[128 + tid]) + (sRed[256 + tid] + sRed[384 + tid]);
        }

#pragma unroll
        for (int mi = 0; mi < 4; mi++) {
            int r0 = wm * 64 + mi * 16 + gid;
            float a0 = sAl[r0], a1 = sAl[r0 + 8];
#pragma unroll
            for (int ni = 0; ni < 2; ni++) {
                oacc[mi][ni][0] *= a0;
                oacc[mi][ni][1] *= a0;
                oacc[mi][ni][2] *= a1;
                oacc[mi][ni][3] *= a1;
            }
        }

#pragma unroll
        for (int ks = 0; ks < 16; ks++) {
            const int k = ks * 8;
            uint32_t af[4][4], bf[2][2];
#pragma unroll
            for (int mi = 0; mi < 4; mi++) {
                int r0 = wm * 64 + mi * 16 + gid;
                af[mi][0] = uP[r0 * 132 + k + tig];
                af[mi][1] = uP[(r0 + 8) * 132 + k + tig];
                af[mi][2] = uP[r0 * 132 + k + tig + 4];
                af[mi][3] = uP[(r0 + 8) * 132 + k + tig + 4];
            }
#pragma unroll
            for (int ni = 0; ni < 2; ni++) {
                int n0 = wn * 16 + ni * 8 + gid;
                bf[ni][0] = uV[(k + tig) * 68 + n0];
                bf[ni][1] = uV[(k + tig + 4) * 68 + n0];
            }
#pragma unroll
            for (int mi = 0; mi < 4; mi++)
#pragma unroll
                for (int ni = 0; ni < 2; ni++)
                    mma8(oacc[mi][ni], af[mi], bf[ni]);
        }
    }
    __syncthreads();

    // O /= l, write out tf32-rounded (feeds out-proj GEMM only)
#pragma unroll
    for (int mi = 0; mi < 4; mi++) {
        int r0 = wm * 64 + mi * 16 + gid;
        float i0 = 1.f / sL[r0], i1 = 1.f / sL[r0 + 8];
        long o0 = ((long)bb * TT + q0 + r0) * H + hh * DHD;
        long o1 = ((long)bb * TT + q0 + r0 + 8) * H + hh * DHD;
#pragma unroll
        for (int ni = 0; ni < 2; ni++) {
            int c0 = wn * 16 + ni * 8 + tig * 2;
            *(float2*)&att[o0 + c0] = make_float2(rndf(oacc[mi][ni][0] * i0), rndf(oacc[mi][ni][1] * i0));
            *(float2*)&att[o1 + c0] = make_float2(rndf(oacc[mi][ni][2] * i1), rndf(oacc[mi][ni][3] * i1));
        }
    }
}

// ---------------- LayerNorm (tf32-rounded output; h feeds GEMMs only) ----------------
__global__ void ln_k(const float* __restrict__ x, const float* __restrict__ g,
                     const float* __restrict__ b, float* __restrict__ o)
{
    long row = blockIdx.x;
    int t = threadIdx.x;
    float4 v = ((const float4*)(x + row * H))[t];
    float s = v.x + v.y + v.z + v.w;
    float ss = v.x * v.x + v.y * v.y + v.z * v.z + v.w * v.w;
#pragma unroll
    for (int off = 16; off; off >>= 1) {
        s += __shfl_xor_sync(0xffffffffu, s, off);
        ss += __shfl_xor_sync(0xffffffffu, ss, off);
    }
    __shared__ float sm0[4], sm1[4];
    int w = t >> 5;
    if ((t & 31) == 0) { sm0[w] = s; sm1[w] = ss; }
    __syncthreads();
    s = sm0[0] + sm0[1] + sm0[2] + sm0[3];
    ss = sm1[0] + sm1[1] + sm1[2] + sm1[3];
    float mean = s * (1.f / H);
    float var = ss * (1.f / H) - mean * mean;
    float rstd = rsqrtf(var + 1e-5f);
    float4 gg = ((const float4*)g)[t];
    float4 bb4 = ((const float4*)b)[t];
    float4 out;
    out.x = rndf((v.x - mean) * rstd * gg.x + bb4.x);
    out.y = rndf((v.y - mean) * rstd * gg.y + bb4.y);
    out.z = rndf((v.z - mean) * rstd * gg.z + bb4.z);
    out.w = rndf((v.w - mean) * rstd * gg.w + bb4.w);
    ((float4*)(o + row * H))[t] = out;
}

// ---------------- misc kernels ----------------
__global__ void rnd_k(const float* __restrict__ in, float* __restrict__ out, int n4)
{
    int i = blockIdx.x * blockDim.x + threadIdx.x;
    if (i >= n4) return;
    float4 v = ((const float4*)in)[i];
    v.x = rndf(v.x); v.y = rndf(v.y); v.z = rndf(v.z); v.w = rndf(v.w);
    ((float4*)out)[i] = v;
}

__global__ void pe_k(float* __restrict__ pe)
{
    int t = blockIdx.x;
    int i = threadIdx.x;
    float div = expf(-(float)(2 * i) * (logf(10000.f) / (float)H));
    float a = (float)t * div;
    pe[t * H + 2 * i] = sinf(a);
    pe[t * H + 2 * i + 1] = cosf(a);
}

__global__ void convT_k(const float* __restrict__ w, float* __restrict__ o)
{
    int idx = blockIdx.x * blockDim.x + threadIdx.x;
    if (idx >= 4 * H * H) return;
    int k = idx / (H * H);
    int d = (idx / H) % H;
    int c = idx % H;
    o[idx] = rndf(w[c * H * 4 + d * 4 + k]);
}

__global__ void xinit_k(const float* __restrict__ qe, const float* __restrict__ pe,
                        float* __restrict__ x)
{
    long i = blockIdx.x * (long)blockDim.x + threadIdx.x;
    if (i >= (long)BB * TT * H) return;
    int td = (int)(i % (TT * H));
    x[i] = qe[td] + pe[td];
}

__global__ void kin_k(const float* __restrict__ ho, float* __restrict__ out)
{
    int row = blockIdx.x * blockDim.x + threadIdx.x;
    if (row >= BB * TT) return;
    const float* r = ho + (long)row * NOUT;
    float* o = out + (long)row * (3 * NJ);
    float gx[NJ], px[NJ], py[NJ];
    gx[0] = 0.f;
    px[0] = r[100];
    py[0] = r[101];
    o[0] = px[0]; o[1] = py[0]; o[2] = 1.f;
    for (int j = 1; j < NJ; j++) {
        int pa = PAR[j];
        float gg = gx[pa] + r[j];
        gx[j] = gg;
        float s = r[50 + j];
        float sn, cs;
        sincosf(gg, &sn, &cs);
        px[j] = px[pa] + cs * s;
        py[j] = py[pa] + sn * s;
        o[j * 3 + 0] = px[j];
        o[j * 3 + 1] = py[j];
        o[j * 3 + 2] = 1.f;
    }
}

// ---------------- launcher ----------------
static inline dim3 gg128(int M, int N, int bz = 1)
{
    return dim3((N + 127) / 128, (M + 127) / 128, bz);
}

#define Z6 0L, 0L, 0L, 0L, 0L, 0L
#define SMEM_T128 73728

extern "C" void kernel_launch(void* const* d_in, const int* in_sizes, int n_in,
                              void* d_out, int out_size)
{
    const float* memory   = (const float*)d_in[0];
    const float* in_w     = (const float*)d_in[1];
    const float* in_b     = (const float*)d_in[2];
    const float* conv_w   = (const float*)d_in[3];
    const float* conv_b   = (const float*)d_in[4];
    const float* qemb     = (const float*)d_in[5];
    const float* sa_in_w  = (const float*)d_in[6];
    const float* sa_in_b  = (const float*)d_in[7];
    const float* sa_out_w = (const float*)d_in[8];
    const float* sa_out_b = (const float*)d_in[9];
    const float* ca_in_w  = (const float*)d_in[10];
    const float* ca_in_b  = (const float*)d_in[11];
    const float* ca_out_w = (const float*)d_in[12];
    const float* ca_out_b = (const float*)d_in[13];
    const float* ln1_g    = (const float*)d_in[14];
    const float* ln1_b    = (const float*)d_in[15];
    const float* ln2_g    = (const float*)d_in[16];
    const float* ln2_b    = (const float*)d_in[17];
    const float* ln3_g    = (const float*)d_in[18];
    const float* ln3_b    = (const float*)d_in[19];
    const float* ff1_w    = (const float*)d_in[20];
    const float* ff1_b    = (const float*)d_in[21];
    const float* ff2_w    = (const float*)d_in[22];
    const float* ff2_b    = (const float*)d_in[23];
    const float* out_w    = (const float*)d_in[24];
    const float* out_b    = (const float*)d_in[25];

    float *m_, *mem_, *x_, *h_, *qkv_, *att_, *ff_, *ho_, *pe_, *cT_, *wt_;
    cudaGetSymbolAddress((void**)&m_,   g_m);
    cudaGetSymbolAddress((void**)&mem_, g_mem);
    cudaGetSymbolAddress((void**)&x_,   g_x);
    cudaGetSymbolAddress((void**)&h_,   g_h);
    cudaGetSymbolAddress((void**)&qkv_, g_qkv);
    cudaGetSymbolAddress((void**)&att_, g_att);
    cudaGetSymbolAddress((void**)&ff_,  g_ff);
    cudaGetSymbolAddress((void**)&ho_,  g_head);
    cudaGetSymbolAddress((void**)&pe_,  g_pe);
    cudaGetSymbolAddress((void**)&cT_,  g_convT);
    cudaGetSymbolAddress((void**)&wt_,  g_wtf);

    cudaFuncSetAttribute(gemm6<EPI_BIAS,      true,  true >, cudaFuncAttributeMaxDynamicSharedMemorySize, SMEM_T128);
    cudaFuncSetAttribute(gemm6<EPI_CONV,      false, true >, cudaFuncAttributeMaxDynamicSharedMemorySize, SMEM_T128);
    cudaFuncSetAttribute(gemm6<EPI_BIAS,      false, true >, cudaFuncAttributeMaxDynamicSharedMemorySize, SMEM_T128);
    cudaFuncSetAttribute(gemm6<EPI_BIAS_RES,  false, false>, cudaFuncAttributeMaxDynamicSharedMemorySize, SMEM_T128);
    cudaFuncSetAttribute(gemm6<EPI_BIAS_GELU, false, true >, cudaFuncAttributeMaxDynamicSharedMemorySize, SMEM_T128);
    cudaFuncSetAttribute(gemm6<EPI_BIAS,      true,  false>, cudaFuncAttributeMaxDynamicSharedMemorySize, SMEM_T128);
    cudaFuncSetAttribute(fattn_k, cudaFuncAttributeMaxDynamicSharedMemorySize, FA_SMEM_BYTES);

    // prep: pe, conv weights, tf32 weight copies
    pe_k<<<TT, 256>>>(pe_);
    convT_k<<<(4 * H * H + 255) / 256, 256>>>(conv_w, cT_);
    rnd_k<<<(3145728 / 4 + 255) / 256, 256>>>(sa_in_w,  wt_ + WOFF_SAIN,  3145728 / 4);
    rnd_k<<<(1048576 / 4 + 255) / 256, 256>>>(sa_out_w, wt_ + WOFF_SAOUT, 1048576 / 4);
    rnd_k<<<(3145728 / 4 + 255) / 256, 256>>>(ca_in_w,  wt_ + WOFF_CAIN,  3145728 / 4);
    rnd_k<<<(1048576 / 4 + 255) / 256, 256>>>(ca_out_w, wt_ + WOFF_CAOUT, 1048576 / 4);
    rnd_k<<<(4194304 / 4 + 255) / 256, 256>>>(ff1_w,    wt_ + WOFF_FF1,   4194304 / 4);
    rnd_k<<<(4194304 / 4 + 255) / 256, 256>>>(ff2_w,    wt_ + WOFF_FF2,   4194304 / 4);

    // m = memory @ in_w^T + in_b   (raw fp32 inputs -> CVT in loop; rounded output)
    gemm6<EPI_BIAS, true, true><<<gg128(BB * SS, H), 256, SMEM_T128>>>(
        memory, in_w, in_b, nullptr, m_,
        BB * SS, H, H, H, H, H, Z6, 1, 1.f);

    gemm6<EPI_CONV, false, true><<<gg128(BB * SS, H, 4), 256, SMEM_T128>>>(
        m_, cT_, conv_b, pe_, mem_,
        BB * SS, H, H, H, H, H,
        0L, 0L, 0L, (long)H * H, 0L, 0L, 4, 1.f);

    xinit_k<<<(BB * TT * H + 255) / 256, 256>>>(qemb, pe_, x_);

    const dim3 fa_grid(TT / 128, BB * NHEAD);

    for (int l = 0; l < NL; l++) {
        // ======== self-attention ========
        ln_k<<<BB * TT, 128>>>(x_, ln1_g + l * H, ln1_b + l * H, h_);
        gemm6<EPI_BIAS, false, true><<<gg128(BB * TT, 3 * H), 256, SMEM_T128>>>(
            h_, wt_ + WOFF_SAIN + (long)l * 3 * H * H, sa_in_b + (long)l * 3 * H, nullptr, qkv_,
            BB * TT, 3 * H, H, H, H, 3 * H, Z6, 1, 1.f);
        fattn_k<<<fa_grid, 256, FA_SMEM_BYTES>>>(qkv_, att_);
        gemm6<EPI_BIAS_RES, false, false><<<gg128(BB * TT, H), 256, SMEM_T128>>>(
            att_, wt_ + WOFF_SAOUT + (long)l * H * H, sa_out_b + (long)l * H, x_, x_,
            BB * TT, H, H, H, H, H, Z6, 1, 1.f);

        // ======== cross-attention ========
        ln_k<<<BB * TT, 128>>>(x_, ln2_g + l * H, ln2_b + l * H, h_);
        gemm6<EPI_BIAS, false, true><<<gg128(BB * TT, H), 256, SMEM_T128>>>(
            h_, wt_ + WOFF_CAIN + (long)l * 3 * H * H, ca_in_b + (long)l * 3 * H, nullptr, qkv_,
            BB * TT, H, H, H, H, 3 * H, Z6, 1, 1.f);
        gemm6<EPI_BIAS, false, true><<<gg128(BB * TT, 2 * H), 256, SMEM_T128>>>(
            mem_, wt_ + WOFF_CAIN + (long)l * 3 * H * H + (long)H * H,
            ca_in_b + (long)l * 3 * H + H, nullptr, qkv_ + H,
            BB * TT, 2 * H, H, H, H, 3 * H, Z6, 1, 1.f);
        fattn_k<<<fa_grid, 256, FA_SMEM_BYTES>>>(qkv_, att_);
        gemm6<EPI_BIAS_RES, false, false><<<gg128(BB * TT, H), 256, SMEM_T128>>>(
            att_, wt_ + WOFF_CAOUT + (long)l * H * H, ca_out_b + (long)l * H, x_, x_,
            BB * TT, H, H, H, H, H, Z6, 1, 1.f);

        // ======== FFN ========
        ln_k<<<BB * TT, 128>>>(x_, ln3_g + l * H, ln3_b + l * H, h_);
        gemm6<EPI_BIAS_GELU, false, true><<<gg128(BB * TT, FF), 256, SMEM_T128>>>(
            h_, wt_ + WOFF_FF1 + (long)l * FF * H, ff1_b + (long)l * FF, nullptr, ff_,
            BB * TT, FF, H, H, H, FF, Z6, 1, 1.f);
        gemm6<EPI_BIAS_RES, false, false><<<gg128(BB * TT, H), 256, SMEM_T128>>>(
            ff_, wt_ + WOFF_FF2 + (long)l * H * FF, ff2_b + (long)l * H, x_, x_,
            BB * TT, H, FF, FF, FF, H, Z6, 1, 1.f);
    }

    // head: raw fp32 x_ and out_w -> CVT in loop, fp32 output
    gemm6<EPI_BIAS, true, false><<<gg128(BB * TT, NOUT), 256, SMEM_T128>>>(
        x_, out_w, out_b, nullptr, ho_,
        BB * TT, NOUT, H, H, H, NOUT, Z6, 1, 1.f);

    kin_k<<<(BB * TT + 255) / 256, 256>>>(ho_, (float*)d_out);
}

// round 8
// speedup vs baseline: 1.3562x; 1.0053x over previous
#include <cuda_runtime.h>
#include <math.h>
#include <stdint.h>

#define H 512
#define BB 32
#define SS 128
#define TT 512
#define NHEAD 8
#define DHD 64
#define NL 4
#define FF 2048
#define NOUT 102
#define NJ 50

// ---------------- scratch ----------------
__device__ float g_m[BB * SS * H];
__device__ float g_mem[BB * TT * H];
__device__ float g_x[BB * TT * H];
__device__ float g_h[BB * TT * H];
__device__ float g_qkv[BB * TT * 3 * H];
__device__ float g_att[BB * TT * H];
__device__ float g_ff[BB * TT * FF];
__device__ float g_head[BB * TT * NOUT];
__device__ float g_pe[TT * H];
__device__ float g_convT[4 * H * H];
__device__ float g_wtf[16777216];   // tf32-rounded weights, 64 MB

#define WOFF_SAIN  0
#define WOFF_SAOUT 3145728
#define WOFF_CAIN  4194304
#define WOFF_CAOUT 7340032
#define WOFF_FF1   8388608
#define WOFF_FF2   12582912

__constant__ int PAR[NJ] = {
    -1, 0, 1, 2, 3, 1, 5, 6, 1,
    4, 9, 10, 11,  4, 13, 14, 15,  4, 17, 18, 19,  4, 21, 22, 23,  4, 25, 26, 27,
    7, 29, 30, 31, 7, 33, 34, 35,  7, 37, 38, 39,  7, 41, 42, 43,  7, 45, 46, 47,
    8
};

#define EPI_NONE 0
#define EPI_SCALE 1
#define EPI_BIAS 2
#define EPI_BIAS_RES 3
#define EPI_BIAS_GELU 4
#define EPI_CONV 5

// ---------------- ptx helpers ----------------
__device__ __forceinline__ uint32_t f2tf(float f)
{
    uint32_t u;
    asm("cvt.rna.tf32.f32 %0, %1;" : "=r"(u) : "f"(f));
    return u;
}
__device__ __forceinline__ uint32_t u2tf(uint32_t x)
{
    uint32_t u;
    asm("cvt.rna.tf32.f32 %0, %1;" : "=r"(u) : "f"(__uint_as_float(x)));
    return u;
}
__device__ __forceinline__ float rndf(float f) { return __uint_as_float(f2tf(f)); }

__device__ __forceinline__ void cp16(uint32_t dst, const void* src)
{
    asm volatile("cp.async.cg.shared.global [%0], [%1], 16;\n" :: "r"(dst), "l"(src));
}
__device__ __forceinline__ void cp16z(uint32_t dst, const void* src, bool p)
{
    int sz = p ? 16 : 0;
    asm volatile("cp.async.cg.shared.global [%0], [%1], 16, %2;\n"
                 :: "r"(dst), "l"(src), "r"(sz));
}
__device__ __forceinline__ void cpcommit()
{
    asm volatile("cp.async.commit_group;\n" ::: "memory");
}
template <int W>
__device__ __forceinline__ void cpwait()
{
    asm volatile("cp.async.wait_group %0;\n" :: "n"(W) : "memory");
}
__device__ __forceinline__ void mma8(float* d, const uint32_t* a, const uint32_t* b)
{
    asm volatile(
        "mma.sync.aligned.m16n8k8.row.col.f32.tf32.tf32.f32 "
        "{%0,%1,%2,%3}, {%4,%5,%6,%7}, {%8,%9}, {%0,%1,%2,%3};\n"
        : "+f"(d[0]), "+f"(d[1]), "+f"(d[2]), "+f"(d[3])
        : "r"(a[0]), "r"(a[1]), "r"(a[2]), "r"(a[3]), "r"(b[0]), "r"(b[1]));
}
__device__ __forceinline__ void ldsm4(uint32_t* r, uint32_t addr)
{
    asm volatile("ldmatrix.sync.aligned.m8n8.x4.shared.b16 {%0,%1,%2,%3}, [%4];\n"
                 : "=r"(r[0]), "=r"(r[1]), "=r"(r[2]), "=r"(r[3]) : "r"(addr));
}
__device__ __forceinline__ void ldsm2(uint32_t* r, uint32_t addr)
{
    asm volatile("ldmatrix.sync.aligned.m8n8.x2.shared.b16 {%0,%1}, [%2];\n"
                 : "=r"(r[0]), "=r"(r[1]) : "r"(addr));
}

// ---------------- tf32 tensor-core GEMM: 3-stage pipeline, 1 sync/tile ----------------
template <int EPI, bool CVTIN, bool RND>
__global__ void __launch_bounds__(256, 2) gemm7(
    const float* __restrict__ A, const float* __restrict__ Bm,
    const float* __restrict__ bias, const float* __restrict__ resid,
    float* __restrict__ C,
    int M, int N, int K, int lda, int ldb, int ldc,
    long sAb, long sAh, long sBb, long sBh, long sCb, long sCh,
    int nh, float scale)
{
    constexpr int BM = 128, BN_ = 128, BK = 32;
    constexpr int WTM = 64, WTN = 32;
    constexpr int MT = 4, NT = 4;
    constexpr int LDA = BK + 4;
    constexpr int LDB = BK + 4;
    constexpr int ACH = BM * BK / 4 / 256;    // 4
    constexpr int BCH = BN_ * BK / 4 / 256;   // 4
    constexpr int STG = BM * LDA + BN_ * LDB; // floats per stage (9216)

    extern __shared__ float sm[];
    const uint32_t smu = (uint32_t)__cvta_generic_to_shared(sm);

    const int z = blockIdx.z;
    const int bb = z / nh, hh = z - bb * nh;
    A += (long)bb * sAb + (long)hh * sAh;
    Bm += (long)bb * sBb + (long)hh * sBh;
    const long coff = (long)bb * sCb + (long)hh * sCh;

    const int row0 = blockIdx.y * BM;
    const int col0 = blockIdx.x * BN_;
    const int tid = threadIdx.x;
    const int warp = tid >> 5;
    const int lane = tid & 31;
    const int wm = warp >> 2;
    const int wn = warp & 3;
    const int gid = lane >> 2;
    const int tig = lane & 3;
    const int l15 = lane & 15;
    const int l7 = lane & 7;
    const int acol = (lane >> 4) << 2;
    const int bcol = ((lane >> 3) & 1) << 2;

    float acc[MT][NT][4];
#pragma unroll
    for (int i = 0; i < MT; i++)
#pragma unroll
        for (int j = 0; j < NT; j++)
#pragma unroll
            for (int q = 0; q < 4; q++) acc[i][j][q] = 0.f;

    auto cpTile = [&](int k0, int st) {
        uint32_t sbase = smu + (uint32_t)(st * STG) * 4;
#pragma unroll
        for (int l = 0; l < ACH; l++) {
            int idx = l * 256 + tid;
            int r = idx >> 3;
            int cq = (idx & 7) * 4;
            cp16(sbase + (uint32_t)(r * LDA + cq) * 4,
                 A + (long)(row0 + r) * lda + k0 + cq);
        }
        uint32_t bbase = sbase + (uint32_t)(BM * LDA) * 4;
#pragma unroll
        for (int l = 0; l < BCH; l++) {
            int idx = l * 256 + tid;
            int n = idx >> 3;
            int cq = (idx & 7) * 4;
            cp16z(bbase + (uint32_t)(n * LDB + cq) * 4,
                  Bm + (long)(col0 + n) * ldb + k0 + cq,
                  (col0 + n) < N);
        }
        cpcommit();
    };

    auto compute = [&](int st) {
        const uint32_t pAu = smu + (uint32_t)(st * STG) * 4;
        const uint32_t pBu = pAu + (uint32_t)(BM * LDA) * 4;
#pragma unroll
        for (int ks = 0; ks < 4; ks++) {
            const int k = ks * 8;
            uint32_t af[MT][4], bf[NT][2];
#pragma unroll
            for (int mi = 0; mi < MT; mi++) {
                int r0 = wm * WTM + mi * 16 + l15;
                ldsm4(af[mi], pAu + (uint32_t)(r0 * LDA + k + acol) * 4);
                if (CVTIN) {
                    af[mi][0] = u2tf(af[mi][0]);
                    af[mi][1] = u2tf(af[mi][1]);
                    af[mi][2] = u2tf(af[mi][2]);
                    af[mi][3] = u2tf(af[mi][3]);
                }
            }
#pragma unroll
            for (int ni = 0; ni < NT; ni++) {
                int n0 = wn * WTN + ni * 8 + l7;
                ldsm2(bf[ni], pBu + (uint32_t)(n0 * LDB + k + bcol) * 4);
                if (CVTIN) {
                    bf[ni][0] = u2tf(bf[ni][0]);
                    bf[ni][1] = u2tf(bf[ni][1]);
                }
            }
#pragma unroll
            for (int mi = 0; mi < MT; mi++)
#pragma unroll
                for (int ni = 0; ni < NT; ni++)
                    mma8(acc[mi][ni], af[mi], bf[ni]);
        }
    };

    const int nt = K / BK;                 // >= 16 for all our shapes
    cpTile(0, 0);
    cpTile(BK, 1);

    int st = 0;                            // stage of tile t
    for (int t = 0; t < nt; t++) {
        if (t < nt - 1) cpwait<1>(); else cpwait<0>();
        __syncthreads();                   // tile t resident + prev compute done
        if (t + 2 < nt) {
            int st2 = st + 2; if (st2 >= 3) st2 -= 3;
            cpTile((t + 2) * BK, st2);     // overlaps with compute below
        }
        compute(st);
        if (++st == 3) st = 0;
    }

    auto emit = [&](int r, int c, float v) {
        if (EPI == EPI_SCALE) v *= scale;
        if (EPI == EPI_BIAS || EPI == EPI_BIAS_RES || EPI == EPI_BIAS_GELU || EPI == EPI_CONV)
            v += bias[c];
        if (EPI == EPI_BIAS_GELU)
            v = 0.5f * v * (1.f + erff(v * 0.70710678118654752f));
        if (EPI == EPI_CONV) {
            int b_ = r >> 7;
            int s_ = r & 127;
            int t_ = s_ * 4 + hh;
            v += resid[t_ * H + c];
            if (RND) v = rndf(v);
            C[((long)b_ * TT + t_) * ldc + c] = v;
        } else {
            long idx = coff + (long)r * ldc + c;
            if (EPI == EPI_BIAS_RES) v += resid[idx];
            if (RND) v = rndf(v);
            C[idx] = v;
        }
    };

#pragma unroll
    for (int mi = 0; mi < MT; mi++) {
        int r0 = row0 + wm * WTM + mi * 16 + gid;
#pragma unroll
        for (int ni = 0; ni < NT; ni++) {
            int c0 = col0 + wn * WTN + ni * 8 + tig * 2;
            if (c0 < N)     emit(r0,     c0,     acc[mi][ni][0]);
            if (c0 + 1 < N) emit(r0,     c0 + 1, acc[mi][ni][1]);
            if (c0 < N)     emit(r0 + 8, c0,     acc[mi][ni][2]);
            if (c0 + 1 < N) emit(r0 + 8, c0 + 1, acc[mi][ni][3]);
        }
    }
}

// ---------------- fused flash attention (unchanged) ----------------
#define FA_SQ 0
#define FA_SK 8704
#define FA_SV 17408
#define FA_SP 26112
#define FA_RED 43008
#define FA_M 43520
#define FA_L 43648
#define FA_AL 43776
#define FA_SMEM_FLOATS 43904
#define FA_SMEM_BYTES (FA_SMEM_FLOATS * 4)

__global__ void __launch_bounds__(256, 1) fattn_k(
    const float* __restrict__ qkv, float* __restrict__ att)
{
    extern __shared__ float sm[];
    float* sQ = sm + FA_SQ;
    float* sK = sm + FA_SK;
    float* sV = sm + FA_SV;
    float* sP = sm + FA_SP;
    float* sRed = sm + FA_RED;
    float* sM = sm + FA_M;
    float* sL = sm + FA_L;
    float* sAl = sm + FA_AL;
    const uint32_t smu = (uint32_t)__cvta_generic_to_shared(sm);
    const uint32_t* uQ = (const uint32_t*)sQ;
    const uint32_t* uK = (const uint32_t*)sK;
    const uint32_t* uV = (const uint32_t*)sV;
    const uint32_t* uP = (const uint32_t*)sP;

    const int z = blockIdx.y;
    const int bb = z >> 3, hh = z & 7;
    const int q0 = blockIdx.x * 128;
    const long base = (long)bb * TT * 3 * H + (long)hh * DHD;

    const int tid = threadIdx.x;
    const int warp = tid >> 5, lane = tid & 31;
    const int wm = warp >> 2, wn = warp & 3;
    const int gid = lane >> 2, tig = lane & 3;

#pragma unroll
    for (int l = 0; l < 8; l++) {
        int idx = l * 256 + tid;
        int r = idx >> 4, c4 = (idx & 15) * 4;
        cp16(smu + (uint32_t)(FA_SQ + r * 68 + c4) * 4,
             qkv + base + (long)(q0 + r) * (3 * H) + c4);
    }
    cpcommit();
    cpwait<0>();
    __syncthreads();
#pragma unroll
    for (int l = 0; l < 8; l++) {
        int idx = l * 256 + tid;
        int r = idx >> 4, c4 = (idx & 15) * 4;
        float4* p = (float4*)&sQ[r * 68 + c4];
        float4 v = *p;
        v.x *= 0.125f; v.y *= 0.125f; v.z *= 0.125f; v.w *= 0.125f;
        *p = v;
    }
    if (tid < 128) { sM[tid] = -1e30f; sL[tid] = 0.f; }

    float oacc[4][2][4];
#pragma unroll
    for (int mi = 0; mi < 4; mi++)
#pragma unroll
        for (int ni = 0; ni < 2; ni++)
#pragma unroll
            for (int q = 0; q < 4; q++) oacc[mi][ni][q] = 0.f;

    for (int j = 0; j < 4; j++) {
        __syncthreads();
#pragma unroll
        for (int l = 0; l < 8; l++) {
            int idx = l * 256 + tid;
            int r = idx >> 4, c4 = (idx & 15) * 4;
            long row = (long)(j * 128 + r) * (3 * H);
            cp16(smu + (uint32_t)(FA_SK + r * 68 + c4) * 4, qkv + base + H + row + c4);
            cp16(smu + (uint32_t)(FA_SV + r * 68 + c4) * 4, qkv + base + 2 * H + row + c4);
        }
        cpcommit();
        cpwait<0>();
        __syncthreads();

        float sacc[4][4][4];
#pragma unroll
        for (int mi = 0; mi < 4; mi++)
#pragma unroll
            for (int ni = 0; ni < 4; ni++)
#pragma unroll
                for (int q = 0; q < 4; q++) sacc[mi][ni][q] = 0.f;
#pragma unroll
        for (int ks = 0; ks < 8; ks++) {
            const int k = ks * 8;
            uint32_t af[4][4], bf[4][2];
#pragma unroll
            for (int mi = 0; mi < 4; mi++) {
                int r0 = wm * 64 + mi * 16 + gid;
                af[mi][0] = uQ[r0 * 68 + k + tig];
                af[mi][1] = uQ[(r0 + 8) * 68 + k + tig];
                af[mi][2] = uQ[r0 * 68 + k + tig + 4];
                af[mi][3] = uQ[(r0 + 8) * 68 + k + tig + 4];
            }
#pragma unroll
            for (int ni = 0; ni < 4; ni++) {
                int n0 = wn * 32 + ni * 8 + gid;
                bf[ni][0] = uK[n0 * 68 + k + tig];
                bf[ni][1] = uK[n0 * 68 + k + tig + 4];
            }
#pragma unroll
            for (int mi = 0; mi < 4; mi++)
#pragma unroll
                for (int ni = 0; ni < 4; ni++)
                    mma8(sacc[mi][ni], af[mi], bf[ni]);
        }

#pragma unroll
        for (int mi = 0; mi < 4; mi++) {
            float r0m = -1e30f, r1m = -1e30f;
#pragma unroll
            for (int ni = 0; ni < 4; ni++) {
                r0m = fmaxf(r0m, fmaxf(sacc[mi][ni][0], sacc[mi][ni][1]));
                r1m = fmaxf(r1m, fmaxf(sacc[mi][ni][2], sacc[mi][ni][3]));
            }
            r0m = fmaxf(r0m, __shfl_xor_sync(0xffffffffu, r0m, 1));
            r0m = fmaxf(r0m, __shfl_xor_sync(0xffffffffu, r0m, 2));
            r1m = fmaxf(r1m, __shfl_xor_sync(0xffffffffu, r1m, 1));
            r1m = fmaxf(r1m, __shfl_xor_sync(0xffffffffu, r1m, 2));
            if (tig == 0) {
                int r0 = wm * 64 + mi * 16 + gid;
                sRed[wn * 128 + r0] = r0m;
                sRed[wn * 128 + r0 + 8] = r1m;
            }
        }
        __syncthreads();
        if (tid < 128) {
            float mt = fmaxf(fmaxf(sRed[tid], sRed[128 + tid]),
                             fmaxf(sRed[256 + tid], sRed[384 + tid]));
            float mo = sM[tid];
            float mn = fmaxf(mo, mt);
            sAl[tid] = __expf(mo - mn);
            sM[tid] = mn;
        }
        __syncthreads();

#pragma unroll
        for (int mi = 0; mi < 4; mi++) {
            int r0 = wm * 64 + mi * 16 + gid;
            float m0 = sM[r0], m1 = sM[r0 + 8];
            float rs0 = 0.f, rs1 = 0.f;
#pragma unroll
            for (int ni = 0; ni < 4; ni++) {
                int c0 = wn * 32 + ni * 8 + tig * 2;
                float p00 = __expf(sacc[mi][ni][0] - m0);
                float p01 = __expf(sacc[mi][ni][1] - m0);
                float p10 = __expf(sacc[mi][ni][2] - m1);
                float p11 = __expf(sacc[mi][ni][3] - m1);
                rs0 += p00 + p01;
                rs1 += p10 + p11;
                *(float2*)&sP[r0 * 132 + c0] = make_float2(rndf(p00), rndf(p01));
                *(float2*)&sP[(r0 + 8) * 132 + c0] = make_float2(rndf(p10), rndf(p11));
            }
            rs0 += __shfl_xor_sync(0xffffffffu, rs0, 1);
            rs0 += __shfl_xor_sync(0xffffffffu, rs0, 2);
            rs1 += __shfl_xor_sync(0xffffffffu, rs1, 1);
            rs1 += __shfl_xor_sync(0xffffffffu, rs1, 2);
            if (tig == 0) {
                sRed[wn * 128 + r0] = rs0;
                sRed[wn * 128 + r0 + 8] = rs1;
            }
        }
        __syncthreads();
        if (tid < 128) {
            sL[tid] = sL[tid] * sAl[tid] +
                      (sRed[tid] + sRed[128 + tid]) + (sRed[256 + tid] + sRed[384 + tid]);
        }

#pragma unroll
        for (int mi = 0; mi < 4; mi++) {
            int r0 = wm * 64 + mi * 16 + gid;
            float a0 = sAl[r0], a1 = sAl[r0 + 8];
#pragma unroll
            for (int ni = 0; ni < 2; ni++) {
                oacc[mi][ni][0] *= a0;
                oacc[mi][ni][1] *= a0;
                oacc[mi][ni][2] *= a1;
                oacc[mi][ni][3] *= a1;
            }
        }

#pragma unroll
        for (int ks = 0; ks < 16; ks++) {
            const int k = ks * 8;
            uint32_t af[4][4], bf[2][2];
#pragma unroll
            for (int mi = 0; mi < 4; mi++) {
                int r0 = wm * 64 + mi * 16 + gid;
                af[mi][0] = uP[r0 * 132 + k + tig];
                af[mi][1] = uP[(r0 + 8) * 132 + k + tig];
                af[mi][2] = uP[r0 * 132 + k + tig + 4];
                af[mi][3] = uP[(r0 + 8) * 132 + k + tig + 4];
            }
#pragma unroll
            for (int ni = 0; ni < 2; ni++) {
                int n0 = wn * 16 + ni * 8 + gid;
                bf[ni][0] = uV[(k + tig) * 68 + n0];
                bf[ni][1] = uV[(k + tig + 4) * 68 + n0];
            }
#pragma unroll
            for (int mi = 0; mi < 4; mi++)
#pragma unroll
                for (int ni = 0; ni < 2; ni++)
                    mma8(oacc[mi][ni], af[mi], bf[ni]);
        }
    }
    __syncthreads();

#pragma unroll
    for (int mi = 0; mi < 4; mi++) {
        int r0 = wm * 64 + mi * 16 + gid;
        float i0 = 1.f / sL[r0], i1 = 1.f / sL[r0 + 8];
        long o0 = ((long)bb * TT + q0 + r0) * H + hh * DHD;
        long o1 = ((long)bb * TT + q0 + r0 + 8) * H + hh * DHD;
#pragma unroll
        for (int ni = 0; ni < 2; ni++) {
            int c0 = wn * 16 + ni * 8 + tig * 2;
            *(float2*)&att[o0 + c0] = make_float2(rndf(oacc[mi][ni][0] * i0), rndf(oacc[mi][ni][1] * i0));
            *(float2*)&att[o1 + c0] = make_float2(rndf(oacc[mi][ni][2] * i1), rndf(oacc[mi][ni][3] * i1));
        }
    }
}

// ---------------- LayerNorm ----------------
__global__ void ln_k(const float* __restrict__ x, const float* __restrict__ g,
                     const float* __restrict__ b, float* __restrict__ o)
{
    long row = blockIdx.x;
    int t = threadIdx.x;
    float4 v = ((const float4*)(x + row * H))[t];
    float s = v.x + v.y + v.z + v.w;
    float ss = v.x * v.x + v.y * v.y + v.z * v.z + v.w * v.w;
#pragma unroll
    for (int off = 16; off; off >>= 1) {
        s += __shfl_xor_sync(0xffffffffu, s, off);
        ss += __shfl_xor_sync(0xffffffffu, ss, off);
    }
    __shared__ float sm0[4], sm1[4];
    int w = t >> 5;
    if ((t & 31) == 0) { sm0[w] = s; sm1[w] = ss; }
    __syncthreads();
    s = sm0[0] + sm0[1] + sm0[2] + sm0[3];
    ss = sm1[0] + sm1[1] + sm1[2] + sm1[3];
    float mean = s * (1.f / H);
    float var = ss * (1.f / H) - mean * mean;
    float rstd = rsqrtf(var + 1e-5f);
    float4 gg = ((const float4*)g)[t];
    float4 bb4 = ((const float4*)b)[t];
    float4 out;
    out.x = rndf((v.x - mean) * rstd * gg.x + bb4.x);
    out.y = rndf((v.y - mean) * rstd * gg.y + bb4.y);
    out.z = rndf((v.z - mean) * rstd * gg.z + bb4.z);
    out.w = rndf((v.w - mean) * rstd * gg.w + bb4.w);
    ((float4*)(o + row * H))[t] = out;
}

// ---------------- misc kernels ----------------
__global__ void rnd_k(const float* __restrict__ in, float* __restrict__ out, int n4)
{
    int i = blockIdx.x * blockDim.x + threadIdx.x;
    if (i >= n4) return;
    float4 v = ((const float4*)in)[i];
    v.x = rndf(v.x); v.y = rndf(v.y); v.z = rndf(v.z); v.w = rndf(v.w);
    ((float4*)out)[i] = v;
}

__global__ void pe_k(float* __restrict__ pe)
{
    int t = blockIdx.x;
    int i = threadIdx.x;
    float div = expf(-(float)(2 * i) * (logf(10000.f) / (float)H));
    float a = (float)t * div;
    pe[t * H + 2 * i] = sinf(a);
    pe[t * H + 2 * i + 1] = cosf(a);
}

__global__ void convT_k(const float* __restrict__ w, float* __restrict__ o)
{
    int idx = blockIdx.x * blockDim.x + threadIdx.x;
    if (idx >= 4 * H * H) return;
    int k = idx / (H * H);
    int d = (idx / H) % H;
    int c = idx % H;
    o[idx] = rndf(w[c * H * 4 + d * 4 + k]);
}

__global__ void xinit_k(const float* __restrict__ qe, const float* __restrict__ pe,
                        float* __restrict__ x)
{
    long i = blockIdx.x * (long)blockDim.x + threadIdx.x;
    if (i >= (long)BB * TT * H) return;
    int td = (int)(i % (TT * H));
    x[i] = qe[td] + pe[td];
}

__global__ void kin_k(const float* __restrict__ ho, float* __restrict__ out)
{
    int row = blockIdx.x * blockDim.x + threadIdx.x;
    if (row >= BB * TT) return;
    const float* r = ho + (long)row * NOUT;
    float* o = out + (long)row * (3 * NJ);
    float gx[NJ], px[NJ], py[NJ];
    gx[0] = 0.f;
    px[0] = r[100];
    py[0] = r[101];
    o[0] = px[0]; o[1] = py[0]; o[2] = 1.f;
    for (int j = 1; j < NJ; j++) {
        int pa = PAR[j];
        float gg = gx[pa] + r[j];
        gx[j] = gg;
        float s = r[50 + j];
        float sn, cs;
        sincosf(gg, &sn, &cs);
        px[j] = px[pa] + cs * s;
        py[j] = py[pa] + sn * s;
        o[j * 3 + 0] = px[j];
        o[j * 3 + 1] = py[j];
        o[j * 3 + 2] = 1.f;
    }
}

// ---------------- launcher ----------------
static inline dim3 gg128(int M, int N, int bz = 1)
{
    return dim3((N + 127) / 128, (M + 127) / 128, bz);
}

#define Z6 0L, 0L, 0L, 0L, 0L, 0L
#define SMEM_3ST 110592

extern "C" void kernel_launch(void* const* d_in, const int* in_sizes, int n_in,
                              void* d_out, int out_size)
{
    const float* memory   = (const float*)d_in[0];
    const float* in_w     = (const float*)d_in[1];
    const float* in_b     = (const float*)d_in[2];
    const float* conv_w   = (const float*)d_in[3];
    const float* conv_b   = (const float*)d_in[4];
    const float* qemb     = (const float*)d_in[5];
    const float* sa_in_w  = (const float*)d_in[6];
    const float* sa_in_b  = (const float*)d_in[7];
    const float* sa_out_w = (const float*)d_in[8];
    const float* sa_out_b = (const float*)d_in[9];
    const float* ca_in_w  = (const float*)d_in[10];
    const float* ca_in_b  = (const float*)d_in[11];
    const float* ca_out_w = (const float*)d_in[12];
    const float* ca_out_b = (const float*)d_in[13];
    const float* ln1_g    = (const float*)d_in[14];
    const float* ln1_b    = (const float*)d_in[15];
    const float* ln2_g    = (const float*)d_in[16];
    const float* ln2_b    = (const float*)d_in[17];
    const float* ln3_g    = (const float*)d_in[18];
    const float* ln3_b    = (const float*)d_in[19];
    const float* ff1_w    = (const float*)d_in[20];
    const float* ff1_b    = (const float*)d_in[21];
    const float* ff2_w    = (const float*)d_in[22];
    const float* ff2_b    = (const float*)d_in[23];
    const float* out_w    = (const float*)d_in[24];
    const float* out_b    = (const float*)d_in[25];

    float *m_, *mem_, *x_, *h_, *qkv_, *att_, *ff_, *ho_, *pe_, *cT_, *wt_;
    cudaGetSymbolAddress((void**)&m_,   g_m);
    cudaGetSymbolAddress((void**)&mem_, g_mem);
    cudaGetSymbolAddress((void**)&x_,   g_x);
    cudaGetSymbolAddress((void**)&h_,   g_h);
    cudaGetSymbolAddress((void**)&qkv_, g_qkv);
    cudaGetSymbolAddress((void**)&att_, g_att);
    cudaGetSymbolAddress((void**)&ff_,  g_ff);
    cudaGetSymbolAddress((void**)&ho_,  g_head);
    cudaGetSymbolAddress((void**)&pe_,  g_pe);
    cudaGetSymbolAddress((void**)&cT_,  g_convT);
    cudaGetSymbolAddress((void**)&wt_,  g_wtf);

    cudaFuncSetAttribute(gemm7<EPI_BIAS,      true,  true >, cudaFuncAttributeMaxDynamicSharedMemorySize, SMEM_3ST);
    cudaFuncSetAttribute(gemm7<EPI_CONV,      false, true >, cudaFuncAttributeMaxDynamicSharedMemorySize, SMEM_3ST);
    cudaFuncSetAttribute(gemm7<EPI_BIAS,      false, true >, cudaFuncAttributeMaxDynamicSharedMemorySize, SMEM_3ST);
    cudaFuncSetAttribute(gemm7<EPI_BIAS_RES,  false, false>, cudaFuncAttributeMaxDynamicSharedMemorySize, SMEM_3ST);
    cudaFuncSetAttribute(gemm7<EPI_BIAS_GELU, false, true >, cudaFuncAttributeMaxDynamicSharedMemorySize, SMEM_3ST);
    cudaFuncSetAttribute(gemm7<EPI_BIAS,      true,  false>, cudaFuncAttributeMaxDynamicSharedMemorySize, SMEM_3ST);
    cudaFuncSetAttribute(fattn_k, cudaFuncAttributeMaxDynamicSharedMemorySize, FA_SMEM_BYTES);

    pe_k<<<TT, 256>>>(pe_);
    convT_k<<<(4 * H * H + 255) / 256, 256>>>(conv_w, cT_);
    rnd_k<<<(3145728 / 4 + 255) / 256, 256>>>(sa_in_w,  wt_ + WOFF_SAIN,  3145728 / 4);
    rnd_k<<<(1048576 / 4 + 255) / 256, 256>>>(sa_out_w, wt_ + WOFF_SAOUT, 1048576 / 4);
    rnd_k<<<(3145728 / 4 + 255) / 256, 256>>>(ca_in_w,  wt_ + WOFF_CAIN,  3145728 / 4);
    rnd_k<<<(1048576 / 4 + 255) / 256, 256>>>(ca_out_w, wt_ + WOFF_CAOUT, 1048576 / 4);
    rnd_k<<<(4194304 / 4 + 255) / 256, 256>>>(ff1_w,    wt_ + WOFF_FF1,   4194304 / 4);
    rnd_k<<<(4194304 / 4 + 255) / 256, 256>>>(ff2_w,    wt_ + WOFF_FF2,   4194304 / 4);

    gemm7<EPI_BIAS, true, true><<<gg128(BB * SS, H), 256, SMEM_3ST>>>(
        memory, in_w, in_b, nullptr, m_,
        BB * SS, H, H, H, H, H, Z6, 1, 1.f);

    gemm7<EPI_CONV, false, true><<<gg128(BB * SS, H, 4), 256, SMEM_3ST>>>(
        m_, cT_, conv_b, pe_, mem_,
        BB * SS, H, H, H, H, H,
        0L, 0L, 0L, (long)H * H, 0L, 0L, 4, 1.f);

    xinit_k<<<(BB * TT * H + 255) / 256, 256>>>(qemb, pe_, x_);

    const dim3 fa_grid(TT / 128, BB * NHEAD);

    for (int l = 0; l < NL; l++) {
        // ======== self-attention ========
        ln_k<<<BB * TT, 128>>>(x_, ln1_g + l * H, ln1_b + l * H, h_);
        gemm7<EPI_BIAS, false, true><<<gg128(BB * TT, 3 * H), 256, SMEM_3ST>>>(
            h_, wt_ + WOFF_SAIN + (long)l * 3 * H * H, sa_in_b + (long)l * 3 * H, nullptr, qkv_,
            BB * TT, 3 * H, H, H, H, 3 * H, Z6, 1, 1.f);
        fattn_k<<<fa_grid, 256, FA_SMEM_BYTES>>>(qkv_, att_);
        gemm7<EPI_BIAS_RES, false, false><<<gg128(BB * TT, H), 256, SMEM_3ST>>>(
            att_, wt_ + WOFF_SAOUT + (long)l * H * H, sa_out_b + (long)l * H, x_, x_,
            BB * TT, H, H, H, H, H, Z6, 1, 1.f);

        // ======== cross-attention ========
        ln_k<<<BB * TT, 128>>>(x_, ln2_g + l * H, ln2_b + l * H, h_);
        gemm7<EPI_BIAS, false, true><<<gg128(BB * TT, H), 256, SMEM_3ST>>>(
            h_, wt_ + WOFF_CAIN + (long)l * 3 * H * H, ca_in_b + (long)l * 3 * H, nullptr, qkv_,
            BB * TT, H, H, H, H, 3 * H, Z6, 1, 1.f);
        gemm7<EPI_BIAS, false, true><<<gg128(BB * TT, 2 * H), 256, SMEM_3ST>>>(
            mem_, wt_ + WOFF_CAIN + (long)l * 3 * H * H + (long)H * H,
            ca_in_b + (long)l * 3 * H + H, nullptr, qkv_ + H,
            BB * TT, 2 * H, H, H, H, 3 * H, Z6, 1, 1.f);
        fattn_k<<<fa_grid, 256, FA_SMEM_BYTES>>>(qkv_, att_);
        gemm7<EPI_BIAS_RES, false, false><<<gg128(BB * TT, H), 256, SMEM_3ST>>>(
            att_, wt_ + WOFF_CAOUT + (long)l * H * H, ca_out_b + (long)l * H, x_, x_,
            BB * TT, H, H, H, H, H, Z6, 1, 1.f);

        // ======== FFN ========
        ln_k<<<BB * TT, 128>>>(x_, ln3_g + l * H, ln3_b + l * H, h_);
        gemm7<EPI_BIAS_GELU, false, true><<<gg128(BB * TT, FF), 256, SMEM_3ST>>>(
            h_, wt_ + WOFF_FF1 + (long)l * FF * H, ff1_b + (long)l * FF, nullptr, ff_,
            BB * TT, FF, H, H, H, FF, Z6, 1, 1.f);
        gemm7<EPI_BIAS_RES, false, false><<<gg128(BB * TT, H), 256, SMEM_3ST>>>(
            ff_, wt_ + WOFF_FF2 + (long)l * H * FF, ff2_b + (long)l * H, x_, x_,
            BB * TT, H, FF, FF, FF, H, Z6, 1, 1.f);
    }

    gemm7<EPI_BIAS, true, false><<<gg128(BB * TT, NOUT), 256, SMEM_3ST>>>(
        x_, out_w, out_b, nullptr, ho_,
        BB * TT, NOUT, H, H, H, NOUT, Z6, 1, 1.f);

    kin_k<<<(BB * TT + 255) / 256, 256>>>(ho_, (float*)d_out);
}

// round 9
// speedup vs baseline: 1.9209x; 1.4164x over previous
#include <cuda_runtime.h>
#include <cuda_fp16.h>
#include <math.h>
#include <stdint.h>

#define H 512
#define BB 32
#define SS 128
#define TT 512
#define NHEAD 8
#define DHD 64
#define NL 4
#define FF 2048
#define NOUT 102
#define NJ 50

// ---------------- scratch ----------------
__device__ __half g_memh[BB * SS * H];
__device__ __half g_m[BB * SS * H];
__device__ __half g_mem[BB * TT * H];
__device__ float  g_x[BB * TT * H];
__device__ __half g_xh[BB * TT * H];
__device__ __half g_h[BB * TT * H];
__device__ __half g_qkv[BB * TT * 3 * H];
__device__ __half g_att[BB * TT * H];
__device__ __half g_ff[BB * TT * FF];
__device__ float  g_head[BB * TT * NOUT];
__device__ float  g_pe[TT * H];
__device__ __half g_convTh[4 * H * H];
__device__ __half g_inwh[H * H];
__device__ __half g_outwh[NOUT * H];
__device__ __half g_wth[16777216];   // fp16 weights, 32 MB

#define WOFF_SAIN  0
#define WOFF_SAOUT 3145728
#define WOFF_CAIN  4194304
#define WOFF_CAOUT 7340032
#define WOFF_FF1   8388608
#define WOFF_FF2   12582912

__constant__ int PAR[NJ] = {
    -1, 0, 1, 2, 3, 1, 5, 6, 1,
    4, 9, 10, 11,  4, 13, 14, 15,  4, 17, 18, 19,  4, 21, 22, 23,  4, 25, 26, 27,
    7, 29, 30, 31, 7, 33, 34, 35,  7, 37, 38, 39,  7, 41, 42, 43,  7, 45, 46, 47,
    8
};

#define EPI_BIAS 2
#define EPI_BIAS_RES 3
#define EPI_BIAS_GELU 4
#define EPI_CONV 5

// ---------------- ptx helpers ----------------
__device__ __forceinline__ void cp16(uint32_t dst, const void* src)
{
    asm volatile("cp.async.cg.shared.global [%0], [%1], 16;\n" :: "r"(dst), "l"(src));
}
__device__ __forceinline__ void cp16z(uint32_t dst, const void* src, bool p)
{
    int sz = p ? 16 : 0;
    asm volatile("cp.async.cg.shared.global [%0], [%1], 16, %2;\n"
                 :: "r"(dst), "l"(src), "r"(sz));
}
__device__ __forceinline__ void cpcommit()
{
    asm volatile("cp.async.commit_group;\n" ::: "memory");
}
template <int W>
__device__ __forceinline__ void cpwait()
{
    asm volatile("cp.async.wait_group %0;\n" :: "n"(W) : "memory");
}
// m16n8k16 fp16 mma, fp32 accum
__device__ __forceinline__ void mma16(float* d, const uint32_t* a, const uint32_t* b)
{
    asm volatile(
        "mma.sync.aligned.m16n8k16.row.col.f32.f16.f16.f32 "
        "{%0,%1,%2,%3}, {%4,%5,%6,%7}, {%8,%9}, {%0,%1,%2,%3};\n"
        : "+f"(d[0]), "+f"(d[1]), "+f"(d[2]), "+f"(d[3])
        : "r"(a[0]), "r"(a[1]), "r"(a[2]), "r"(a[3]), "r"(b[0]), "r"(b[1]));
}
__device__ __forceinline__ void ldsm4(uint32_t* r, uint32_t addr)
{
    asm volatile("ldmatrix.sync.aligned.m8n8.x4.shared.b16 {%0,%1,%2,%3}, [%4];\n"
                 : "=r"(r[0]), "=r"(r[1]), "=r"(r[2]), "=r"(r[3]) : "r"(addr));
}
__device__ __forceinline__ void ldsm2(uint32_t* r, uint32_t addr)
{
    asm volatile("ldmatrix.sync.aligned.m8n8.x2.shared.b16 {%0,%1}, [%2];\n"
                 : "=r"(r[0]), "=r"(r[1]) : "r"(addr));
}
__device__ __forceinline__ void ldsm2t(uint32_t* r, uint32_t addr)
{
    asm volatile("ldmatrix.sync.aligned.m8n8.x2.trans.shared.b16 {%0,%1}, [%2];\n"
                 : "=r"(r[0]), "=r"(r[1]) : "r"(addr));
}

// ---------------- fp16 tensor-core GEMM: 3-stage, m16n8k16 ----------------
// C[r,c] = sum_k A[r,k] * B[c,k]; A,B fp16; accum fp32; HOUT: store half else float.
template <int EPI, bool HOUT>
__global__ void __launch_bounds__(256, 2) gemm8(
    const __half* __restrict__ A, const __half* __restrict__ Bm,
    const float* __restrict__ bias, const float* __restrict__ resid,
    void* __restrict__ C,
    int M, int N, int K, int lda, int ldb, int ldc,
    long sBh, int nh)
{
    constexpr int BM = 128, BN_ = 128, BK = 32;
    constexpr int LDE = BK + 8;               // 40 halves pitch (80 B)
    constexpr int STGH = BM * LDE * 2;        // halves per stage (A+B) = 10240
    constexpr int CH = BM * BK / 8 / 256;     // 16B chunks per thread = 2

    extern __shared__ char smc[];
    const uint32_t smu = (uint32_t)__cvta_generic_to_shared(smc);

    const int z = blockIdx.z;
    const int hh = z % nh;
    Bm += (long)hh * sBh;

    const int row0 = blockIdx.y * BM;
    const int col0 = blockIdx.x * BN_;
    const int tid = threadIdx.x;
    const int warp = tid >> 5;
    const int lane = tid & 31;
    const int wm = warp >> 2;
    const int wn = warp & 3;
    const int gid = lane >> 2;
    const int tig = lane & 3;
    const int l15 = lane & 15;
    const int l7 = lane & 7;
    const int ah = (lane >> 4) << 3;          // 0 or 8 halves
    const int bh = ((lane >> 3) & 1) << 3;    // 0 or 8 halves

    float acc[4][4][4];
#pragma unroll
    for (int i = 0; i < 4; i++)
#pragma unroll
        for (int j = 0; j < 4; j++)
#pragma unroll
            for (int q = 0; q < 4; q++) acc[i][j][q] = 0.f;

    auto cpTile = [&](int k0, int st) {
        uint32_t abase = smu + (uint32_t)(st * STGH) * 2;
#pragma unroll
        for (int l = 0; l < CH; l++) {
            int idx = l * 256 + tid;
            int r = idx >> 2;
            int cq = (idx & 3) * 8;
            cp16(abase + (uint32_t)(r * LDE + cq) * 2,
                 A + (long)(row0 + r) * lda + k0 + cq);
        }
        uint32_t bbase = abase + (uint32_t)(BM * LDE) * 2;
#pragma unroll
        for (int l = 0; l < CH; l++) {
            int idx = l * 256 + tid;
            int n = idx >> 2;
            int cq = (idx & 3) * 8;
            cp16z(bbase + (uint32_t)(n * LDE + cq) * 2,
                  Bm + (long)(col0 + n) * ldb + k0 + cq,
                  (col0 + n) < N);
        }
        cpcommit();
    };

    auto compute = [&](int st) {
        const uint32_t pAu = smu + (uint32_t)(st * STGH) * 2;
        const uint32_t pBu = pAu + (uint32_t)(BM * LDE) * 2;
#pragma unroll
        for (int ks = 0; ks < 2; ks++) {
            const int k = ks * 16;
            uint32_t af[4][4], bf[4][2];
#pragma unroll
            for (int mi = 0; mi < 4; mi++) {
                int r0 = wm * 64 + mi * 16 + l15;
                ldsm4(af[mi], pAu + (uint32_t)(r0 * LDE + k + ah) * 2);
            }
#pragma unroll
            for (int ni = 0; ni < 4; ni++) {
                int n0 = wn * 32 + ni * 8 + l7;
                ldsm2(bf[ni], pBu + (uint32_t)(n0 * LDE + k + bh) * 2);
            }
#pragma unroll
            for (int mi = 0; mi < 4; mi++)
#pragma unroll
                for (int ni = 0; ni < 4; ni++)
                    mma16(acc[mi][ni], af[mi], bf[ni]);
        }
    };

    const int nt = K / BK;
    cpTile(0, 0);
    cpTile(BK, 1);
    int st = 0;
    for (int t = 0; t < nt; t++) {
        if (t < nt - 1) cpwait<1>(); else cpwait<0>();
        __syncthreads();
        if (t + 2 < nt) {
            int st2 = st + 2; if (st2 >= 3) st2 -= 3;
            cpTile((t + 2) * BK, st2);
        }
        compute(st);
        if (++st == 3) st = 0;
    }

    auto emit = [&](int r, int c, float v) {
        v += bias[c];
        if (EPI == EPI_BIAS_GELU)
            v = 0.5f * v * (1.f + erff(v * 0.70710678118654752f));
        long idx;
        if (EPI == EPI_CONV) {
            int b_ = r >> 7;
            int s_ = r & 127;
            int t_ = s_ * 4 + hh;
            v += resid[t_ * H + c];
            idx = ((long)b_ * TT + t_) * ldc + c;
        } else {
            idx = (long)r * ldc + c;
            if (EPI == EPI_BIAS_RES) v += resid[idx];
        }
        if (HOUT) ((__half*)C)[idx] = __float2half_rn(v);
        else      ((float*)C)[idx] = v;
    };

#pragma unroll
    for (int mi = 0; mi < 4; mi++) {
        int r0 = row0 + wm * 64 + mi * 16 + gid;
#pragma unroll
        for (int ni = 0; ni < 4; ni++) {
            int c0 = col0 + wn * 32 + ni * 8 + tig * 2;
            if (c0 < N)     emit(r0,     c0,     acc[mi][ni][0]);
            if (c0 + 1 < N) emit(r0,     c0 + 1, acc[mi][ni][1]);
            if (c0 < N)     emit(r0 + 8, c0,     acc[mi][ni][2]);
            if (c0 + 1 < N) emit(r0 + 8, c0 + 1, acc[mi][ni][3]);
        }
    }
}

// ---------------- fused flash attention (fp16 MMA, fp32 softmax) ----------------
// smem byte offsets
#define FAB_Q 0
#define FAB_K 18432
#define FAB_V 36864
#define FAB_P 55296
#define FAB_RED 90112
#define FAB_M 92160
#define FAB_L 92672
#define FAB_AL 93184
#define FA_BYTES 93696

__global__ void __launch_bounds__(256, 1) fattn_k(
    const __half* __restrict__ qkv, __half* __restrict__ att)
{
    extern __shared__ char smc[];
    __half* sQ = (__half*)(smc + FAB_Q);
    __half* sP = (__half*)(smc + FAB_P);
    float* sRed = (float*)(smc + FAB_RED);
    float* sM = (float*)(smc + FAB_M);
    float* sL = (float*)(smc + FAB_L);
    float* sAl = (float*)(smc + FAB_AL);
    const uint32_t smu = (uint32_t)__cvta_generic_to_shared(smc);

    const int z = blockIdx.y;
    const int bb = z >> 3, hh = z & 7;
    const int q0 = blockIdx.x * 128;
    const long base = (long)bb * TT * 3 * H + (long)hh * DHD;   // halves

    const int tid = threadIdx.x;
    const int warp = tid >> 5, lane = tid & 31;
    const int wm = warp >> 2, wn = warp & 3;
    const int gid = lane >> 2, tig = lane & 3;
    const int l15 = lane & 15;
    const int l7 = lane & 7;
    const int ah = (lane >> 4) << 3;
    const int bh = ((lane >> 3) & 1) << 3;

    // load Q (128 x 64 halves, pitch 72)
#pragma unroll
    for (int l = 0; l < 4; l++) {
        int idx = l * 256 + tid;
        int r = idx >> 3, c8 = (idx & 7) * 8;
        cp16(smu + FAB_Q + (uint32_t)(r * 72 + c8) * 2,
             qkv + base + (long)(q0 + r) * (3 * H) + c8);
    }
    cpcommit();
    cpwait<0>();
    __syncthreads();
    // scale Q by 1/8
    {
        const __half2 s8 = __float2half2_rn(0.125f);
        __half2* q2 = (__half2*)sQ;
#pragma unroll
        for (int l = 0; l < 16; l++) {
            int idx = l * 256 + tid;      // 4096 half2
            int r = idx >> 5, c2 = idx & 31;
            q2[r * 36 + c2] = __hmul2(q2[r * 36 + c2], s8);
        }
    }
    if (tid < 128) { sM[tid] = -1e30f; sL[tid] = 0.f; }

    float oacc[4][2][4];
#pragma unroll
    for (int mi = 0; mi < 4; mi++)
#pragma unroll
        for (int ni = 0; ni < 2; ni++)
#pragma unroll
            for (int q = 0; q < 4; q++) oacc[mi][ni][q] = 0.f;

    for (int j = 0; j < 4; j++) {
        __syncthreads();
#pragma unroll
        for (int l = 0; l < 4; l++) {
            int idx = l * 256 + tid;
            int r = idx >> 3, c8 = (idx & 7) * 8;
            long row = (long)(j * 128 + r) * (3 * H);
            cp16(smu + FAB_K + (uint32_t)(r * 72 + c8) * 2, qkv + base + H + row + c8);
            cp16(smu + FAB_V + (uint32_t)(r * 72 + c8) * 2, qkv + base + 2 * H + row + c8);
        }
        cpcommit();
        cpwait<0>();
        __syncthreads();

        // ---- S = Q K^T (128x128, k=64 -> 4 ks of 16) ----
        float sacc[4][4][4];
#pragma unroll
        for (int mi = 0; mi < 4; mi++)
#pragma unroll
            for (int ni = 0; ni < 4; ni++)
#pragma unroll
                for (int q = 0; q < 4; q++) sacc[mi][ni][q] = 0.f;
#pragma unroll
        for (int ks = 0; ks < 4; ks++) {
            const int k = ks * 16;
            uint32_t af[4][4], bf[4][2];
#pragma unroll
            for (int mi = 0; mi < 4; mi++) {
                int r0 = wm * 64 + mi * 16 + l15;
                ldsm4(af[mi], smu + FAB_Q + (uint32_t)(r0 * 72 + k + ah) * 2);
            }
#pragma unroll
            for (int ni = 0; ni < 4; ni++) {
                int n0 = wn * 32 + ni * 8 + l7;
                ldsm2(bf[ni], smu + FAB_K + (uint32_t)(n0 * 72 + k + bh) * 2);
            }
#pragma unroll
            for (int mi = 0; mi < 4; mi++)
#pragma unroll
                for (int ni = 0; ni < 4; ni++)
                    mma16(sacc[mi][ni], af[mi], bf[ni]);
        }

        // ---- row max ----
#pragma unroll
        for (int mi = 0; mi < 4; mi++) {
            float r0m = -1e30f, r1m = -1e30f;
#pragma unroll
            for (int ni = 0; ni < 4; ni++) {
                r0m = fmaxf(r0m, fmaxf(sacc[mi][ni][0], sacc[mi][ni][1]));
                r1m = fmaxf(r1m, fmaxf(sacc[mi][ni][2], sacc[mi][ni][3]));
            }
            r0m = fmaxf(r0m, __shfl_xor_sync(0xffffffffu, r0m, 1));
            r0m = fmaxf(r0m, __shfl_xor_sync(0xffffffffu, r0m, 2));
            r1m = fmaxf(r1m, __shfl_xor_sync(0xffffffffu, r1m, 1));
            r1m = fmaxf(r1m, __shfl_xor_sync(0xffffffffu, r1m, 2));
            if (tig == 0) {
                int r0 = wm * 64 + mi * 16 + gid;
                sRed[wn * 128 + r0] = r0m;
                sRed[wn * 128 + r0 + 8] = r1m;
            }
        }
        __syncthreads();
        if (tid < 128) {
            float mt = fmaxf(fmaxf(sRed[tid], sRed[128 + tid]),
                             fmaxf(sRed[256 + tid], sRed[384 + tid]));
            float mo = sM[tid];
            float mn = fmaxf(mo, mt);
            sAl[tid] = __expf(mo - mn);
            sM[tid] = mn;
        }
        __syncthreads();

        // ---- P = exp(S-m), rowsum, store P half ----
#pragma unroll
        for (int mi = 0; mi < 4; mi++) {
            int r0 = wm * 64 + mi * 16 + gid;
            float m0 = sM[r0], m1 = sM[r0 + 8];
            float rs0 = 0.f, rs1 = 0.f;
#pragma unroll
            for (int ni = 0; ni < 4; ni++) {
                int c0 = wn * 32 + ni * 8 + tig * 2;
                float p00 = __expf(sacc[mi][ni][0] - m0);
                float p01 = __expf(sacc[mi][ni][1] - m0);
                float p10 = __expf(sacc[mi][ni][2] - m1);
                float p11 = __expf(sacc[mi][ni][3] - m1);
                rs0 += p00 + p01;
                rs1 += p10 + p11;
                *(__half2*)&sP[r0 * 136 + c0] = __floats2half2_rn(p00, p01);
                *(__half2*)&sP[(r0 + 8) * 136 + c0] = __floats2half2_rn(p10, p11);
            }
            rs0 += __shfl_xor_sync(0xffffffffu, rs0, 1);
            rs0 += __shfl_xor_sync(0xffffffffu, rs0, 2);
            rs1 += __shfl_xor_sync(0xffffffffu, rs1, 1);
            rs1 += __shfl_xor_sync(0xffffffffu, rs1, 2);
            if (tig == 0) {
                sRed[wn * 128 + r0] = rs0;
                sRed[wn * 128 + r0 + 8] = rs1;
            }
        }
        __syncthreads();
        if (tid < 128) {
            sL[tid] = sL[tid] * sAl[tid] +
                      (sRed[tid] + sRed[128 + tid]) + (sRed[256 + tid] + sRed[384 + tid]);
        }

        // ---- rescale O ----
#pragma unroll
        for (int mi = 0; mi < 4; mi++) {
            int r0 = wm * 64 + mi * 16 + gid;
            float a0 = sAl[r0], a1 = sAl[r0 + 8];
#pragma unroll
            for (int ni = 0; ni < 2; ni++) {
                oacc[mi][ni][0] *= a0;
                oacc[mi][ni][1] *= a0;
                oacc[mi][ni][2] *= a1;
                oacc[mi][ni][3] *= a1;
            }
        }

        // ---- O += P @ V (128x64, k=128 -> 8 ks of 16); V via ldmatrix.trans ----
#pragma unroll
        for (int ks = 0; ks < 8; ks++) {
            const int k = ks * 16;
            uint32_t af[4][4], bf[2][2];
#pragma unroll
            for (int mi = 0; mi < 4; mi++) {
                int r0 = wm * 64 + mi * 16 + l15;
                ldsm4(af[mi], smu + FAB_P + (uint32_t)(r0 * 136 + k + ah) * 2);
            }
#pragma unroll
            for (int ni = 0; ni < 2; ni++) {
                int n0 = wn * 16 + ni * 8;
                ldsm2t(bf[ni], smu + FAB_V + (uint32_t)((k + l15) * 72 + n0) * 2);
            }
#pragma unroll
            for (int mi = 0; mi < 4; mi++)
#pragma unroll
                for (int ni = 0; ni < 2; ni++)
                    mma16(oacc[mi][ni], af[mi], bf[ni]);
        }
    }
    __syncthreads();

    // ---- O /= l, write half ----
#pragma unroll
    for (int mi = 0; mi < 4; mi++) {
        int r0 = wm * 64 + mi * 16 + gid;
        float i0 = 1.f / sL[r0], i1 = 1.f / sL[r0 + 8];
        long o0 = ((long)bb * TT + q0 + r0) * H + hh * DHD;
        long o1 = ((long)bb * TT + q0 + r0 + 8) * H + hh * DHD;
#pragma unroll
        for (int ni = 0; ni < 2; ni++) {
            int c0 = wn * 16 + ni * 8 + tig * 2;
            *(__half2*)&att[o0 + c0] = __floats2half2_rn(oacc[mi][ni][0] * i0, oacc[mi][ni][1] * i0);
            *(__half2*)&att[o1 + c0] = __floats2half2_rn(oacc[mi][ni][2] * i1, oacc[mi][ni][3] * i1);
        }
    }
}

// ---------------- LayerNorm: fp32 in, fp16 out ----------------
__global__ void ln_k(const float* __restrict__ x, const float* __restrict__ g,
                     const float* __restrict__ b, __half* __restrict__ o)
{
    long row = blockIdx.x;
    int t = threadIdx.x;
    float4 v = ((const float4*)(x + row * H))[t];
    float s = v.x + v.y + v.z + v.w;
    float ss = v.x * v.x + v.y * v.y + v.z * v.z + v.w * v.w;
#pragma unroll
    for (int off = 16; off; off >>= 1) {
        s += __shfl_xor_sync(0xffffffffu, s, off);
        ss += __shfl_xor_sync(0xffffffffu, ss, off);
    }
    __shared__ float sm0[4], sm1[4];
    int w = t >> 5;
    if ((t & 31) == 0) { sm0[w] = s; sm1[w] = ss; }
    __syncthreads();
    s = sm0[0] + sm0[1] + sm0[2] + sm0[3];
    ss = sm1[0] + sm1[1] + sm1[2] + sm1[3];
    float mean = s * (1.f / H);
    float var = ss * (1.f / H) - mean * mean;
    float rstd = rsqrtf(var + 1e-5f);
    float4 gg = ((const float4*)g)[t];
    float4 bb4 = ((const float4*)b)[t];
    __half2* op = (__half2*)(o + row * H);
    op[t * 2]     = __floats2half2_rn((v.x - mean) * rstd * gg.x + bb4.x,
                                      (v.y - mean) * rstd * gg.y + bb4.y);
    op[t * 2 + 1] = __floats2half2_rn((v.z - mean) * rstd * gg.z + bb4.z,
                                      (v.w - mean) * rstd * gg.w + bb4.w);
}

// ---------------- misc kernels ----------------
__global__ void cvth_k(const float* __restrict__ in, __half* __restrict__ out, int n4)
{
    int i = blockIdx.x * blockDim.x + threadIdx.x;
    if (i >= n4) return;
    float4 v = ((const float4*)in)[i];
    ((__half2*)out)[i * 2]     = __floats2half2_rn(v.x, v.y);
    ((__half2*)out)[i * 2 + 1] = __floats2half2_rn(v.z, v.w);
}

__global__ void pe_k(float* __restrict__ pe)
{
    int t = blockIdx.x;
    int i = threadIdx.x;
    float div = expf(-(float)(2 * i) * (logf(10000.f) / (float)H));
    float a = (float)t * div;
    pe[t * H + 2 * i] = sinf(a);
    pe[t * H + 2 * i + 1] = cosf(a);
}

__global__ void convT_k(const float* __restrict__ w, __half* __restrict__ o)
{
    int idx = blockIdx.x * blockDim.x + threadIdx.x;
    if (idx >= 4 * H * H) return;
    int k = idx / (H * H);
    int d = (idx / H) % H;
    int c = idx % H;
    o[idx] = __float2half_rn(w[c * H * 4 + d * 4 + k]);
}

__global__ void xinit_k(const float* __restrict__ qe, const float* __restrict__ pe,
                        float* __restrict__ x)
{
    long i = blockIdx.x * (long)blockDim.x + threadIdx.x;
    if (i >= (long)BB * TT * H) return;
    int td = (int)(i % (TT * H));
    x[i] = qe[td] + pe[td];
}

__global__ void kin_k(const float* __restrict__ ho, float* __restrict__ out)
{
    int row = blockIdx.x * blockDim.x + threadIdx.x;
    if (row >= BB * TT) return;
    const float* r = ho + (long)row * NOUT;
    float* o = out + (long)row * (3 * NJ);
    float gx[NJ], px[NJ], py[NJ];
    gx[0] = 0.f;
    px[0] = r[100];
    py[0] = r[101];
    o[0] = px[0]; o[1] = py[0]; o[2] = 1.f;
    for (int j = 1; j < NJ; j++) {
        int pa = PAR[j];
        float gg = gx[pa] + r[j];
        gx[j] = gg;
        float s = r[50 + j];
        float sn, cs;
        sincosf(gg, &sn, &cs);
        px[j] = px[pa] + cs * s;
        py[j] = py[pa] + sn * s;
        o[j * 3 + 0] = px[j];
        o[j * 3 + 1] = py[j];
        o[j * 3 + 2] = 1.f;
    }
}

// ---------------- launcher ----------------
static inline dim3 gg128(int M, int N, int bz = 1)
{
    return dim3((N + 127) / 128, (M + 127) / 128, bz);
}

#define SMEM_G8 61440    // 3 stages x 20480 B

extern "C" void kernel_launch(void* const* d_in, const int* in_sizes, int n_in,
                              void* d_out, int out_size)
{
    const float* memory   = (const float*)d_in[0];
    const float* in_w     = (const float*)d_in[1];
    const float* in_b     = (const float*)d_in[2];
    const float* conv_w   = (const float*)d_in[3];
    const float* conv_b   = (const float*)d_in[4];
    const float* qemb     = (const float*)d_in[5];
    const float* sa_in_w  = (const float*)d_in[6];
    const float* sa_in_b  = (const float*)d_in[7];
    const float* sa_out_w = (const float*)d_in[8];
    const float* sa_out_b = (const float*)d_in[9];
    const float* ca_in_w  = (const float*)d_in[10];
    const float* ca_in_b  = (const float*)d_in[11];
    const float* ca_out_w = (const float*)d_in[12];
    const float* ca_out_b = (const float*)d_in[13];
    const float* ln1_g    = (const float*)d_in[14];
    const float* ln1_b    = (const float*)d_in[15];
    const float* ln2_g    = (const float*)d_in[16];
    const float* ln2_b    = (const float*)d_in[17];
    const float* ln3_g    = (const float*)d_in[18];
    const float* ln3_b    = (const float*)d_in[19];
    const float* ff1_w    = (const float*)d_in[20];
    const float* ff1_b    = (const float*)d_in[21];
    const float* ff2_w    = (const float*)d_in[22];
    const float* ff2_b    = (const float*)d_in[23];
    const float* out_w    = (const float*)d_in[24];
    const float* out_b    = (const float*)d_in[25];

    __half *memh_, *m_, *mem_, *xh_, *h_, *qkv_, *att_, *ff_, *cT_, *inwh_, *outwh_, *wt_;
    float *x_, *ho_, *pe_;
    cudaGetSymbolAddress((void**)&memh_, g_memh);
    cudaGetSymbolAddress((void**)&m_,    g_m);
    cudaGetSymbolAddress((void**)&mem_,  g_mem);
    cudaGetSymbolAddress((void**)&x_,    g_x);
    cudaGetSymbolAddress((void**)&xh_,   g_xh);
    cudaGetSymbolAddress((void**)&h_,    g_h);
    cudaGetSymbolAddress((void**)&qkv_,  g_qkv);
    cudaGetSymbolAddress((void**)&att_,  g_att);
    cudaGetSymbolAddress((void**)&ff_,   g_ff);
    cudaGetSymbolAddress((void**)&ho_,   g_head);
    cudaGetSymbolAddress((void**)&pe_,   g_pe);
    cudaGetSymbolAddress((void**)&cT_,   g_convTh);
    cudaGetSymbolAddress((void**)&inwh_, g_inwh);
    cudaGetSymbolAddress((void**)&outwh_,g_outwh);
    cudaGetSymbolAddress((void**)&wt_,   g_wth);

    cudaFuncSetAttribute(gemm8<EPI_BIAS,      true >, cudaFuncAttributeMaxDynamicSharedMemorySize, SMEM_G8);
    cudaFuncSetAttribute(gemm8<EPI_CONV,      true >, cudaFuncAttributeMaxDynamicSharedMemorySize, SMEM_G8);
    cudaFuncSetAttribute(gemm8<EPI_BIAS_RES,  false>, cudaFuncAttributeMaxDynamicSharedMemorySize, SMEM_G8);
    cudaFuncSetAttribute(gemm8<EPI_BIAS_GELU, true >, cudaFuncAttributeMaxDynamicSharedMemorySize, SMEM_G8);
    cudaFuncSetAttribute(gemm8<EPI_BIAS,      false>, cudaFuncAttributeMaxDynamicSharedMemorySize, SMEM_G8);
    cudaFuncSetAttribute(fattn_k, cudaFuncAttributeMaxDynamicSharedMemorySize, FA_BYTES);

    // prep
    pe_k<<<TT, 256>>>(pe_);
    convT_k<<<(4 * H * H + 255) / 256, 256>>>(conv_w, cT_);
    cvth_k<<<(2097152 / 4 + 255) / 256, 256>>>(memory,   memh_,  2097152 / 4);
    cvth_k<<<(262144 / 4 + 255) / 256, 256>>>(in_w,      inwh_,  262144 / 4);
    cvth_k<<<(52224 / 4 + 255) / 256, 256>>>(out_w,      outwh_, 52224 / 4);
    cvth_k<<<(3145728 / 4 + 255) / 256, 256>>>(sa_in_w,  wt_ + WOFF_SAIN,  3145728 / 4);
    cvth_k<<<(1048576 / 4 + 255) / 256, 256>>>(sa_out_w, wt_ + WOFF_SAOUT, 1048576 / 4);
    cvth_k<<<(3145728 / 4 + 255) / 256, 256>>>(ca_in_w,  wt_ + WOFF_CAIN,  3145728 / 4);
    cvth_k<<<(1048576 / 4 + 255) / 256, 256>>>(ca_out_w, wt_ + WOFF_CAOUT, 1048576 / 4);
    cvth_k<<<(4194304 / 4 + 255) / 256, 256>>>(ff1_w,    wt_ + WOFF_FF1,   4194304 / 4);
    cvth_k<<<(4194304 / 4 + 255) / 256, 256>>>(ff2_w,    wt_ + WOFF_FF2,   4194304 / 4);

    // m = memory @ in_w^T + in_b
    gemm8<EPI_BIAS, true><<<gg128(BB * SS, H), 256, SMEM_G8>>>(
        memh_, inwh_, in_b, nullptr, m_,
        BB * SS, H, H, H, H, H, 0L, 1);

    // conv upsample (4 taps batched over z; tap = hh)
    gemm8<EPI_CONV, true><<<gg128(BB * SS, H, 4), 256, SMEM_G8>>>(
        m_, cT_, conv_b, pe_, mem_,
        BB * SS, H, H, H, H, H, (long)H * H, 4);

    xinit_k<<<(BB * TT * H + 255) / 256, 256>>>(qemb, pe_, x_);

    const dim3 fa_grid(TT / 128, BB * NHEAD);

    for (int l = 0; l < NL; l++) {
        // ======== self-attention ========
        ln_k<<<BB * TT, 128>>>(x_, ln1_g + l * H, ln1_b + l * H, h_);
        gemm8<EPI_BIAS, true><<<gg128(BB * TT, 3 * H), 256, SMEM_G8>>>(
            h_, wt_ + WOFF_SAIN + (long)l * 3 * H * H, sa_in_b + (long)l * 3 * H, nullptr, qkv_,
            BB * TT, 3 * H, H, H, H, 3 * H, 0L, 1);
        fattn_k<<<fa_grid, 256, FA_BYTES>>>(qkv_, att_);
        gemm8<EPI_BIAS_RES, false><<<gg128(BB * TT, H), 256, SMEM_G8>>>(
            att_, wt_ + WOFF_SAOUT + (long)l * H * H, sa_out_b + (long)l * H, x_, x_,
            BB * TT, H, H, H, H, H, 0L, 1);

        // ======== cross-attention ========
        ln_k<<<BB * TT, 128>>>(x_, ln2_g + l * H, ln2_b + l * H, h_);
        gemm8<EPI_BIAS, true><<<gg128(BB * TT, H), 256, SMEM_G8>>>(
            h_, wt_ + WOFF_CAIN + (long)l * 3 * H * H, ca_in_b + (long)l * 3 * H, nullptr, qkv_,
            BB * TT, H, H, H, H, 3 * H, 0L, 1);
        gemm8<EPI_BIAS, true><<<gg128(BB * TT, 2 * H), 256, SMEM_G8>>>(
            mem_, wt_ + WOFF_CAIN + (long)l * 3 * H * H + (long)H * H,
            ca_in_b + (long)l * 3 * H + H, nullptr, qkv_ + H,
            BB * TT, 2 * H, H, H, H, 3 * H, 0L, 1);
        fattn_k<<<fa_grid, 256, FA_BYTES>>>(qkv_, att_);
        gemm8<EPI_BIAS_RES, false><<<gg128(BB * TT, H), 256, SMEM_G8>>>(
            att_, wt_ + WOFF_CAOUT + (long)l * H * H, ca_out_b + (long)l * H, x_, x_,
            BB * TT, H, H, H, H, H, 0L, 1);

        // ======== FFN ========
        ln_k<<<BB * TT, 128>>>(x_, ln3_g + l * H, ln3_b + l * H, h_);
        gemm8<EPI_BIAS_GELU, true><<<gg128(BB * TT, FF), 256, SMEM_G8>>>(
            h_, wt_ + WOFF_FF1 + (long)l * FF * H, ff1_b + (long)l * FF, nullptr, ff_,
            BB * TT, FF, H, H, H, FF, 0L, 1);
        gemm8<EPI_BIAS_RES, false><<<gg128(BB * TT, H), 256, SMEM_G8>>>(
            ff_, wt_ + WOFF_FF2 + (long)l * H * FF, ff2_b + (long)l * H, x_, x_,
            BB * TT, H, FF, FF, FF, H, 0L, 1);
    }

    // head
    cvth_k<<<(16777216 / 4 + 255) / 256, 256>>>(x_, xh_, 16777216 / 4);
    gemm8<EPI_BIAS, false><<<gg128(BB * TT, NOUT), 256, SMEM_G8>>>(
        xh_, outwh_, out_b, nullptr, ho_,
        BB * TT, NOUT, H, H, H, NOUT, 0L, 1);

    kin_k<<<(BB * TT + 255) / 256, 256>>>(ho_, (float*)d_out);
}

// round 11
// speedup vs baseline: 2.2353x; 1.1637x over previous
#include <cuda_runtime.h>
#include <cuda_fp16.h>
#include <math.h>
#include <stdint.h>

#define H 512
#define BB 32
#define SS 128
#define TT 512
#define NHEAD 8
#define DHD 64
#define NL 4
#define FF 2048
#define NOUT 102
#define NJ 50

// ---------------- scratch ----------------
__device__ __half g_memh[BB * SS * H];
__device__ __half g_m[BB * SS * H];
__device__ __half g_mem[BB * TT * H];
__device__ float  g_x[BB * TT * H];
__device__ __half g_xh[BB * TT * H];
__device__ __half g_h[BB * TT * H];
__device__ __half g_qkv[BB * TT * 3 * H];
__device__ __half g_att[BB * TT * H];
__device__ __half g_ff[BB * TT * FF];
__device__ float  g_head[BB * TT * NOUT];
__device__ float  g_pe[TT * H];
__device__ __half g_convTh[4 * H * H];
__device__ __half g_inwh[H * H];
__device__ __half g_outwh[NOUT * H];
__device__ __half g_wth[16777216];

#define WOFF_SAIN  0
#define WOFF_SAOUT 3145728
#define WOFF_CAIN  4194304
#define WOFF_CAOUT 7340032
#define WOFF_FF1   8388608
#define WOFF_FF2   12582912

__constant__ int PAR[NJ] = {
    -1, 0, 1, 2, 3, 1, 5, 6, 1,
    4, 9, 10, 11,  4, 13, 14, 15,  4, 17, 18, 19,  4, 21, 22, 23,  4, 25, 26, 27,
    7, 29, 30, 31, 7, 33, 34, 35,  7, 37, 38, 39,  7, 41, 42, 43,  7, 45, 46, 47,
    8
};

#define EPI_BIAS 2
#define EPI_BIAS_RES 3
#define EPI_BIAS_GELU 4
#define EPI_CONV 5

// ---------------- ptx helpers ----------------
__device__ __forceinline__ void cp16(uint32_t dst, const void* src)
{
    asm volatile("cp.async.cg.shared.global [%0], [%1], 16;\n" :: "r"(dst), "l"(src));
}
__device__ __forceinline__ void cp16z(uint32_t dst, const void* src, bool p)
{
    int sz = p ? 16 : 0;
    asm volatile("cp.async.cg.shared.global [%0], [%1], 16, %2;\n"
                 :: "r"(dst), "l"(src), "r"(sz));
}
__device__ __forceinline__ void cpcommit()
{
    asm volatile("cp.async.commit_group;\n" ::: "memory");
}
template <int W>
__device__ __forceinline__ void cpwait()
{
    asm volatile("cp.async.wait_group %0;\n" :: "n"(W) : "memory");
}
__device__ __forceinline__ void mma16(float* d, const uint32_t* a, const uint32_t* b)
{
    asm volatile(
        "mma.sync.aligned.m16n8k16.row.col.f32.f16.f16.f32 "
        "{%0,%1,%2,%3}, {%4,%5,%6,%7}, {%8,%9}, {%0,%1,%2,%3};\n"
        : "+f"(d[0]), "+f"(d[1]), "+f"(d[2]), "+f"(d[3])
        : "r"(a[0]), "r"(a[1]), "r"(a[2]), "r"(a[3]), "r"(b[0]), "r"(b[1]));
}
__device__ __forceinline__ void ldsm4(uint32_t* r, uint32_t addr)
{
    asm volatile("ldmatrix.sync.aligned.m8n8.x4.shared.b16 {%0,%1,%2,%3}, [%4];\n"
                 : "=r"(r[0]), "=r"(r[1]), "=r"(r[2]), "=r"(r[3]) : "r"(addr));
}
__device__ __forceinline__ void ldsm2t(uint32_t* r, uint32_t addr)
{
    asm volatile("ldmatrix.sync.aligned.m8n8.x2.trans.shared.b16 {%0,%1}, [%2];\n"
                 : "=r"(r[0]), "=r"(r[1]) : "r"(addr));
}

// ---------------- fp16 tensor-core GEMM: 3-stage, m16n8k16 ----------------
// C[r,c] = sum_k A[r,k] * B[c,k]; QS: scale cols < H by 1/8 (for q projections).
template <int EPI, bool HOUT, bool QS>
__global__ void __launch_bounds__(256, 2) gemm8(
    const __half* __restrict__ A, const __half* __restrict__ Bm,
    const float* __restrict__ bias, const float* __restrict__ resid,
    void* __restrict__ C,
    int M, int N, int K, int lda, int ldb, int ldc,
    long sBh, int nh)
{
    constexpr int BM = 128, BN_ = 128, BK = 32;
    constexpr int LDE = BK + 8;               // 40 halves pitch
    constexpr int STGH = BM * LDE * 2;        // halves per stage (A+B)
    constexpr int CH = BM * BK / 8 / 256;     // 2

    extern __shared__ char smc[];
    const uint32_t smu = (uint32_t)__cvta_generic_to_shared(smc);

    const int z = blockIdx.z;
    const int hh = z % nh;
    Bm += (long)hh * sBh;

    const int row0 = blockIdx.y * BM;
    const int col0 = blockIdx.x * BN_;
    const int tid = threadIdx.x;
    const int warp = tid >> 5;
    const int lane = tid & 31;
    const int wm = warp >> 2;
    const int wn = warp & 3;
    const int gid = lane >> 2;
    const int tig = lane & 3;
    const int l15 = lane & 15;
    const int ah = (lane >> 4) << 3;          // 0 or 8 halves (k-half select)

    float acc[4][4][4];
#pragma unroll
    for (int i = 0; i < 4; i++)
#pragma unroll
        for (int j = 0; j < 4; j++)
#pragma unroll
            for (int q = 0; q < 4; q++) acc[i][j][q] = 0.f;

    auto cpTile = [&](int k0, int st) {
        uint32_t abase = smu + (uint32_t)(st * STGH) * 2;
#pragma unroll
        for (int l = 0; l < CH; l++) {
            int idx = l * 256 + tid;
            int r = idx >> 2;
            int cq = (idx & 3) * 8;
            cp16(abase + (uint32_t)(r * LDE + cq) * 2,
                 A + (long)(row0 + r) * lda + k0 + cq);
        }
        uint32_t bbase = abase + (uint32_t)(BM * LDE) * 2;
#pragma unroll
        for (int l = 0; l < CH; l++) {
            int idx = l * 256 + tid;
            int n = idx >> 2;
            int cq = (idx & 3) * 8;
            cp16z(bbase + (uint32_t)(n * LDE + cq) * 2,
                  Bm + (long)(col0 + n) * ldb + k0 + cq,
                  (col0 + n) < N);
        }
        cpcommit();
    };

    auto compute = [&](int st) {
        const uint32_t pAu = smu + (uint32_t)(st * STGH) * 2;
        const uint32_t pBu = pAu + (uint32_t)(BM * LDE) * 2;
#pragma unroll
        for (int ks = 0; ks < 2; ks++) {
            const int k = ks * 16;
            uint32_t af[4][4], bf[4][2];
#pragma unroll
            for (int mi = 0; mi < 4; mi++) {
                int r0 = wm * 64 + mi * 16 + l15;
                ldsm4(af[mi], pAu + (uint32_t)(r0 * LDE + k + ah) * 2);
            }
#pragma unroll
            for (int pb = 0; pb < 2; pb++) {
                uint32_t q[4];
                int n0 = wn * 32 + pb * 16 + l15;
                ldsm4(q, pBu + (uint32_t)(n0 * LDE + k + ah) * 2);
                bf[pb * 2][0] = q[0];     bf[pb * 2][1] = q[2];
                bf[pb * 2 + 1][0] = q[1]; bf[pb * 2 + 1][1] = q[3];
            }
#pragma unroll
            for (int mi = 0; mi < 4; mi++)
#pragma unroll
                for (int ni = 0; ni < 4; ni++)
                    mma16(acc[mi][ni], af[mi], bf[ni]);
        }
    };

    const int nt = K / BK;
    cpTile(0, 0);
    cpTile(BK, 1);
    int st = 0;
    for (int t = 0; t < nt; t++) {
        if (t < nt - 1) cpwait<1>(); else cpwait<0>();
        __syncthreads();
        if (t + 2 < nt) {
            int st2 = st + 2; if (st2 >= 3) st2 -= 3;
            cpTile((t + 2) * BK, st2);
        }
        compute(st);
        if (++st == 3) st = 0;
    }

    auto emit2 = [&](int r, int c, float v0, float v1) {
        v0 += bias[c];
        v1 += bias[c + 1];
        if (QS && c < H) { v0 *= 0.125f; v1 *= 0.125f; }
        if (EPI == EPI_BIAS_GELU) {
            v0 = 0.5f * v0 * (1.f + erff(v0 * 0.70710678118654752f));
            v1 = 0.5f * v1 * (1.f + erff(v1 * 0.70710678118654752f));
        }
        long idx;
        if (EPI == EPI_CONV) {
            int b_ = r >> 7;
            int s_ = r & 127;
            int t_ = s_ * 4 + hh;
            float2 rv = *(const float2*)&resid[t_ * H + c];
            v0 += rv.x; v1 += rv.y;
            idx = ((long)b_ * TT + t_) * ldc + c;
        } else {
            idx = (long)r * ldc + c;
            if (EPI == EPI_BIAS_RES) {
                float2 rv = *(const float2*)&resid[idx];
                v0 += rv.x; v1 += rv.y;
            }
        }
        if (HOUT) *(__half2*)((__half*)C + idx) = __floats2half2_rn(v0, v1);
        else      *(float2*)((float*)C + idx) = make_float2(v0, v1);
    };

#pragma unroll
    for (int mi = 0; mi < 4; mi++) {
        int r0 = row0 + wm * 64 + mi * 16 + gid;
#pragma unroll
        for (int ni = 0; ni < 4; ni++) {
            int c0 = col0 + wn * 32 + ni * 8 + tig * 2;
            if (c0 < N) {
                emit2(r0,     c0, acc[mi][ni][0], acc[mi][ni][1]);
                emit2(r0 + 8, c0, acc[mi][ni][2], acc[mi][ni][3]);
            }
        }
    }
}

// ---------------- fused flash attention (fp16 MMA, KV double-buffered) ----------------
// q arrives pre-scaled by 1/8 from the q projection GEMM.
#define FAB_Q 0
#define FAB_K0 18432
#define FAB_V0 55296
#define FAB_KVS 18432     // stride between KV stage buffers
#define FAB_P 92160
#define FAB_RED 126976
#define FAB_M 129024
#define FAB_L 129536
#define FAB_AL 130048
#define FA_BYTES 130560

__global__ void __launch_bounds__(256, 1) fattn_k(
    const __half* __restrict__ qkv, __half* __restrict__ att)
{
    extern __shared__ char smc[];
    __half* sP = (__half*)(smc + FAB_P);
    float* sRed = (float*)(smc + FAB_RED);
    float* sM = (float*)(smc + FAB_M);
    float* sL = (float*)(smc + FAB_L);
    float* sAl = (float*)(smc + FAB_AL);
    const uint32_t smu = (uint32_t)__cvta_generic_to_shared(smc);

    const int z = blockIdx.y;
    const int bb = z >> 3, hh = z & 7;
    const int q0 = blockIdx.x * 128;
    const long base = (long)bb * TT * 3 * H + (long)hh * DHD;

    const int tid = threadIdx.x;
    const int warp = tid >> 5, lane = tid & 31;
    const int wm = warp >> 2, wn = warp & 3;
    const int gid = lane >> 2, tig = lane & 3;
    const int l15 = lane & 15;
    const int ah = (lane >> 4) << 3;

    // load Q (128 x 64 halves, pitch 72)
#pragma unroll
    for (int l = 0; l < 4; l++) {
        int idx = l * 256 + tid;
        int r = idx >> 3, c8 = (idx & 7) * 8;
        cp16(smu + FAB_Q + (uint32_t)(r * 72 + c8) * 2,
             qkv + base + (long)(q0 + r) * (3 * H) + c8);
    }
    cpcommit();
    // load KV tile 0 into stage 0
#pragma unroll
    for (int l = 0; l < 4; l++) {
        int idx = l * 256 + tid;
        int r = idx >> 3, c8 = (idx & 7) * 8;
        long row = (long)r * (3 * H);
        cp16(smu + FAB_K0 + (uint32_t)(r * 72 + c8) * 2, qkv + base + H + row + c8);
        cp16(smu + FAB_V0 + (uint32_t)(r * 72 + c8) * 2, qkv + base + 2 * H + row + c8);
    }
    cpcommit();
    cpwait<1>();   // Q retired; KV0 may be in flight

    if (tid < 128) { sM[tid] = -1e30f; sL[tid] = 0.f; }

    float oacc[4][2][4];
#pragma unroll
    for (int mi = 0; mi < 4; mi++)
#pragma unroll
        for (int ni = 0; ni < 2; ni++)
#pragma unroll
            for (int q = 0; q < 4; q++) oacc[mi][ni][q] = 0.f;

    for (int j = 0; j < 4; j++) {
        __syncthreads();   // prior reads of the prefetch-target buffer are done
        if (j < 3) {
            const uint32_t dK = smu + FAB_K0 + (uint32_t)(((j + 1) & 1) * FAB_KVS);
            const uint32_t dV = smu + FAB_V0 + (uint32_t)(((j + 1) & 1) * FAB_KVS);
#pragma unroll
            for (int l = 0; l < 4; l++) {
                int idx = l * 256 + tid;
                int r = idx >> 3, c8 = (idx & 7) * 8;
                long row = (long)((j + 1) * 128 + r) * (3 * H);
                cp16(dK + (uint32_t)(r * 72 + c8) * 2, qkv + base + H + row + c8);
                cp16(dV + (uint32_t)(r * 72 + c8) * 2, qkv + base + 2 * H + row + c8);
            }
            cpcommit();
            cpwait<1>();   // current tile j resident; j+1 in flight
        } else {
            cpwait<0>();
        }
        __syncthreads();

        const uint32_t KB = smu + FAB_K0 + (uint32_t)((j & 1) * FAB_KVS);
        const uint32_t VB = smu + FAB_V0 + (uint32_t)((j & 1) * FAB_KVS);

        // ---- S = Q K^T (128x128, k=64) ----
        float sacc[4][4][4];
#pragma unroll
        for (int mi = 0; mi < 4; mi++)
#pragma unroll
            for (int ni = 0; ni < 4; ni++)
#pragma unroll
                for (int q = 0; q < 4; q++) sacc[mi][ni][q] = 0.f;
#pragma unroll
        for (int ks = 0; ks < 4; ks++) {
            const int k = ks * 16;
            uint32_t af[4][4], bf[4][2];
#pragma unroll
            for (int mi = 0; mi < 4; mi++) {
                int r0 = wm * 64 + mi * 16 + l15;
                ldsm4(af[mi], smu + FAB_Q + (uint32_t)(r0 * 72 + k + ah) * 2);
            }
#pragma unroll
            for (int pb = 0; pb < 2; pb++) {
                uint32_t q[4];
                int n0 = wn * 32 + pb * 16 + l15;
                ldsm4(q, KB + (uint32_t)(n0 * 72 + k + ah) * 2);
                bf[pb * 2][0] = q[0];     bf[pb * 2][1] = q[2];
                bf[pb * 2 + 1][0] = q[1]; bf[pb * 2 + 1][1] = q[3];
            }
#pragma unroll
            for (int mi = 0; mi < 4; mi++)
#pragma unroll
                for (int ni = 0; ni < 4; ni++)
                    mma16(sacc[mi][ni], af[mi], bf[ni]);
        }

        // ---- row max ----
#pragma unroll
        for (int mi = 0; mi < 4; mi++) {
            float r0m = -1e30f, r1m = -1e30f;
#pragma unroll
            for (int ni = 0; ni < 4; ni++) {
                r0m = fmaxf(r0m, fmaxf(sacc[mi][ni][0], sacc[mi][ni][1]));
                r1m = fmaxf(r1m, fmaxf(sacc[mi][ni][2], sacc[mi][ni][3]));
            }
            r0m = fmaxf(r0m, __shfl_xor_sync(0xffffffffu, r0m, 1));
            r0m = fmaxf(r0m, __shfl_xor_sync(0xffffffffu, r0m, 2));
            r1m = fmaxf(r1m, __shfl_xor_sync(0xffffffffu, r1m, 1));
            r1m = fmaxf(r1m, __shfl_xor_sync(0xffffffffu, r1m, 2));
            if (tig == 0) {
                int r0 = wm * 64 + mi * 16 + gid;
                sRed[wn * 128 + r0] = r0m;
                sRed[wn * 128 + r0 + 8] = r1m;
            }
        }
        __syncthreads();
        if (tid < 128) {
            float mt = fmaxf(fmaxf(sRed[tid], sRed[128 + tid]),
                             fmaxf(sRed[256 + tid], sRed[384 + tid]));
            float mo = sM[tid];
            float mn = fmaxf(mo, mt);
            sAl[tid] = __expf(mo - mn);
            sM[tid] = mn;
        }
        __syncthreads();

        // ---- P = exp(S-m), rowsum, store P half ----
#pragma unroll
        for (int mi = 0; mi < 4; mi++) {
            int r0 = wm * 64 + mi * 16 + gid;
            float m0 = sM[r0], m1 = sM[r0 + 8];
            float rs0 = 0.f, rs1 = 0.f;
#pragma unroll
            for (int ni = 0; ni < 4; ni++) {
                int c0 = wn * 32 + ni * 8 + tig * 2;
                float p00 = __expf(sacc[mi][ni][0] - m0);
                float p01 = __expf(sacc[mi][ni][1] - m0);
                float p10 = __expf(sacc[mi][ni][2] - m1);
                float p11 = __expf(sacc[mi][ni][3] - m1);
                rs0 += p00 + p01;
                rs1 += p10 + p11;
                *(__half2*)&sP[r0 * 136 + c0] = __floats2half2_rn(p00, p01);
                *(__half2*)&sP[(r0 + 8) * 136 + c0] = __floats2half2_rn(p10, p11);
            }
            rs0 += __shfl_xor_sync(0xffffffffu, rs0, 1);
            rs0 += __shfl_xor_sync(0xffffffffu, rs0, 2);
            rs1 += __shfl_xor_sync(0xffffffffu, rs1, 1);
            rs1 += __shfl_xor_sync(0xffffffffu, rs1, 2);
            if (tig == 0) {
                sRed[wn * 128 + r0] = rs0;
                sRed[wn * 128 + r0 + 8] = rs1;
            }
        }
        __syncthreads();
        if (tid < 128) {
            sL[tid] = sL[tid] * sAl[tid] +
                      (sRed[tid] + sRed[128 + tid]) + (sRed[256 + tid] + sRed[384 + tid]);
        }

        // ---- rescale O ----
#pragma unroll
        for (int mi = 0; mi < 4; mi++) {
            int r0 = wm * 64 + mi * 16 + gid;
            float a0 = sAl[r0], a1 = sAl[r0 + 8];
#pragma unroll
            for (int ni = 0; ni < 2; ni++) {
                oacc[mi][ni][0] *= a0;
                oacc[mi][ni][1] *= a0;
                oacc[mi][ni][2] *= a1;
                oacc[mi][ni][3] *= a1;
            }
        }

        // ---- O += P @ V (128x64, k=128); V via ldmatrix.trans ----
#pragma unroll
        for (int ks = 0; ks < 8; ks++) {
            const int k = ks * 16;
            uint32_t af[4][4], bf[2][2];
#pragma unroll
            for (int mi = 0; mi < 4; mi++) {
                int r0 = wm * 64 + mi * 16 + l15;
                ldsm4(af[mi], smu + FAB_P + (uint32_t)(r0 * 136 + k + ah) * 2);
            }
#pragma unroll
            for (int ni = 0; ni < 2; ni++) {
                int n0 = wn * 16 + ni * 8;
                ldsm2t(bf[ni], VB + (uint32_t)((k + l15) * 72 + n0) * 2);
            }
#pragma unroll
            for (int mi = 0; mi < 4; mi++)
#pragma unroll
                for (int ni = 0; ni < 2; ni++)
                    mma16(oacc[mi][ni], af[mi], bf[ni]);
        }
    }
    __syncthreads();

    // ---- O /= l, write half ----
#pragma unroll
    for (int mi = 0; mi < 4; mi++) {
        int r0 = wm * 64 + mi * 16 + gid;
        float i0 = 1.f / sL[r0], i1 = 1.f / sL[r0 + 8];
        long o0 = ((long)bb * TT + q0 + r0) * H + hh * DHD;
        long o1 = ((long)bb * TT + q0 + r0 + 8) * H + hh * DHD;
#pragma unroll
        for (int ni = 0; ni < 2; ni++) {
            int c0 = wn * 16 + ni * 8 + tig * 2;
            *(__half2*)&att[o0 + c0] = __floats2half2_rn(oacc[mi][ni][0] * i0, oacc[mi][ni][1] * i0);
            *(__half2*)&att[o1 + c0] = __floats2half2_rn(oacc[mi][ni][2] * i1, oacc[mi][ni][3] * i1);
        }
    }
}

// ---------------- LayerNorm: fp32 in, fp16 out ----------------
__global__ void ln_k(const float* __restrict__ x, const float* __restrict__ g,
                     const float* __restrict__ b, __half* __restrict__ o)
{
    long row = blockIdx.x;
    int t = threadIdx.x;
    float4 v = ((const float4*)(x + row * H))[t];
    float s = v.x + v.y + v.z + v.w;
    float ss = v.x * v.x + v.y * v.y + v.z * v.z + v.w * v.w;
#pragma unroll
    for (int off = 16; off; off >>= 1) {
        s += __shfl_xor_sync(0xffffffffu, s, off);
        ss += __shfl_xor_sync(0xffffffffu, ss, off);
    }
    __shared__ float sm0[4], sm1[4];
    int w = t >> 5;
    if ((t & 31) == 0) { sm0[w] = s; sm1[w] = ss; }
    __syncthreads();
    s = sm0[0] + sm0[1] + sm0[2] + sm0[3];
    ss = sm1[0] + sm1[1] + sm1[2] + sm1[3];
    float mean = s * (1.f / H);
    float var = ss * (1.f / H) - mean * mean;
    float rstd = rsqrtf(var + 1e-5f);
    float4 gg = ((const float4*)g)[t];
    float4 bb4 = ((const float4*)b)[t];
    __half2* op = (__half2*)(o + row * H);
    op[t * 2]     = __floats2half2_rn((v.x - mean) * rstd * gg.x + bb4.x,
                                      (v.y - mean) * rstd * gg.y + bb4.y);
    op[t * 2 + 1] = __floats2half2_rn((v.z - mean) * rstd * gg.z + bb4.z,
                                      (v.w - mean) * rstd * gg.w + bb4.w);
}

// ---------------- misc kernels ----------------
__global__ void cvth_k(const float* __restrict__ in, __half* __restrict__ out, int n4)
{
    int i = blockIdx.x * blockDim.x + threadIdx.x;
    if (i >= n4) return;
    float4 v = ((const float4*)in)[i];
    ((__half2*)out)[i * 2]     = __floats2half2_rn(v.x, v.y);
    ((__half2*)out)[i * 2 + 1] = __floats2half2_rn(v.z, v.w);
}

__global__ void pe_k(float* __restrict__ pe)
{
    int t = blockIdx.x;
    int i = threadIdx.x;
    float div = expf(-(float)(2 * i) * (logf(10000.f) / (float)H));
    float a = (float)t * div;
    pe[t * H + 2 * i] = sinf(a);
    pe[t * H + 2 * i + 1] = cosf(a);
}

__global__ void convT_k(const float* __restrict__ w, __half* __restrict__ o)
{
    int idx = blockIdx.x * blockDim.x + threadIdx.x;
    if (idx >= 4 * H * H) return;
    int k = idx / (H * H);
    int d = (idx / H) % H;
    int c = idx % H;
    o[idx] = __float2half_rn(w[c * H * 4 + d * 4 + k]);
}

__global__ void xinit_k(const float* __restrict__ qe, const float* __restrict__ pe,
                        float* __restrict__ x)
{
    long i = blockIdx.x * (long)blockDim.x + threadIdx.x;
    if (i >= (long)BB * TT * H) return;
    int td = (int)(i % (TT * H));
    x[i] = qe[td] + pe[td];
}

__global__ void kin_k(const float* __restrict__ ho, float* __restrict__ out)
{
    int row = blockIdx.x * blockDim.x + threadIdx.x;
    if (row >= BB * TT) return;
    const float* r = ho + (long)row * NOUT;
    float* o = out + (long)row * (3 * NJ);
    float gx[NJ], px[NJ], py[NJ];
    gx[0] = 0.f;
    px[0] = r[100];
    py[0] = r[101];
    o[0] = px[0]; o[1] = py[0]; o[2] = 1.f;
    for (int j = 1; j < NJ; j++) {
        int pa = PAR[j];
        float gg = gx[pa] + r[j];
        gx[j] = gg;
        float s = r[50 + j];
        float sn, cs;
        sincosf(gg, &sn, &cs);
        px[j] = px[pa] + cs * s;
        py[j] = py[pa] + sn * s;
        o[j * 3 + 0] = px[j];
        o[j * 3 + 1] = py[j];
        o[j * 3 + 2] = 1.f;
    }
}

// ---------------- launcher ----------------
static inline dim3 gg128(int M, int N, int bz = 1)
{
    return dim3((N + 127) / 128, (M + 127) / 128, bz);
}

#define SMEM_G8 61440

extern "C" void kernel_launch(void* const* d_in, const int* in_sizes, int n_in,
                              void* d_out, int out_size)
{
    const float* memory   = (const float*)d_in[0];
    const float* in_w     = (const float*)d_in[1];
    const float* in_b     = (const float*)d_in[2];
    const float* conv_w   = (const float*)d_in[3];
    const float* conv_b   = (const float*)d_in[4];
    const float* qemb     = (const float*)d_in[5];
    const float* sa_in_w  = (const float*)d_in[6];
    const float* sa_in_b  = (const float*)d_in[7];
    const float* sa_out_w = (const float*)d_in[8];
    const float* sa_out_b = (const float*)d_in[9];
    const float* ca_in_w  = (const float*)d_in[10];
    const float* ca_in_b  = (const float*)d_in[11];
    const float* ca_out_w = (const float*)d_in[12];
    const float* ca_out_b = (const float*)d_in[13];
    const float* ln1_g    = (const float*)d_in[14];
    const float* ln1_b    = (const float*)d_in[15];
    const float* ln2_g    = (const float*)d_in[16];
    const float* ln2_b    = (const float*)d_in[17];
    const float* ln3_g    = (const float*)d_in[18];
    const float* ln3_b    = (const float*)d_in[19];
    const float* ff1_w    = (const float*)d_in[20];
    const float* ff1_b    = (const float*)d_in[21];
    const float* ff2_w    = (const float*)d_in[22];
    const float* ff2_b    = (const float*)d_in[23];
    const float* out_w    = (const float*)d_in[24];
    const float* out_b    = (const float*)d_in[25];

    __half *memh_, *m_, *mem_, *xh_, *h_, *qkv_, *att_, *ff_, *cT_, *inwh_, *outwh_, *wt_;
    float *x_, *ho_, *pe_;
    cudaGetSymbolAddress((void**)&memh_, g_memh);
    cudaGetSymbolAddress((void**)&m_,    g_m);
    cudaGetSymbolAddress((void**)&mem_,  g_mem);
    cudaGetSymbolAddress((void**)&x_,    g_x);
    cudaGetSymbolAddress((void**)&xh_,   g_xh);
    cudaGetSymbolAddress((void**)&h_,    g_h);
    cudaGetSymbolAddress((void**)&qkv_,  g_qkv);
    cudaGetSymbolAddress((void**)&att_,  g_att);
    cudaGetSymbolAddress((void**)&ff_,   g_ff);
    cudaGetSymbolAddress((void**)&ho_,   g_head);
    cudaGetSymbolAddress((void**)&pe_,   g_pe);
    cudaGetSymbolAddress((void**)&cT_,   g_convTh);
    cudaGetSymbolAddress((void**)&inwh_, g_inwh);
    cudaGetSymbolAddress((void**)&outwh_,g_outwh);
    cudaGetSymbolAddress((void**)&wt_,   g_wth);

    cudaFuncSetAttribute(gemm8<EPI_BIAS,      true,  true >, cudaFuncAttributeMaxDynamicSharedMemorySize, SMEM_G8);
    cudaFuncSetAttribute(gemm8<EPI_BIAS,      true,  false>, cudaFuncAttributeMaxDynamicSharedMemorySize, SMEM_G8);
    cudaFuncSetAttribute(gemm8<EPI_CONV,      true,  false>, cudaFuncAttributeMaxDynamicSharedMemorySize, SMEM_G8);
    cudaFuncSetAttribute(gemm8<EPI_BIAS_RES,  false, false>, cudaFuncAttributeMaxDynamicSharedMemorySize, SMEM_G8);
    cudaFuncSetAttribute(gemm8<EPI_BIAS_GELU, true,  false>, cudaFuncAttributeMaxDynamicSharedMemorySize, SMEM_G8);
    cudaFuncSetAttribute(gemm8<EPI_BIAS,      false, false>, cudaFuncAttributeMaxDynamicSharedMemorySize, SMEM_G8);
    cudaFuncSetAttribute(fattn_k, cudaFuncAttributeMaxDynamicSharedMemorySize, FA_BYTES);

    // prep
    pe_k<<<TT, 256>>>(pe_);
    convT_k<<<(4 * H * H + 255) / 256, 256>>>(conv_w, cT_);
    cvth_k<<<(2097152 / 4 + 255) / 256, 256>>>(memory,   memh_,  2097152 / 4);
    cvth_k<<<(262144 / 4 + 255) / 256, 256>>>(in_w,      inwh_,  262144 / 4);
    cvth_k<<<(52224 / 4 + 255) / 256, 256>>>(out_w,      outwh_, 52224 / 4);
    cvth_k<<<(3145728 / 4 + 255) / 256, 256>>>(sa_in_w,  wt_ + WOFF_SAIN,  3145728 / 4);
    cvth_k<<<(1048576 / 4 + 255) / 256, 256>>>(sa_out_w, wt_ + WOFF_SAOUT, 1048576 / 4);
    cvth_k<<<(3145728 / 4 + 255) / 256, 256>>>(ca_in_w,  wt_ + WOFF_CAIN,  3145728 / 4);
    cvth_k<<<(1048576 / 4 + 255) / 256, 256>>>(ca_out_w, wt_ + WOFF_CAOUT, 1048576 / 4);
    cvth_k<<<(4194304 / 4 + 255) / 256, 256>>>(ff1_w,    wt_ + WOFF_FF1,   4194304 / 4);
    cvth_k<<<(4194304 / 4 + 255) / 256, 256>>>(ff2_w,    wt_ + WOFF_FF2,   4194304 / 4);

    // m = memory @ in_w^T + in_b
    gemm8<EPI_BIAS, true, false><<<gg128(BB * SS, H), 256, SMEM_G8>>>(
        memh_, inwh_, in_b, nullptr, m_,
        BB * SS, H, H, H, H, H, 0L, 1);

    // conv upsample (4 taps batched over z; tap = hh)
    gemm8<EPI_CONV, true, false><<<gg128(BB * SS, H, 4), 256, SMEM_G8>>>(
        m_, cT_, conv_b, pe_, mem_,
        BB * SS, H, H, H, H, H, (long)H * H, 4);

    xinit_k<<<(BB * TT * H + 255) / 256, 256>>>(qemb, pe_, x_);

    const dim3 fa_grid(TT / 128, BB * NHEAD);

    for (int l = 0; l < NL; l++) {
        // ======== self-attention ========
        ln_k<<<BB * TT, 128>>>(x_, ln1_g + l * H, ln1_b + l * H, h_);
        gemm8<EPI_BIAS, true, true><<<gg128(BB * TT, 3 * H), 256, SMEM_G8>>>(
            h_, wt_ + WOFF_SAIN + (long)l * 3 * H * H, sa_in_b + (long)l * 3 * H, nullptr, qkv_,
            BB * TT, 3 * H, H, H, H, 3 * H, 0L, 1);
        fattn_k<<<fa_grid, 256, FA_BYTES>>>(qkv_, att_);
        gemm8<EPI_BIAS_RES, false, false><<<gg128(BB * TT, H), 256, SMEM_G8>>>(
            att_, wt_ + WOFF_SAOUT + (long)l * H * H, sa_out_b + (long)l * H, x_, x_,
            BB * TT, H, H, H, H, H, 0L, 1);

        // ======== cross-attention ========
        ln_k<<<BB * TT, 128>>>(x_, ln2_g + l * H, ln2_b + l * H, h_);
        gemm8<EPI_BIAS, true, true><<<gg128(BB * TT, H), 256, SMEM_G8>>>(
            h_, wt_ + WOFF_CAIN + (long)l * 3 * H * H, ca_in_b + (long)l * 3 * H, nullptr, qkv_,
            BB * TT, H, H, H, H, 3 * H, 0L, 1);
        gemm8<EPI_BIAS, true, false><<<gg128(BB * TT, 2 * H), 256, SMEM_G8>>>(
            mem_, wt_ + WOFF_CAIN + (long)l * 3 * H * H + (long)H * H,
            ca_in_b + (long)l * 3 * H + H, nullptr, qkv_ + H,
            BB * TT, 2 * H, H, H, H, 3 * H, 0L, 1);
        fattn_k<<<fa_grid, 256, FA_BYTES>>>(qkv_, att_);
        gemm8<EPI_BIAS_RES, false, false><<<gg128(BB * TT, H), 256, SMEM_G8>>>(
            att_, wt_ + WOFF_CAOUT + (long)l * H * H, ca_out_b + (long)l * H, x_, x_,
            BB * TT, H, H, H, H, H, 0L, 1);

        // ======== FFN ========
        ln_k<<<BB * TT, 128>>>(x_, ln3_g + l * H, ln3_b + l * H, h_);
        gemm8<EPI_BIAS_GELU, true, false><<<gg128(BB * TT, FF), 256, SMEM_G8>>>(
            h_, wt_ + WOFF_FF1 + (long)l * FF * H, ff1_b + (long)l * FF, nullptr, ff_,
            BB * TT, FF, H, H, H, FF, 0L, 1);
        gemm8<EPI_BIAS_RES, false, false><<<gg128(BB * TT, H), 256, SMEM_G8>>>(
            ff_, wt_ + WOFF_FF2 + (long)l * H * FF, ff2_b + (long)l * H, x_, x_,
            BB * TT, H, FF, FF, FF, H, 0L, 1);
    }

    // head
    cvth_k<<<(16777216 / 4 + 255) / 256, 256>>>(x_, xh_, 16777216 / 4);
    gemm8<EPI_BIAS, false, false><<<gg128(BB * TT, NOUT), 256, SMEM_G8>>>(
        xh_, outwh_, out_b, nullptr, ho_,
        BB * TT, NOUT, H, H, H, NOUT, 0L, 1);

    kin_k<<<(BB * TT + 255) / 256, 256>>>(ho_, (float*)d_out);
}